// round 1
// baseline (speedup 1.0000x reference)
#include <cuda_runtime.h>
#include <math.h>

#define T    2048
#define HDIM 1024
#define FDIM 3584
#define NEXP 8
#define NH   16
#define SEQ  2048
#define NSEL 204   // int(0.1 * 2048)

// ---------------- device scratch (no allocations allowed) ----------------
__device__ float g_scores[T];
__device__ float g_l1[T];
__device__ int   g_sel[T * 2];
__device__ float g_rw[T * 2];
__device__ int   g_top1prune[T];
__device__ int   g_low[T];
__device__ int   g_high[T];
__device__ int   g_cnt[NEXP];
__device__ int   g_ptok[NEXP * T];
__device__ float g_pw[NEXP * T];
__device__ float g_act[NEXP * T * FDIM];  // 224 MB activation scratch

// ---------------- kernel 1: router (logits, softmax, top-2, l1 norm) -----
__global__ void router_kernel(const float* __restrict__ x,
                              const float* __restrict__ gw,
                              float* logits_out) {
    int t = blockIdx.x;
    int lane = threadIdx.x & 31;
    int w = threadIdx.x >> 5;          // 8 warps == 8 experts
    __shared__ float s_logit[NEXP];
    __shared__ float s_l1;

    const float* xr = x + (size_t)t * HDIM;
    const float* ge = gw + (size_t)w * HDIM;
    float acc = 0.f, l1 = 0.f;
    for (int i = lane; i < HDIM; i += 32) {
        float xv = xr[i];
        acc += xv * ge[i];
        l1 += fabsf(xv);
    }
    #pragma unroll
    for (int o = 16; o; o >>= 1) {
        acc += __shfl_xor_sync(0xffffffffu, acc, o);
        l1  += __shfl_xor_sync(0xffffffffu, l1, o);
    }
    if (lane == 0) {
        s_logit[w] = acc;
        if (w == 0) s_l1 = l1;
    }
    __syncthreads();
    if (threadIdx.x == 0) {
        float p[NEXP];
        float mx = s_logit[0];
        for (int e = 1; e < NEXP; e++) if (s_logit[e] > mx) mx = s_logit[e];
        float sum = 0.f;
        for (int e = 0; e < NEXP; e++) { p[e] = expf(s_logit[e] - mx); sum += p[e]; }
        float inv = 1.f / sum;
        for (int e = 0; e < NEXP; e++) p[e] *= inv;
        int i0 = 0;
        for (int e = 1; e < NEXP; e++) if (p[e] > p[i0]) i0 = e;
        int i1 = (i0 == 0) ? 1 : 0;
        for (int e = 0; e < NEXP; e++) if (e != i0 && p[e] > p[i1]) i1 = e;
        g_sel[2 * t] = i0;  g_sel[2 * t + 1] = i1;
        g_rw[2 * t] = p[i0]; g_rw[2 * t + 1] = p[i1];
        g_top1prune[t] = (p[i1] < 0.5f * p[i0]) ? 1 : 0;
        g_l1[t] = s_l1;
        if (logits_out) {
            for (int e = 0; e < NEXP; e++) logits_out[(size_t)t * NEXP + e] = s_logit[e];
        }
    }
}

// ---------------- kernel 2: attention-score reduction --------------------
__global__ void attn_kernel(const float* __restrict__ attn) {
    int i = blockIdx.x;  // row
    float s = 0.f;
    for (int h = 0; h < NH; h++) {
        const float* row = attn + ((size_t)h * SEQ + i) * SEQ;
        for (int j = threadIdx.x; j < SEQ; j += 256) s += row[j];
    }
    __shared__ float red[256];
    red[threadIdx.x] = s;
    __syncthreads();
    for (int st = 128; st > 0; st >>= 1) {
        if (threadIdx.x < st) red[threadIdx.x] += red[threadIdx.x + st];
        __syncthreads();
    }
    if (threadIdx.x == 0)
        g_scores[i] = red[0] / (16.f * (float)(SEQ - i)) * g_l1[i];
}

// ---------------- kernel 3: top-k selection + routing finalize -----------
__global__ void route_finalize_kernel() {
    __shared__ float sval[T];
    __shared__ int   sidx[T];
    int tid = threadIdx.x;  // 1024 threads

    for (int t = tid; t < T; t += 1024) { g_low[t] = 0; g_high[t] = 0; }
    if (tid < NEXP) g_cnt[tid] = 0;

    for (int mode = 0; mode < 2; mode++) {
        __syncthreads();
        for (int t = tid; t < T; t += 1024) { sval[t] = g_scores[t]; sidx[t] = t; }
        __syncthreads();
        // bitonic sort of 2048 (val, idx)
        for (int k = 2; k <= T; k <<= 1) {
            for (int j = k >> 1; j > 0; j >>= 1) {
                #pragma unroll
                for (int s = 0; s < 2; s++) {
                    int i = tid + s * 1024;
                    int ixj = i ^ j;
                    if (ixj > i) {
                        float va = sval[i], vb = sval[ixj];
                        int ia = sidx[i], ib = sidx[ixj];
                        bool aBeforeB;
                        if (mode == 0)  // ascending score (for bottom-k), tie: idx asc
                            aBeforeB = (va < vb) || (va == vb && ia < ib);
                        else            // descending score (for top-k), tie: idx asc
                            aBeforeB = (va > vb) || (va == vb && ia < ib);
                        bool up = ((i & k) == 0);
                        bool doswap = up ? !aBeforeB : aBeforeB;
                        if (doswap) {
                            sval[i] = vb; sval[ixj] = va;
                            sidx[i] = ib; sidx[ixj] = ia;
                        }
                    }
                }
                __syncthreads();
            }
        }
        for (int r = tid; r < NSEL; r += 1024) {
            if (mode == 0) g_low[sidx[r]] = 1;
            else           g_high[sidx[r]] = 1;
        }
        __syncthreads();
    }

    // finalize routing weights and build per-expert pair lists
    for (int t = tid; t < T; t += 1024) {
        float r0 = g_rw[2 * t], r1 = g_rw[2 * t + 1];
        float n0 = 1.f;
        float n1 = g_top1prune[t] ? 0.f : 1.f;
        if (g_low[t])  { n0 = 0.f; n1 = 0.f; }
        if (g_high[t]) { n0 = 1.f; n1 = 1.f; }
        r0 *= n0; r1 *= n1;
        float d = r0 + r1;
        if (d > 0.f) { r0 /= d; r1 /= d; }
        if (r0 > 0.f) {
            int e = g_sel[2 * t];
            int p = atomicAdd(&g_cnt[e], 1);
            g_ptok[e * T + p] = t;  g_pw[e * T + p] = r0;
        }
        if (r1 > 0.f) {
            int e = g_sel[2 * t + 1];
            int p = atomicAdd(&g_cnt[e], 1);
            g_ptok[e * T + p] = t;  g_pw[e * T + p] = r1;
        }
    }
}

// ---------------- kernel 4: grouped GEMM pass 1 (x@w1, x@w3 -> act) ------
// act[pair, f] = cw * silu(x.w1) * (x.w3);  64x64 tile, 4x4 reg tile
__global__ __launch_bounds__(256) void gemm1_kernel(const float* __restrict__ x,
                                                    const float* __restrict__ w1,
                                                    const float* __restrict__ w3) {
    const int e = blockIdx.z;
    const int Ne = g_cnt[e];
    const int m0 = blockIdx.x * 64;
    if (m0 >= Ne) return;
    const int f0 = blockIdx.y * 64;

    __shared__ float As[16][68];
    __shared__ float B1s[16][68];
    __shared__ float B3s[16][68];
    __shared__ int   stok[64];
    __shared__ float spw[64];

    const int tid = threadIdx.x;
    if (tid < 64) {
        int m = m0 + tid; int tok = 0; float pw = 0.f;
        if (m < Ne) { tok = g_ptok[e * T + m]; pw = g_pw[e * T + m]; }
        stok[tid] = tok; spw[tid] = pw;
    }
    __syncthreads();

    const int lr = tid >> 2;            // 0..63 (tile row)
    const int lk = (tid & 3) << 2;      // 0,4,8,12 (k offset)
    const int ty = tid >> 4, tx = tid & 15;

    const float* xrow = x + (size_t)stok[lr] * HDIM + lk;
    const float* w1r = w1 + ((size_t)e * FDIM + f0 + lr) * HDIM + lk;
    const float* w3r = w3 + ((size_t)e * FDIM + f0 + lr) * HDIM + lk;

    float accH[4][4] = {{0.f}}, accG[4][4] = {{0.f}};

    for (int k0 = 0; k0 < HDIM; k0 += 16) {
        float4 av = *reinterpret_cast<const float4*>(xrow + k0);
        float4 b1 = *reinterpret_cast<const float4*>(w1r + k0);
        float4 b3 = *reinterpret_cast<const float4*>(w3r + k0);
        As[lk + 0][lr] = av.x; As[lk + 1][lr] = av.y; As[lk + 2][lr] = av.z; As[lk + 3][lr] = av.w;
        B1s[lk + 0][lr] = b1.x; B1s[lk + 1][lr] = b1.y; B1s[lk + 2][lr] = b1.z; B1s[lk + 3][lr] = b1.w;
        B3s[lk + 0][lr] = b3.x; B3s[lk + 1][lr] = b3.y; B3s[lk + 2][lr] = b3.z; B3s[lk + 3][lr] = b3.w;
        __syncthreads();
        #pragma unroll
        for (int k = 0; k < 16; k++) {
            float4 a = *reinterpret_cast<const float4*>(&As[k][ty << 2]);
            float4 b = *reinterpret_cast<const float4*>(&B1s[k][tx << 2]);
            float4 c = *reinterpret_cast<const float4*>(&B3s[k][tx << 2]);
            float aa[4] = {a.x, a.y, a.z, a.w};
            float bb[4] = {b.x, b.y, b.z, b.w};
            float cc[4] = {c.x, c.y, c.z, c.w};
            #pragma unroll
            for (int i = 0; i < 4; i++)
                #pragma unroll
                for (int j = 0; j < 4; j++) {
                    accH[i][j] += aa[i] * bb[j];
                    accG[i][j] += aa[i] * cc[j];
                }
        }
        __syncthreads();
    }

    #pragma unroll
    for (int i = 0; i < 4; i++) {
        int m = (ty << 2) + i;
        int row = m0 + m;
        if (row < Ne) {
            float pw = spw[m];
            float4 v;
            float h;
            h = accH[i][0]; v.x = pw * accG[i][0] * (h / (1.f + expf(-h)));
            h = accH[i][1]; v.y = pw * accG[i][1] * (h / (1.f + expf(-h)));
            h = accH[i][2]; v.z = pw * accG[i][2] * (h / (1.f + expf(-h)));
            h = accH[i][3]; v.w = pw * accG[i][3] * (h / (1.f + expf(-h)));
            *reinterpret_cast<float4*>(g_act + ((size_t)(e * T + row)) * FDIM + f0 + (tx << 2)) = v;
        }
    }
}

// ---------------- kernel 5: grouped GEMM pass 2 (act @ w2^T -> out) ------
__global__ __launch_bounds__(256) void gemm2_kernel(const float* __restrict__ w2,
                                                    float* __restrict__ out) {
    const int e = blockIdx.z;
    const int Ne = g_cnt[e];
    const int m0 = blockIdx.x * 64;
    if (m0 >= Ne) return;
    const int h0 = blockIdx.y * 64;

    __shared__ float As[16][68];
    __shared__ float Bs[16][68];

    const int tid = threadIdx.x;
    const int lr = tid >> 2;
    const int lk = (tid & 3) << 2;
    const int ty = tid >> 4, tx = tid & 15;

    const float* ar = g_act + ((size_t)(e * T + m0 + lr)) * FDIM + lk;
    const float* br = w2 + ((size_t)e * HDIM + h0 + lr) * FDIM + lk;

    float acc[4][4] = {{0.f}};

    for (int k0 = 0; k0 < FDIM; k0 += 16) {
        float4 av = *reinterpret_cast<const float4*>(ar + k0);
        float4 bv = *reinterpret_cast<const float4*>(br + k0);
        As[lk + 0][lr] = av.x; As[lk + 1][lr] = av.y; As[lk + 2][lr] = av.z; As[lk + 3][lr] = av.w;
        Bs[lk + 0][lr] = bv.x; Bs[lk + 1][lr] = bv.y; Bs[lk + 2][lr] = bv.z; Bs[lk + 3][lr] = bv.w;
        __syncthreads();
        #pragma unroll
        for (int k = 0; k < 16; k++) {
            float4 a = *reinterpret_cast<const float4*>(&As[k][ty << 2]);
            float4 b = *reinterpret_cast<const float4*>(&Bs[k][tx << 2]);
            float aa[4] = {a.x, a.y, a.z, a.w};
            float bb[4] = {b.x, b.y, b.z, b.w};
            #pragma unroll
            for (int i = 0; i < 4; i++)
                #pragma unroll
                for (int j = 0; j < 4; j++)
                    acc[i][j] += aa[i] * bb[j];
        }
        __syncthreads();
    }

    #pragma unroll
    for (int i = 0; i < 4; i++) {
        int row = m0 + (ty << 2) + i;
        if (row < Ne) {
            int tok = g_ptok[e * T + row];
            float* o = out + (size_t)tok * HDIM + h0 + (tx << 2);
            atomicAdd(o + 0, acc[i][0]);
            atomicAdd(o + 1, acc[i][1]);
            atomicAdd(o + 2, acc[i][2]);
            atomicAdd(o + 3, acc[i][3]);
        }
    }
}

// ---------------- launch ---------------------------------------------------
extern "C" void kernel_launch(void* const* d_in, const int* in_sizes, int n_in,
                              void* d_out, int out_size) {
    const float* x    = (const float*)d_in[0];  // [1, 2048, 1024]
    const float* attn = (const float*)d_in[1];  // [1, 16, 2048, 2048]
    const float* gw   = (const float*)d_in[2];  // [8, 1024]
    const float* w1   = (const float*)d_in[3];  // [8, 3584, 1024]
    const float* w2   = (const float*)d_in[4];  // [8, 1024, 3584]
    const float* w3   = (const float*)d_in[5];  // [8, 3584, 1024]

    float* out = (float*)d_out;
    float* logits = (out_size >= (int)(T * HDIM + T * NEXP)) ? out + (size_t)T * HDIM
                                                             : nullptr;

    cudaMemsetAsync(d_out, 0, (size_t)T * HDIM * sizeof(float));
    router_kernel<<<T, 256>>>(x, gw, logits);
    attn_kernel<<<SEQ, 256>>>(attn);
    route_finalize_kernel<<<1, 1024>>>();
    gemm1_kernel<<<dim3(T / 64, FDIM / 64, NEXP), 256>>>(x, w1, w3);
    gemm2_kernel<<<dim3(T / 64, HDIM / 64, NEXP), 256>>>(w2, out);
}

// round 3
// speedup vs baseline: 1.9255x; 1.9255x over previous
#include <cuda_runtime.h>
#include <cuda_bf16.h>
#include <math.h>
#include <stdint.h>

#define T    2048
#define HDIM 1024
#define FDIM 3584
#define NEXP 8
#define NH   16
#define SEQ  2048
#define NSEL 204   // int(0.1 * 2048)

// ---------------- device scratch (no allocations allowed) ----------------
__device__ float g_scores[T];
__device__ float g_l1[T];
__device__ int   g_sel[T * 2];
__device__ float g_rw[T * 2];
__device__ int   g_top1prune[T];
__device__ int   g_low[T];
__device__ int   g_high[T];
__device__ int   g_cnt[NEXP];
__device__ int   g_ptok[NEXP * T];
__device__ float g_pw[NEXP * T];
__device__ float g_act[(size_t)NEXP * T * FDIM];  // fp32 activations

// ============================ helpers =====================================
__device__ __forceinline__ uint32_t smem_u32(const void* p) {
    uint32_t a;
    asm("{ .reg .u64 t; cvta.to.shared.u64 t, %1; cvt.u32.u64 %0, t; }" : "=r"(a) : "l"(p));
    return a;
}

__device__ __forceinline__ void ldm_x4(uint32_t r[4], uint32_t addr) {
    asm volatile("ldmatrix.sync.aligned.m8n8.x4.shared.b16 {%0,%1,%2,%3}, [%4];"
                 : "=r"(r[0]), "=r"(r[1]), "=r"(r[2]), "=r"(r[3]) : "r"(addr));
}

__device__ __forceinline__ void mma4(float d[4], const uint32_t a[4], const uint32_t b[2]) {
    asm volatile("mma.sync.aligned.m16n8k16.row.col.f32.bf16.bf16.f32 "
                 "{%0,%1,%2,%3}, {%4,%5,%6,%7}, {%8,%9}, {%0,%1,%2,%3};"
                 : "+f"(d[0]), "+f"(d[1]), "+f"(d[2]), "+f"(d[3])
                 : "r"(a[0]), "r"(a[1]), "r"(a[2]), "r"(a[3]), "r"(b[0]), "r"(b[1]));
}

// pack two floats -> bf16x2 (low addr = first)
__device__ __forceinline__ uint32_t pk(float a, float b) {
    return (uint32_t)__bfloat16_as_ushort(__float2bfloat16(a))
         | ((uint32_t)__bfloat16_as_ushort(__float2bfloat16(b)) << 16);
}
// split float4 into hi/lo bf16 quads, store 8B each
__device__ __forceinline__ void store_hl(char* ph, char* pl, float4 v) {
    float hx = __bfloat162float(__float2bfloat16(v.x));
    float hy = __bfloat162float(__float2bfloat16(v.y));
    float hz = __bfloat162float(__float2bfloat16(v.z));
    float hw = __bfloat162float(__float2bfloat16(v.w));
    uint2 uh; uh.x = pk(v.x, v.y); uh.y = pk(v.z, v.w);
    uint2 ul; ul.x = pk(v.x - hx, v.y - hy); ul.y = pk(v.z - hz, v.w - hw);
    *reinterpret_cast<uint2*>(ph) = uh;
    *reinterpret_cast<uint2*>(pl) = ul;
}

// row stride in smem: 32 bf16 data + 8 pad = 40 bf16 = 80 bytes (conflict-free)
#define RS 80

// gemm1 smem layout (per stage, 40960 B): AH 0, AL 10240, B1H 20480, B1L 25600,
// B3H 30720, B3L 35840.  2 stages = 81920, then stok(512B) + spw(512B).
#define G1_STG   40960
#define G1_SMEM  (2 * G1_STG + 1024)
// gemm2 layout (per stage, 30720 B): AH 0, AL 10240, BH 20480, BL 25600.
#define G2_STG   30720
#define G2_SMEM  (2 * G2_STG + 512)

// ---------------- kernel 1: router ---------------------------------------
__global__ void router_kernel(const float* __restrict__ x,
                              const float* __restrict__ gw,
                              float* logits_out) {
    int t = blockIdx.x;
    int lane = threadIdx.x & 31;
    int w = threadIdx.x >> 5;
    __shared__ float s_logit[NEXP];
    __shared__ float s_l1;

    const float* xr = x + (size_t)t * HDIM;
    const float* ge = gw + (size_t)w * HDIM;
    float acc = 0.f, l1 = 0.f;
    for (int i = lane; i < HDIM; i += 32) {
        float xv = xr[i];
        acc += xv * ge[i];
        l1 += fabsf(xv);
    }
    #pragma unroll
    for (int o = 16; o; o >>= 1) {
        acc += __shfl_xor_sync(0xffffffffu, acc, o);
        l1  += __shfl_xor_sync(0xffffffffu, l1, o);
    }
    if (lane == 0) {
        s_logit[w] = acc;
        if (w == 0) s_l1 = l1;
    }
    __syncthreads();
    if (threadIdx.x == 0) {
        float p[NEXP];
        float mx = s_logit[0];
        for (int e = 1; e < NEXP; e++) if (s_logit[e] > mx) mx = s_logit[e];
        float sum = 0.f;
        for (int e = 0; e < NEXP; e++) { p[e] = expf(s_logit[e] - mx); sum += p[e]; }
        float inv = 1.f / sum;
        for (int e = 0; e < NEXP; e++) p[e] *= inv;
        int i0 = 0;
        for (int e = 1; e < NEXP; e++) if (p[e] > p[i0]) i0 = e;
        int i1 = (i0 == 0) ? 1 : 0;
        for (int e = 0; e < NEXP; e++) if (e != i0 && p[e] > p[i1]) i1 = e;
        g_sel[2 * t] = i0;  g_sel[2 * t + 1] = i1;
        g_rw[2 * t] = p[i0]; g_rw[2 * t + 1] = p[i1];
        g_top1prune[t] = (p[i1] < 0.5f * p[i0]) ? 1 : 0;
        g_l1[t] = s_l1;
        if (logits_out) {
            for (int e = 0; e < NEXP; e++) logits_out[(size_t)t * NEXP + e] = s_logit[e];
        }
    }
}

// ---------------- kernel 2: attention-score reduction --------------------
__global__ void attn_kernel(const float* __restrict__ attn) {
    int i = blockIdx.x;
    float s = 0.f;
    for (int h = 0; h < NH; h++) {
        const float4* row = reinterpret_cast<const float4*>(attn + ((size_t)h * SEQ + i) * SEQ);
        for (int j = threadIdx.x; j < SEQ / 4; j += 256) {
            float4 v = row[j];
            s += v.x + v.y + v.z + v.w;
        }
    }
    __shared__ float red[256];
    red[threadIdx.x] = s;
    __syncthreads();
    for (int st = 128; st > 0; st >>= 1) {
        if (threadIdx.x < st) red[threadIdx.x] += red[threadIdx.x + st];
        __syncthreads();
    }
    if (threadIdx.x == 0)
        g_scores[i] = red[0] / (16.f * (float)(SEQ - i)) * g_l1[i];
}

// ---------------- kernel 3: top-k selection + routing finalize -----------
__global__ void route_finalize_kernel() {
    __shared__ float sval[T];
    __shared__ int   sidx[T];
    int tid = threadIdx.x;  // 1024 threads

    for (int t = tid; t < T; t += 1024) { g_low[t] = 0; g_high[t] = 0; }
    if (tid < NEXP) g_cnt[tid] = 0;

    for (int mode = 0; mode < 2; mode++) {
        __syncthreads();
        for (int t = tid; t < T; t += 1024) { sval[t] = g_scores[t]; sidx[t] = t; }
        __syncthreads();
        for (int k = 2; k <= T; k <<= 1) {
            for (int j = k >> 1; j > 0; j >>= 1) {
                #pragma unroll
                for (int s = 0; s < 2; s++) {
                    int i = tid + s * 1024;
                    int ixj = i ^ j;
                    if (ixj > i) {
                        float va = sval[i], vb = sval[ixj];
                        int ia = sidx[i], ib = sidx[ixj];
                        bool aBeforeB;
                        if (mode == 0)
                            aBeforeB = (va < vb) || (va == vb && ia < ib);
                        else
                            aBeforeB = (va > vb) || (va == vb && ia < ib);
                        bool up = ((i & k) == 0);
                        bool doswap = up ? !aBeforeB : aBeforeB;
                        if (doswap) {
                            sval[i] = vb; sval[ixj] = va;
                            sidx[i] = ib; sidx[ixj] = ia;
                        }
                    }
                }
                __syncthreads();
            }
        }
        for (int r = tid; r < NSEL; r += 1024) {
            if (mode == 0) g_low[sidx[r]] = 1;
            else           g_high[sidx[r]] = 1;
        }
        __syncthreads();
    }

    for (int t = tid; t < T; t += 1024) {
        float r0 = g_rw[2 * t], r1 = g_rw[2 * t + 1];
        float n0 = 1.f;
        float n1 = g_top1prune[t] ? 0.f : 1.f;
        if (g_low[t])  { n0 = 0.f; n1 = 0.f; }
        if (g_high[t]) { n0 = 1.f; n1 = 1.f; }
        r0 *= n0; r1 *= n1;
        float d = r0 + r1;
        if (d > 0.f) { r0 /= d; r1 /= d; }
        if (r0 > 0.f) {
            int e = g_sel[2 * t];
            int p = atomicAdd(&g_cnt[e], 1);
            g_ptok[e * T + p] = t;  g_pw[e * T + p] = r0;
        }
        if (r1 > 0.f) {
            int e = g_sel[2 * t + 1];
            int p = atomicAdd(&g_cnt[e], 1);
            g_ptok[e * T + p] = t;  g_pw[e * T + p] = r1;
        }
    }
}

// ---------------- gemm1: mma.sync bf16x3, x@{w1,w3}^T + silu fuse --------
__global__ void __launch_bounds__(512) gemm1_mma(const float* __restrict__ x,
                                                 const float* __restrict__ w1,
                                                 const float* __restrict__ w3) {
    extern __shared__ char sm[];
    const int e = blockIdx.z;
    const int Ne = g_cnt[e];
    const int m0 = blockIdx.x * 128;
    if (m0 >= Ne) return;
    const int f0 = blockIdx.y * 64;
    const int tid = threadIdx.x;
    const int lane = tid & 31, wid = tid >> 5;
    const int wm = wid & 3, wn = wid >> 2;

    const uint32_t sb = smem_u32(sm);
    int*   stok = reinterpret_cast<int*>(sm + 2 * G1_STG);
    float* spw  = reinterpret_cast<float*>(sm + 2 * G1_STG + 512);
    if (tid < 128) {
        int m = m0 + tid; int tk = 0; float pw = 0.f;
        if (m < Ne) { tk = g_ptok[e * T + m]; pw = g_pw[e * T + m]; }
        stok[tid] = tk; spw[tid] = pw;
    }
    __syncthreads();

    // producer setup: 2 float4 of A, 2 float4 of B per thread per stage
    const float* asrc[2]; const float* bsrc[2];
    int arow[2], ac4[2], bOffH[2], brow[2], bc4[2];
    #pragma unroll
    for (int i = 0; i < 2; i++) {
        int idx = tid + i * 512;
        arow[i] = idx >> 3; ac4[i] = (idx & 7) << 2;
        asrc[i] = x + (size_t)stok[arow[i]] * HDIM + ac4[i];
        int bm = idx >> 9; brow[i] = (idx >> 3) & 63; bc4[i] = (idx & 7) << 2;
        bOffH[i] = bm ? 30720 : 20480;
        const float* ws = bm ? w3 : w1;
        bsrc[i] = ws + ((size_t)e * FDIM + f0 + brow[i]) * HDIM + bc4[i];
    }

    float4 sa[2], sb4[2];
    float hc[2][2][4] = {{{0.f}}}, gc[2][2][4] = {{{0.f}}};

    // prologue
    #pragma unroll
    for (int i = 0; i < 2; i++) { sa[i] = *reinterpret_cast<const float4*>(asrc[i]); sb4[i] = *reinterpret_cast<const float4*>(bsrc[i]); }
    {
        char* bp = sm;
        #pragma unroll
        for (int i = 0; i < 2; i++) {
            store_hl(bp + arow[i] * RS + ac4[i] * 2, bp + 10240 + arow[i] * RS + ac4[i] * 2, sa[i]);
            store_hl(bp + bOffH[i] + brow[i] * RS + bc4[i] * 2, bp + bOffH[i] + 5120 + brow[i] * RS + bc4[i] * 2, sb4[i]);
        }
    }
    __syncthreads();

    const int lrow = lane & 15;
    const int lhik = ((lane >> 4) & 1) * 16;
    const int bn = (lane & 7) + ((lane >> 4) & 1) * 8;
    const int bhk = ((lane >> 3) & 1) * 16;

    for (int s = 0; s < 32; s++) {
        if (s + 1 < 32) {
            int k0 = (s + 1) * 32;
            #pragma unroll
            for (int i = 0; i < 2; i++) {
                sa[i]  = *reinterpret_cast<const float4*>(asrc[i] + k0);
                sb4[i] = *reinterpret_cast<const float4*>(bsrc[i] + k0);
            }
        }
        const uint32_t bb = sb + (uint32_t)(s & 1) * G1_STG;
        #pragma unroll
        for (int kk = 0; kk < 2; kk++) {
            const uint32_t koff = kk * 32;
            uint32_t Ah[2][4], Al[2][4];
            #pragma unroll
            for (int fm = 0; fm < 2; fm++) {
                uint32_t o = (uint32_t)((wm * 32 + fm * 16 + lrow) * RS) + koff + lhik;
                ldm_x4(Ah[fm], bb + o);
                ldm_x4(Al[fm], bb + 10240 + o);
            }
            uint32_t bo = (uint32_t)((wn * 16 + bn) * RS) + koff + bhk;
            uint32_t B1h[4], B1l[4], B3h[4], B3l[4];
            ldm_x4(B1h, bb + 20480 + bo);
            ldm_x4(B1l, bb + 25600 + bo);
            ldm_x4(B3h, bb + 30720 + bo);
            ldm_x4(B3l, bb + 35840 + bo);
            #pragma unroll
            for (int fm = 0; fm < 2; fm++) {
                #pragma unroll
                for (int fn = 0; fn < 2; fn++) {
                    mma4(hc[fm][fn], Ah[fm], B1h + 2 * fn);
                    mma4(hc[fm][fn], Ah[fm], B1l + 2 * fn);
                    mma4(hc[fm][fn], Al[fm], B1h + 2 * fn);
                    mma4(gc[fm][fn], Ah[fm], B3h + 2 * fn);
                    mma4(gc[fm][fn], Ah[fm], B3l + 2 * fn);
                    mma4(gc[fm][fn], Al[fm], B3h + 2 * fn);
                }
            }
        }
        if (s + 1 < 32) {
            char* bp = sm + ((s + 1) & 1) * G1_STG;
            #pragma unroll
            for (int i = 0; i < 2; i++) {
                store_hl(bp + arow[i] * RS + ac4[i] * 2, bp + 10240 + arow[i] * RS + ac4[i] * 2, sa[i]);
                store_hl(bp + bOffH[i] + brow[i] * RS + bc4[i] * 2, bp + bOffH[i] + 5120 + brow[i] * RS + bc4[i] * 2, sb4[i]);
            }
            __syncthreads();
        }
    }

    // epilogue: act = pw * g * silu(h)
    const int g = lane >> 2, tq = lane & 3;
    #pragma unroll
    for (int fm = 0; fm < 2; fm++) {
        #pragma unroll
        for (int fn = 0; fn < 2; fn++) {
            int rl = wm * 32 + fm * 16 + g;
            int c  = f0 + wn * 16 + fn * 8 + 2 * tq;
            float pw0 = spw[rl], pw1 = spw[rl + 8];
            float h0 = hc[fm][fn][0], h1 = hc[fm][fn][1];
            float h2 = hc[fm][fn][2], h3 = hc[fm][fn][3];
            float2 v0, v1;
            v0.x = pw0 * gc[fm][fn][0] * (h0 / (1.f + expf(-h0)));
            v0.y = pw0 * gc[fm][fn][1] * (h1 / (1.f + expf(-h1)));
            v1.x = pw1 * gc[fm][fn][2] * (h2 / (1.f + expf(-h2)));
            v1.y = pw1 * gc[fm][fn][3] * (h3 / (1.f + expf(-h3)));
            *reinterpret_cast<float2*>(g_act + ((size_t)(e * T + m0 + rl)) * FDIM + c) = v0;
            *reinterpret_cast<float2*>(g_act + ((size_t)(e * T + m0 + rl + 8)) * FDIM + c) = v1;
        }
    }
}

// ---------------- gemm2: mma.sync bf16x3, act @ w2^T -> scatter-add ------
__global__ void __launch_bounds__(512) gemm2_mma(const float* __restrict__ w2,
                                                 float* __restrict__ out) {
    extern __shared__ char sm[];
    const int e = blockIdx.z;
    const int Ne = g_cnt[e];
    const int m0 = blockIdx.x * 128;
    if (m0 >= Ne) return;
    const int h0 = blockIdx.y * 64;
    const int tid = threadIdx.x;
    const int lane = tid & 31, wid = tid >> 5;
    const int wm = wid & 3, wn = wid >> 2;

    const uint32_t sb = smem_u32(sm);
    int* stok = reinterpret_cast<int*>(sm + 2 * G2_STG);
    if (tid < 128) {
        int m = m0 + tid; int tk = 0;
        if (m < Ne) tk = g_ptok[e * T + m];
        stok[tid] = tk;
    }
    __syncthreads();

    // producer: A 2 float4, B 1 float4 per thread per stage
    const float* asrc[2]; const float* bsrc;
    int arow[2], ac4[2], brow, bc4;
    #pragma unroll
    for (int i = 0; i < 2; i++) {
        int idx = tid + i * 512;
        arow[i] = idx >> 3; ac4[i] = (idx & 7) << 2;
        asrc[i] = g_act + ((size_t)(e * T + m0 + arow[i])) * FDIM + ac4[i];
    }
    brow = tid >> 3; bc4 = (tid & 7) << 2;
    bsrc = w2 + ((size_t)e * HDIM + h0 + brow) * FDIM + bc4;

    float4 sa[2], sbv;
    float acc[2][2][4] = {{{0.f}}};

    #pragma unroll
    for (int i = 0; i < 2; i++) sa[i] = *reinterpret_cast<const float4*>(asrc[i]);
    sbv = *reinterpret_cast<const float4*>(bsrc);
    {
        char* bp = sm;
        #pragma unroll
        for (int i = 0; i < 2; i++)
            store_hl(bp + arow[i] * RS + ac4[i] * 2, bp + 10240 + arow[i] * RS + ac4[i] * 2, sa[i]);
        store_hl(bp + 20480 + brow * RS + bc4 * 2, bp + 25600 + brow * RS + bc4 * 2, sbv);
    }
    __syncthreads();

    const int lrow = lane & 15;
    const int lhik = ((lane >> 4) & 1) * 16;
    const int bn = (lane & 7) + ((lane >> 4) & 1) * 8;
    const int bhk = ((lane >> 3) & 1) * 16;

    const int NST = FDIM / 32;  // 112
    for (int s = 0; s < NST; s++) {
        if (s + 1 < NST) {
            int k0 = (s + 1) * 32;
            #pragma unroll
            for (int i = 0; i < 2; i++) sa[i] = *reinterpret_cast<const float4*>(asrc[i] + k0);
            sbv = *reinterpret_cast<const float4*>(bsrc + k0);
        }
        const uint32_t bb = sb + (uint32_t)(s & 1) * G2_STG;
        #pragma unroll
        for (int kk = 0; kk < 2; kk++) {
            const uint32_t koff = kk * 32;
            uint32_t Ah[2][4], Al[2][4];
            #pragma unroll
            for (int fm = 0; fm < 2; fm++) {
                uint32_t o = (uint32_t)((wm * 32 + fm * 16 + lrow) * RS) + koff + lhik;
                ldm_x4(Ah[fm], bb + o);
                ldm_x4(Al[fm], bb + 10240 + o);
            }
            uint32_t bo = (uint32_t)((wn * 16 + bn) * RS) + koff + bhk;
            uint32_t Bh[4], Bl[4];
            ldm_x4(Bh, bb + 20480 + bo);
            ldm_x4(Bl, bb + 25600 + bo);
            #pragma unroll
            for (int fm = 0; fm < 2; fm++) {
                #pragma unroll
                for (int fn = 0; fn < 2; fn++) {
                    mma4(acc[fm][fn], Ah[fm], Bh + 2 * fn);
                    mma4(acc[fm][fn], Ah[fm], Bl + 2 * fn);
                    mma4(acc[fm][fn], Al[fm], Bh + 2 * fn);
                }
            }
        }
        if (s + 1 < NST) {
            char* bp = sm + ((s + 1) & 1) * G2_STG;
            #pragma unroll
            for (int i = 0; i < 2; i++)
                store_hl(bp + arow[i] * RS + ac4[i] * 2, bp + 10240 + arow[i] * RS + ac4[i] * 2, sa[i]);
            store_hl(bp + 20480 + brow * RS + bc4 * 2, bp + 25600 + brow * RS + bc4 * 2, sbv);
            __syncthreads();
        }
    }

    // epilogue: scatter-add
    const int g = lane >> 2, tq = lane & 3;
    #pragma unroll
    for (int fm = 0; fm < 2; fm++) {
        #pragma unroll
        for (int fn = 0; fn < 2; fn++) {
            int rl = wm * 32 + fm * 16 + g;
            int c  = h0 + wn * 16 + fn * 8 + 2 * tq;
            if (m0 + rl < Ne) {
                float* o = out + (size_t)stok[rl] * HDIM + c;
                atomicAdd(o + 0, acc[fm][fn][0]);
                atomicAdd(o + 1, acc[fm][fn][1]);
            }
            if (m0 + rl + 8 < Ne) {
                float* o = out + (size_t)stok[rl + 8] * HDIM + c;
                atomicAdd(o + 0, acc[fm][fn][2]);
                atomicAdd(o + 1, acc[fm][fn][3]);
            }
        }
    }
}

// ---------------- launch ---------------------------------------------------
extern "C" void kernel_launch(void* const* d_in, const int* in_sizes, int n_in,
                              void* d_out, int out_size) {
    const float* x    = (const float*)d_in[0];
    const float* attn = (const float*)d_in[1];
    const float* gw   = (const float*)d_in[2];
    const float* w1   = (const float*)d_in[3];
    const float* w2   = (const float*)d_in[4];
    const float* w3   = (const float*)d_in[5];

    float* out = (float*)d_out;
    float* logits = (out_size >= (int)(T * HDIM + T * NEXP)) ? out + (size_t)T * HDIM
                                                             : nullptr;

    cudaFuncSetAttribute(gemm1_mma, cudaFuncAttributeMaxDynamicSharedMemorySize, G1_SMEM);
    cudaFuncSetAttribute(gemm2_mma, cudaFuncAttributeMaxDynamicSharedMemorySize, G2_SMEM);

    cudaMemsetAsync(d_out, 0, (size_t)T * HDIM * sizeof(float));
    router_kernel<<<T, 256>>>(x, gw, logits);
    attn_kernel<<<SEQ, 256>>>(attn);
    route_finalize_kernel<<<1, 1024>>>();
    gemm1_mma<<<dim3(16, FDIM / 64, NEXP), 512, G1_SMEM>>>(x, w1, w3);
    gemm2_mma<<<dim3(16, HDIM / 64, NEXP), 512, G2_SMEM>>>(w2, out);
}

// round 4
// speedup vs baseline: 2.0684x; 1.0742x over previous
#include <cuda_runtime.h>
#include <cuda_bf16.h>
#include <math.h>
#include <stdint.h>

#define T    2048
#define HDIM 1024
#define FDIM 3584
#define NEXP 8
#define NH   16
#define SEQ  2048
#define NSEL 204   // int(0.1 * 2048)

// ---------------- device scratch (no allocations allowed) ----------------
__device__ float g_scores[T];
__device__ float g_l1[T];
__device__ int   g_sel[T * 2];
__device__ float g_rw[T * 2];
__device__ int   g_top1prune[T];
__device__ int   g_low[T];
__device__ int   g_high[T];
__device__ int   g_cnt[NEXP];
__device__ int   g_ptok[NEXP * T];
__device__ float g_pw[NEXP * T];
__device__ float g_act[(size_t)NEXP * T * FDIM];  // fp32 activations

// ============================ helpers =====================================
__device__ __forceinline__ uint32_t smem_u32(const void* p) {
    uint32_t a;
    asm("{ .reg .u64 t; cvta.to.shared.u64 t, %1; cvt.u32.u64 %0, t; }" : "=r"(a) : "l"(p));
    return a;
}

__device__ __forceinline__ void ldm_x4(uint32_t r[4], uint32_t addr) {
    asm volatile("ldmatrix.sync.aligned.m8n8.x4.shared.b16 {%0,%1,%2,%3}, [%4];"
                 : "=r"(r[0]), "=r"(r[1]), "=r"(r[2]), "=r"(r[3]) : "r"(addr));
}

__device__ __forceinline__ void mma4(float d[4], const uint32_t a[4], const uint32_t b[2]) {
    asm volatile("mma.sync.aligned.m16n8k16.row.col.f32.bf16.bf16.f32 "
                 "{%0,%1,%2,%3}, {%4,%5,%6,%7}, {%8,%9}, {%0,%1,%2,%3};"
                 : "+f"(d[0]), "+f"(d[1]), "+f"(d[2]), "+f"(d[3])
                 : "r"(a[0]), "r"(a[1]), "r"(a[2]), "r"(a[3]), "r"(b[0]), "r"(b[1]));
}

__device__ __forceinline__ uint32_t pk(float a, float b) {
    return (uint32_t)__bfloat16_as_ushort(__float2bfloat16(a))
         | ((uint32_t)__bfloat16_as_ushort(__float2bfloat16(b)) << 16);
}
__device__ __forceinline__ void store_hl(char* ph, char* pl, float4 v) {
    float hx = __bfloat162float(__float2bfloat16(v.x));
    float hy = __bfloat162float(__float2bfloat16(v.y));
    float hz = __bfloat162float(__float2bfloat16(v.z));
    float hw = __bfloat162float(__float2bfloat16(v.w));
    uint2 uh; uh.x = pk(v.x, v.y); uh.y = pk(v.z, v.w);
    uint2 ul; ul.x = pk(v.x - hx, v.y - hy); ul.y = pk(v.z - hz, v.w - hw);
    *reinterpret_cast<uint2*>(ph) = uh;
    *reinterpret_cast<uint2*>(pl) = ul;
}

// row stride in smem: 32 bf16 data + 8 pad = 80 bytes (conflict-free)
#define RS 80

// gemm1 per-stage: AH 0, AL 10240, B1H 20480, B1L 25600, B3H 30720, B3L 35840
#define G1_STG   40960
#define G1_SMEM  (2 * G1_STG + 1024)
// gemm2 per-stage: AH 0, AL 10240, BH 20480, BL 25600
#define G2_STG   30720
#define G2_SMEM  (2 * G2_STG + 512)

// ---------------- kernel 1: router ---------------------------------------
__global__ void router_kernel(const float* __restrict__ x,
                              const float* __restrict__ gw,
                              float* logits_out) {
    int t = blockIdx.x;
    int lane = threadIdx.x & 31;
    int w = threadIdx.x >> 5;
    __shared__ float s_logit[NEXP];
    __shared__ float s_l1;

    const float* xr = x + (size_t)t * HDIM;
    const float* ge = gw + (size_t)w * HDIM;
    float acc = 0.f, l1 = 0.f;
    for (int i = lane; i < HDIM; i += 32) {
        float xv = xr[i];
        acc += xv * ge[i];
        l1 += fabsf(xv);
    }
    #pragma unroll
    for (int o = 16; o; o >>= 1) {
        acc += __shfl_xor_sync(0xffffffffu, acc, o);
        l1  += __shfl_xor_sync(0xffffffffu, l1, o);
    }
    if (lane == 0) {
        s_logit[w] = acc;
        if (w == 0) s_l1 = l1;
    }
    __syncthreads();
    if (threadIdx.x == 0) {
        float p[NEXP];
        float mx = s_logit[0];
        for (int e = 1; e < NEXP; e++) if (s_logit[e] > mx) mx = s_logit[e];
        float sum = 0.f;
        for (int e = 0; e < NEXP; e++) { p[e] = expf(s_logit[e] - mx); sum += p[e]; }
        float inv = 1.f / sum;
        for (int e = 0; e < NEXP; e++) p[e] *= inv;
        int i0 = 0;
        for (int e = 1; e < NEXP; e++) if (p[e] > p[i0]) i0 = e;
        int i1 = (i0 == 0) ? 1 : 0;
        for (int e = 0; e < NEXP; e++) if (e != i0 && p[e] > p[i1]) i1 = e;
        g_sel[2 * t] = i0;  g_sel[2 * t + 1] = i1;
        g_rw[2 * t] = p[i0]; g_rw[2 * t + 1] = p[i1];
        g_top1prune[t] = (p[i1] < 0.5f * p[i0]) ? 1 : 0;
        g_l1[t] = s_l1;
        if (logits_out) {
            for (int e = 0; e < NEXP; e++) logits_out[(size_t)t * NEXP + e] = s_logit[e];
        }
    }
}

// ---------------- kernel 2: attention-score reduction --------------------
__global__ void attn_kernel(const float* __restrict__ attn) {
    int i = blockIdx.x;
    float s = 0.f;
    for (int h = 0; h < NH; h++) {
        const float4* row = reinterpret_cast<const float4*>(attn + ((size_t)h * SEQ + i) * SEQ);
        for (int j = threadIdx.x; j < SEQ / 4; j += 256) {
            float4 v = row[j];
            s += v.x + v.y + v.z + v.w;
        }
    }
    __shared__ float red[256];
    red[threadIdx.x] = s;
    __syncthreads();
    for (int st = 128; st > 0; st >>= 1) {
        if (threadIdx.x < st) red[threadIdx.x] += red[threadIdx.x + st];
        __syncthreads();
    }
    if (threadIdx.x == 0)
        g_scores[i] = red[0] / (16.f * (float)(SEQ - i)) * g_l1[i];
}

// ---------------- kernel 3: top-k selection + routing finalize -----------
__global__ void route_finalize_kernel() {
    __shared__ float sval[T];
    __shared__ int   sidx[T];
    int tid = threadIdx.x;  // 1024 threads

    for (int t = tid; t < T; t += 1024) { g_low[t] = 0; g_high[t] = 0; }
    if (tid < NEXP) g_cnt[tid] = 0;

    for (int mode = 0; mode < 2; mode++) {
        __syncthreads();
        for (int t = tid; t < T; t += 1024) { sval[t] = g_scores[t]; sidx[t] = t; }
        __syncthreads();
        for (int k = 2; k <= T; k <<= 1) {
            for (int j = k >> 1; j > 0; j >>= 1) {
                #pragma unroll
                for (int s = 0; s < 2; s++) {
                    int i = tid + s * 1024;
                    int ixj = i ^ j;
                    if (ixj > i) {
                        float va = sval[i], vb = sval[ixj];
                        int ia = sidx[i], ib = sidx[ixj];
                        bool aBeforeB;
                        if (mode == 0)
                            aBeforeB = (va < vb) || (va == vb && ia < ib);
                        else
                            aBeforeB = (va > vb) || (va == vb && ia < ib);
                        bool up = ((i & k) == 0);
                        bool doswap = up ? !aBeforeB : aBeforeB;
                        if (doswap) {
                            sval[i] = vb; sval[ixj] = va;
                            sidx[i] = ib; sidx[ixj] = ia;
                        }
                    }
                }
                __syncthreads();
            }
        }
        for (int r = tid; r < NSEL; r += 1024) {
            if (mode == 0) g_low[sidx[r]] = 1;
            else           g_high[sidx[r]] = 1;
        }
        __syncthreads();
    }

    for (int t = tid; t < T; t += 1024) {
        float r0 = g_rw[2 * t], r1 = g_rw[2 * t + 1];
        float n0 = 1.f;
        float n1 = g_top1prune[t] ? 0.f : 1.f;
        if (g_low[t])  { n0 = 0.f; n1 = 0.f; }
        if (g_high[t]) { n0 = 1.f; n1 = 1.f; }
        r0 *= n0; r1 *= n1;
        float d = r0 + r1;
        if (d > 0.f) { r0 /= d; r1 /= d; }
        if (r0 > 0.f) {
            int e = g_sel[2 * t];
            int p = atomicAdd(&g_cnt[e], 1);
            g_ptok[e * T + p] = t;  g_pw[e * T + p] = r0;
        }
        if (r1 > 0.f) {
            int e = g_sel[2 * t + 1];
            int p = atomicAdd(&g_cnt[e], 1);
            g_ptok[e * T + p] = t;  g_pw[e * T + p] = r1;
        }
    }
}

// ---------------- gemm1: 128x64 tile, 8 warps (4x2), warp tile 32x32 -----
__global__ void __launch_bounds__(256, 2) gemm1_mma(const float* __restrict__ x,
                                                    const float* __restrict__ w1,
                                                    const float* __restrict__ w3) {
    extern __shared__ char sm[];
    const int e = blockIdx.z;
    const int Ne = g_cnt[e];
    const int m0 = blockIdx.x * 128;
    if (m0 >= Ne) return;
    const int f0 = blockIdx.y * 64;
    const int tid = threadIdx.x;
    const int lane = tid & 31, wid = tid >> 5;
    const int wm = wid & 3, wn = wid >> 2;   // 4 x 2 warp grid

    const uint32_t sb = smem_u32(sm);
    int*   stok = reinterpret_cast<int*>(sm + 2 * G1_STG);
    float* spw  = reinterpret_cast<float*>(sm + 2 * G1_STG + 512);
    if (tid < 128) {
        int m = m0 + tid; int tk = 0; float pw = 0.f;
        if (m < Ne) { tk = g_ptok[e * T + m]; pw = g_pw[e * T + m]; }
        stok[tid] = tk; spw[tid] = pw;
    }
    __syncthreads();

    // producer: A 4 float4/thread, B 4 float4/thread per stage
    const float* asrc[4]; int aoffH[4], aoffL[4];
    const float* bsrc[4]; int boffH[4], boffL[4];
    #pragma unroll
    for (int i = 0; i < 4; i++) {
        int idx = tid + i * 256;
        int ar = idx >> 3, ac4 = (idx & 7) << 2;
        asrc[i]  = x + (size_t)stok[ar] * HDIM + ac4;
        aoffH[i] = ar * RS + ac4 * 2;
        aoffL[i] = aoffH[i] + 10240;
        int bm = idx >> 9, br = (idx >> 3) & 63, bc4 = (idx & 7) << 2;
        const float* ws = bm ? w3 : w1;
        bsrc[i]  = ws + ((size_t)e * FDIM + f0 + br) * HDIM + bc4;
        boffH[i] = 20480 + bm * 10240 + br * RS + bc4 * 2;
        boffL[i] = boffH[i] + 5120;
    }

    // prologue: fill stage 0
    #pragma unroll
    for (int i = 0; i < 4; i++) store_hl(sm + aoffH[i], sm + aoffL[i], *reinterpret_cast<const float4*>(asrc[i]));
    #pragma unroll
    for (int i = 0; i < 4; i++) store_hl(sm + boffH[i], sm + boffL[i], *reinterpret_cast<const float4*>(bsrc[i]));
    __syncthreads();

    const int lrow = lane & 15;
    const int lhik = ((lane >> 4) & 1) * 16;
    const int bn = (lane & 7) + ((lane >> 4) & 1) * 8;
    const int bhk = ((lane >> 3) & 1) * 16;

    float hc[2][4][4] = {{{0.f}}}, gc[2][4][4] = {{{0.f}}};

    auto mma_blk = [&](uint32_t bb, uint32_t koff) {
        uint32_t Ah[2][4], Al[2][4];
        #pragma unroll
        for (int fm = 0; fm < 2; fm++) {
            uint32_t o = (uint32_t)((wm * 32 + fm * 16 + lrow) * RS) + koff + lhik;
            ldm_x4(Ah[fm], bb + o);
            ldm_x4(Al[fm], bb + 10240 + o);
        }
        #pragma unroll
        for (int fnh = 0; fnh < 2; fnh++) {
            uint32_t bo = (uint32_t)((wn * 32 + fnh * 16 + bn) * RS) + koff + bhk;
            uint32_t Bh[4], Bl[4];
            ldm_x4(Bh, bb + 20480 + bo);
            ldm_x4(Bl, bb + 25600 + bo);
            #pragma unroll
            for (int fm = 0; fm < 2; fm++)
                #pragma unroll
                for (int f2 = 0; f2 < 2; f2++) {
                    int fn = fnh * 2 + f2;
                    mma4(hc[fm][fn], Ah[fm], Bh + 2 * f2);
                    mma4(hc[fm][fn], Ah[fm], Bl + 2 * f2);
                    mma4(hc[fm][fn], Al[fm], Bh + 2 * f2);
                }
            ldm_x4(Bh, bb + 30720 + bo);
            ldm_x4(Bl, bb + 35840 + bo);
            #pragma unroll
            for (int fm = 0; fm < 2; fm++)
                #pragma unroll
                for (int f2 = 0; f2 < 2; f2++) {
                    int fn = fnh * 2 + f2;
                    mma4(gc[fm][fn], Ah[fm], Bh + 2 * f2);
                    mma4(gc[fm][fn], Ah[fm], Bl + 2 * f2);
                    mma4(gc[fm][fn], Al[fm], Bh + 2 * f2);
                }
        }
    };

    for (int s = 0; s < 32; s++) {
        const uint32_t bb = sb + (uint32_t)(s & 1) * G1_STG;
        char* bp = sm + ((s + 1) & 1) * G1_STG;
        const bool more = (s + 1 < 32);
        const int k0 = (s + 1) * 32;

        float4 av[4];
        if (more) {
            #pragma unroll
            for (int i = 0; i < 4; i++) av[i] = *reinterpret_cast<const float4*>(asrc[i] + k0);
        }
        mma_blk(bb, 0);
        if (more) {
            #pragma unroll
            for (int i = 0; i < 4; i++) store_hl(bp + aoffH[i], bp + aoffL[i], av[i]);
        }
        float4 bv[4];
        if (more) {
            #pragma unroll
            for (int i = 0; i < 4; i++) bv[i] = *reinterpret_cast<const float4*>(bsrc[i] + k0);
        }
        mma_blk(bb, 32);
        if (more) {
            #pragma unroll
            for (int i = 0; i < 4; i++) store_hl(bp + boffH[i], bp + boffL[i], bv[i]);
            __syncthreads();
        }
    }

    // epilogue: act = pw * g * silu(h)
    const int g = lane >> 2, tq = lane & 3;
    #pragma unroll
    for (int fm = 0; fm < 2; fm++) {
        #pragma unroll
        for (int fn = 0; fn < 4; fn++) {
            int rl = wm * 32 + fm * 16 + g;
            int c  = f0 + wn * 32 + fn * 8 + 2 * tq;
            float pw0 = spw[rl], pw1 = spw[rl + 8];
            float h0 = hc[fm][fn][0], h1 = hc[fm][fn][1];
            float h2 = hc[fm][fn][2], h3 = hc[fm][fn][3];
            float2 v0, v1;
            v0.x = pw0 * gc[fm][fn][0] * (h0 / (1.f + expf(-h0)));
            v0.y = pw0 * gc[fm][fn][1] * (h1 / (1.f + expf(-h1)));
            v1.x = pw1 * gc[fm][fn][2] * (h2 / (1.f + expf(-h2)));
            v1.y = pw1 * gc[fm][fn][3] * (h3 / (1.f + expf(-h3)));
            *reinterpret_cast<float2*>(g_act + ((size_t)(e * T + m0 + rl)) * FDIM + c) = v0;
            *reinterpret_cast<float2*>(g_act + ((size_t)(e * T + m0 + rl + 8)) * FDIM + c) = v1;
        }
    }
}

// ---------------- gemm2: 128x64 tile, 8 warps (4x2), warp tile 32x32 -----
__global__ void __launch_bounds__(256, 2) gemm2_mma(const float* __restrict__ w2,
                                                    float* __restrict__ out) {
    extern __shared__ char sm[];
    const int e = blockIdx.z;
    const int Ne = g_cnt[e];
    const int m0 = blockIdx.x * 128;
    if (m0 >= Ne) return;
    const int h0 = blockIdx.y * 64;
    const int tid = threadIdx.x;
    const int lane = tid & 31, wid = tid >> 5;
    const int wm = wid & 3, wn = wid >> 2;

    const uint32_t sb = smem_u32(sm);
    int* stok = reinterpret_cast<int*>(sm + 2 * G2_STG);
    if (tid < 128) {
        int m = m0 + tid; int tk = 0;
        if (m < Ne) tk = g_ptok[e * T + m];
        stok[tid] = tk;
    }
    __syncthreads();

    // producer: A 4 f4/thread, B 2 f4/thread per stage
    const float* asrc[4]; int aoffH[4], aoffL[4];
    const float* bsrc[2]; int boffH[2], boffL[2];
    #pragma unroll
    for (int i = 0; i < 4; i++) {
        int idx = tid + i * 256;
        int ar = idx >> 3, ac4 = (idx & 7) << 2;
        asrc[i]  = g_act + ((size_t)(e * T + m0 + ar)) * FDIM + ac4;
        aoffH[i] = ar * RS + ac4 * 2;
        aoffL[i] = aoffH[i] + 10240;
    }
    #pragma unroll
    for (int i = 0; i < 2; i++) {
        int idx = tid + i * 256;
        int br = idx >> 3, bc4 = (idx & 7) << 2;
        bsrc[i]  = w2 + ((size_t)e * HDIM + h0 + br) * FDIM + bc4;
        boffH[i] = 20480 + br * RS + bc4 * 2;
        boffL[i] = boffH[i] + 5120;
    }

    #pragma unroll
    for (int i = 0; i < 4; i++) store_hl(sm + aoffH[i], sm + aoffL[i], *reinterpret_cast<const float4*>(asrc[i]));
    #pragma unroll
    for (int i = 0; i < 2; i++) store_hl(sm + boffH[i], sm + boffL[i], *reinterpret_cast<const float4*>(bsrc[i]));
    __syncthreads();

    const int lrow = lane & 15;
    const int lhik = ((lane >> 4) & 1) * 16;
    const int bn = (lane & 7) + ((lane >> 4) & 1) * 8;
    const int bhk = ((lane >> 3) & 1) * 16;

    float acc[2][4][4] = {{{0.f}}};

    auto mma_blk = [&](uint32_t bb, uint32_t koff) {
        uint32_t Ah[2][4], Al[2][4];
        #pragma unroll
        for (int fm = 0; fm < 2; fm++) {
            uint32_t o = (uint32_t)((wm * 32 + fm * 16 + lrow) * RS) + koff + lhik;
            ldm_x4(Ah[fm], bb + o);
            ldm_x4(Al[fm], bb + 10240 + o);
        }
        #pragma unroll
        for (int fnh = 0; fnh < 2; fnh++) {
            uint32_t bo = (uint32_t)((wn * 32 + fnh * 16 + bn) * RS) + koff + bhk;
            uint32_t Bh[4], Bl[4];
            ldm_x4(Bh, bb + 20480 + bo);
            ldm_x4(Bl, bb + 25600 + bo);
            #pragma unroll
            for (int fm = 0; fm < 2; fm++)
                #pragma unroll
                for (int f2 = 0; f2 < 2; f2++) {
                    int fn = fnh * 2 + f2;
                    mma4(acc[fm][fn], Ah[fm], Bh + 2 * f2);
                    mma4(acc[fm][fn], Ah[fm], Bl + 2 * f2);
                    mma4(acc[fm][fn], Al[fm], Bh + 2 * f2);
                }
        }
    };

    const int NST = FDIM / 32;  // 112
    for (int s = 0; s < NST; s++) {
        const uint32_t bb = sb + (uint32_t)(s & 1) * G2_STG;
        char* bp = sm + ((s + 1) & 1) * G2_STG;
        const bool more = (s + 1 < NST);
        const int k0 = (s + 1) * 32;

        float4 av[4];
        if (more) {
            #pragma unroll
            for (int i = 0; i < 4; i++) av[i] = *reinterpret_cast<const float4*>(asrc[i] + k0);
        }
        mma_blk(bb, 0);
        if (more) {
            #pragma unroll
            for (int i = 0; i < 4; i++) store_hl(bp + aoffH[i], bp + aoffL[i], av[i]);
        }
        float4 bv[2];
        if (more) {
            #pragma unroll
            for (int i = 0; i < 2; i++) bv[i] = *reinterpret_cast<const float4*>(bsrc[i] + k0);
        }
        mma_blk(bb, 32);
        if (more) {
            #pragma unroll
            for (int i = 0; i < 2; i++) store_hl(bp + boffH[i], bp + boffL[i], bv[i]);
            __syncthreads();
        }
    }

    // epilogue: scatter-add
    const int g = lane >> 2, tq = lane & 3;
    #pragma unroll
    for (int fm = 0; fm < 2; fm++) {
        #pragma unroll
        for (int fn = 0; fn < 4; fn++) {
            int rl = wm * 32 + fm * 16 + g;
            int c  = h0 + wn * 32 + fn * 8 + 2 * tq;
            if (m0 + rl < Ne) {
                float* o = out + (size_t)stok[rl] * HDIM + c;
                atomicAdd(o + 0, acc[fm][fn][0]);
                atomicAdd(o + 1, acc[fm][fn][1]);
            }
            if (m0 + rl + 8 < Ne) {
                float* o = out + (size_t)stok[rl + 8] * HDIM + c;
                atomicAdd(o + 0, acc[fm][fn][2]);
                atomicAdd(o + 1, acc[fm][fn][3]);
            }
        }
    }
}

// ---------------- launch ---------------------------------------------------
extern "C" void kernel_launch(void* const* d_in, const int* in_sizes, int n_in,
                              void* d_out, int out_size) {
    const float* x    = (const float*)d_in[0];
    const float* attn = (const float*)d_in[1];
    const float* gw   = (const float*)d_in[2];
    const float* w1   = (const float*)d_in[3];
    const float* w2   = (const float*)d_in[4];
    const float* w3   = (const float*)d_in[5];

    float* out = (float*)d_out;
    float* logits = (out_size >= (int)(T * HDIM + T * NEXP)) ? out + (size_t)T * HDIM
                                                             : nullptr;

    cudaFuncSetAttribute(gemm1_mma, cudaFuncAttributeMaxDynamicSharedMemorySize, G1_SMEM);
    cudaFuncSetAttribute(gemm2_mma, cudaFuncAttributeMaxDynamicSharedMemorySize, G2_SMEM);

    cudaMemsetAsync(d_out, 0, (size_t)T * HDIM * sizeof(float));
    router_kernel<<<T, 256>>>(x, gw, logits);
    attn_kernel<<<SEQ, 256>>>(attn);
    route_finalize_kernel<<<1, 1024>>>();
    gemm1_mma<<<dim3(16, FDIM / 64, NEXP), 256, G1_SMEM>>>(x, w1, w3);
    gemm2_mma<<<dim3(16, HDIM / 64, NEXP), 256, G2_SMEM>>>(w2, out);
}

// round 5
// speedup vs baseline: 2.4044x; 1.1624x over previous
#include <cuda_runtime.h>
#include <cuda_bf16.h>
#include <math.h>
#include <stdint.h>

#define T    2048
#define HDIM 1024
#define FDIM 3584
#define NEXP 8
#define NH   16
#define SEQ  2048
#define NSEL 204   // int(0.1 * 2048)

// ---------------- device scratch (no allocations allowed) ----------------
__device__ float g_scores[T];
__device__ float g_l1[T];
__device__ int   g_sel[T * 2];
__device__ float g_rw[T * 2];
__device__ int   g_top1prune[T];
__device__ int   g_low[T];
__device__ int   g_high[T];
__device__ int   g_cnt[NEXP];
__device__ int   g_ptok[NEXP * T];
__device__ float g_pw[NEXP * T];
__device__ float g_act[(size_t)NEXP * T * FDIM];  // fp32 activations

// ============================ helpers =====================================
__device__ __forceinline__ uint32_t smem_u32(const void* p) {
    uint32_t a;
    asm("{ .reg .u64 t; cvta.to.shared.u64 t, %1; cvt.u32.u64 %0, t; }" : "=r"(a) : "l"(p));
    return a;
}

__device__ __forceinline__ void ldm_x4(uint32_t r[4], uint32_t addr) {
    asm volatile("ldmatrix.sync.aligned.m8n8.x4.shared.b16 {%0,%1,%2,%3}, [%4];"
                 : "=r"(r[0]), "=r"(r[1]), "=r"(r[2]), "=r"(r[3]) : "r"(addr));
}

__device__ __forceinline__ void mma4(float d[4], const uint32_t a[4], const uint32_t b[2]) {
    asm volatile("mma.sync.aligned.m16n8k16.row.col.f32.bf16.bf16.f32 "
                 "{%0,%1,%2,%3}, {%4,%5,%6,%7}, {%8,%9}, {%0,%1,%2,%3};"
                 : "+f"(d[0]), "+f"(d[1]), "+f"(d[2]), "+f"(d[3])
                 : "r"(a[0]), "r"(a[1]), "r"(a[2]), "r"(a[3]), "r"(b[0]), "r"(b[1]));
}

__device__ __forceinline__ uint32_t pk(float a, float b) {
    return (uint32_t)__bfloat16_as_ushort(__float2bfloat16(a))
         | ((uint32_t)__bfloat16_as_ushort(__float2bfloat16(b)) << 16);
}
__device__ __forceinline__ void store_hl(char* ph, char* pl, float4 v) {
    float hx = __bfloat162float(__float2bfloat16(v.x));
    float hy = __bfloat162float(__float2bfloat16(v.y));
    float hz = __bfloat162float(__float2bfloat16(v.z));
    float hw = __bfloat162float(__float2bfloat16(v.w));
    uint2 uh; uh.x = pk(v.x, v.y); uh.y = pk(v.z, v.w);
    uint2 ul; ul.x = pk(v.x - hx, v.y - hy); ul.y = pk(v.z - hz, v.w - hw);
    *reinterpret_cast<uint2*>(ph) = uh;
    *reinterpret_cast<uint2*>(pl) = ul;
}

// row stride in smem: 32 bf16 data + 8 pad = 80 bytes (conflict-free)
#define RS 80

// gemm1 per-stage: AH 0, AL 10240, B1H 20480, B1L 25600, B3H 30720, B3L 35840
#define G1_STG   40960
#define G1_SMEM  (2 * G1_STG + 1024)
// gemm2 per-stage: AH 0, AL 10240, BH 20480, BL 30720 (128 rows each)
#define G2_STG   40960
#define G2_SMEM  (2 * G2_STG + 512)

// ---------------- kernel 1: router ---------------------------------------
__global__ void router_kernel(const float* __restrict__ x,
                              const float* __restrict__ gw,
                              float* logits_out) {
    int t = blockIdx.x;
    int lane = threadIdx.x & 31;
    int w = threadIdx.x >> 5;
    __shared__ float s_logit[NEXP];
    __shared__ float s_l1;

    const float* xr = x + (size_t)t * HDIM;
    const float* ge = gw + (size_t)w * HDIM;
    float acc = 0.f, l1 = 0.f;
    for (int i = lane; i < HDIM; i += 32) {
        float xv = xr[i];
        acc += xv * ge[i];
        l1 += fabsf(xv);
    }
    #pragma unroll
    for (int o = 16; o; o >>= 1) {
        acc += __shfl_xor_sync(0xffffffffu, acc, o);
        l1  += __shfl_xor_sync(0xffffffffu, l1, o);
    }
    if (lane == 0) {
        s_logit[w] = acc;
        if (w == 0) s_l1 = l1;
    }
    __syncthreads();
    if (threadIdx.x == 0) {
        float p[NEXP];
        float mx = s_logit[0];
        for (int e = 1; e < NEXP; e++) if (s_logit[e] > mx) mx = s_logit[e];
        float sum = 0.f;
        for (int e = 0; e < NEXP; e++) { p[e] = expf(s_logit[e] - mx); sum += p[e]; }
        float inv = 1.f / sum;
        for (int e = 0; e < NEXP; e++) p[e] *= inv;
        int i0 = 0;
        for (int e = 1; e < NEXP; e++) if (p[e] > p[i0]) i0 = e;
        int i1 = (i0 == 0) ? 1 : 0;
        for (int e = 0; e < NEXP; e++) if (e != i0 && p[e] > p[i1]) i1 = e;
        g_sel[2 * t] = i0;  g_sel[2 * t + 1] = i1;
        g_rw[2 * t] = p[i0]; g_rw[2 * t + 1] = p[i1];
        g_top1prune[t] = (p[i1] < 0.5f * p[i0]) ? 1 : 0;
        g_l1[t] = s_l1;
        if (logits_out) {
            for (int e = 0; e < NEXP; e++) logits_out[(size_t)t * NEXP + e] = s_logit[e];
        }
    }
}

// ---------------- kernel 2: attention-score reduction --------------------
__global__ void attn_kernel(const float* __restrict__ attn) {
    int i = blockIdx.x;
    float s = 0.f;
    for (int h = 0; h < NH; h++) {
        const float4* row = reinterpret_cast<const float4*>(attn + ((size_t)h * SEQ + i) * SEQ);
        for (int j = threadIdx.x; j < SEQ / 4; j += 256) {
            float4 v = row[j];
            s += v.x + v.y + v.z + v.w;
        }
    }
    __shared__ float red[256];
    red[threadIdx.x] = s;
    __syncthreads();
    for (int st = 128; st > 0; st >>= 1) {
        if (threadIdx.x < st) red[threadIdx.x] += red[threadIdx.x + st];
        __syncthreads();
    }
    if (threadIdx.x == 0)
        g_scores[i] = red[0] / (16.f * (float)(SEQ - i)) * g_l1[i];
}

// ---------------- kernel 3: single bitonic sort + routing finalize -------
__global__ void route_finalize_kernel() {
    __shared__ float sval[T];
    __shared__ int   sidx[T];
    int tid = threadIdx.x;  // 1024 threads

    for (int t = tid; t < T; t += 1024) {
        g_low[t] = 0; g_high[t] = 0;
        sval[t] = g_scores[t]; sidx[t] = t;
    }
    if (tid < NEXP) g_cnt[tid] = 0;
    __syncthreads();

    // ascending bitonic sort (tie: idx asc)
    for (int k = 2; k <= T; k <<= 1) {
        for (int j = k >> 1; j > 0; j >>= 1) {
            #pragma unroll
            for (int s = 0; s < 2; s++) {
                int i = tid + s * 1024;
                int ixj = i ^ j;
                if (ixj > i) {
                    float va = sval[i], vb = sval[ixj];
                    int ia = sidx[i], ib = sidx[ixj];
                    bool aBeforeB = (va < vb) || (va == vb && ia < ib);
                    bool up = ((i & k) == 0);
                    bool doswap = up ? !aBeforeB : aBeforeB;
                    if (doswap) {
                        sval[i] = vb; sval[ixj] = va;
                        sidx[i] = ib; sidx[ixj] = ia;
                    }
                }
            }
            __syncthreads();
        }
    }
    for (int r = tid; r < NSEL; r += 1024) {
        g_low[sidx[r]] = 1;          // NSEL smallest
        g_high[sidx[T - 1 - r]] = 1; // NSEL largest
    }
    __syncthreads();

    for (int t = tid; t < T; t += 1024) {
        float r0 = g_rw[2 * t], r1 = g_rw[2 * t + 1];
        float n0 = 1.f;
        float n1 = g_top1prune[t] ? 0.f : 1.f;
        if (g_low[t])  { n0 = 0.f; n1 = 0.f; }
        if (g_high[t]) { n0 = 1.f; n1 = 1.f; }
        r0 *= n0; r1 *= n1;
        float d = r0 + r1;
        if (d > 0.f) { r0 /= d; r1 /= d; }
        if (r0 > 0.f) {
            int e = g_sel[2 * t];
            int p = atomicAdd(&g_cnt[e], 1);
            g_ptok[e * T + p] = t;  g_pw[e * T + p] = r0;
        }
        if (r1 > 0.f) {
            int e = g_sel[2 * t + 1];
            int p = atomicAdd(&g_cnt[e], 1);
            g_ptok[e * T + p] = t;  g_pw[e * T + p] = r1;
        }
    }
}

// ---------------- gemm1: 128x64 tile, 8 warps (4x2), warp tile 32x32 -----
__global__ void __launch_bounds__(256, 2) gemm1_mma(const float* __restrict__ x,
                                                    const float* __restrict__ w1,
                                                    const float* __restrict__ w3) {
    extern __shared__ char sm[];
    const int e = blockIdx.z;
    const int Ne = g_cnt[e];
    const int m0 = blockIdx.x * 128;
    if (m0 >= Ne) return;
    const int f0 = blockIdx.y * 64;
    const int tid = threadIdx.x;
    const int lane = tid & 31, wid = tid >> 5;
    const int wm = wid & 3, wn = wid >> 2;   // 4 x 2 warp grid

    const uint32_t sb = smem_u32(sm);
    int*   stok = reinterpret_cast<int*>(sm + 2 * G1_STG);
    float* spw  = reinterpret_cast<float*>(sm + 2 * G1_STG + 512);
    if (tid < 128) {
        int m = m0 + tid; int tk = 0; float pw = 0.f;
        if (m < Ne) { tk = g_ptok[e * T + m]; pw = g_pw[e * T + m]; }
        stok[tid] = tk; spw[tid] = pw;
    }
    __syncthreads();

    // producer mapping: A 4 float4/thread, B 4 float4/thread per stage
    const float* asrc[4]; int aoffH[4];
    const float* bsrc[4]; int boffH[4];
    #pragma unroll
    for (int i = 0; i < 4; i++) {
        int idx = tid + i * 256;
        int ar = idx >> 3, ac4 = (idx & 7) << 2;
        asrc[i]  = x + (size_t)stok[ar] * HDIM + ac4;
        aoffH[i] = ar * RS + ac4 * 2;
        int bm = idx >> 9, br = (idx >> 3) & 63, bc4 = (idx & 7) << 2;
        const float* ws = bm ? w3 : w1;
        bsrc[i]  = ws + ((size_t)e * FDIM + f0 + br) * HDIM + bc4;
        boffH[i] = 20480 + bm * 10240 + br * RS + bc4 * 2;
    }

    // prologue: fill stage 0
    #pragma unroll
    for (int i = 0; i < 4; i++)
        store_hl(sm + aoffH[i], sm + aoffH[i] + 10240, *reinterpret_cast<const float4*>(asrc[i]));
    #pragma unroll
    for (int i = 0; i < 4; i++)
        store_hl(sm + boffH[i], sm + boffH[i] + 5120, *reinterpret_cast<const float4*>(bsrc[i]));
    __syncthreads();

    const int lrow = lane & 15;
    const int lhik = ((lane >> 4) & 1) * 16;
    const int bn = (lane & 7) + ((lane >> 4) & 1) * 8;
    const int bhk = ((lane >> 3) & 1) * 16;

    float hc[2][4][4] = {{{0.f}}}, gc[2][4][4] = {{{0.f}}};

    auto mma_blk = [&](uint32_t bb, uint32_t koff) {
        uint32_t Ah[2][4], Al[2][4];
        #pragma unroll
        for (int fm = 0; fm < 2; fm++) {
            uint32_t o = (uint32_t)((wm * 32 + fm * 16 + lrow) * RS) + koff + lhik;
            ldm_x4(Ah[fm], bb + o);
            ldm_x4(Al[fm], bb + 10240 + o);
        }
        #pragma unroll
        for (int fnh = 0; fnh < 2; fnh++) {
            uint32_t bo = (uint32_t)((wn * 32 + fnh * 16 + bn) * RS) + koff + bhk;
            uint32_t Bh[4], Bl[4];
            ldm_x4(Bh, bb + 20480 + bo);
            ldm_x4(Bl, bb + 25600 + bo);
            #pragma unroll
            for (int fm = 0; fm < 2; fm++)
                #pragma unroll
                for (int f2 = 0; f2 < 2; f2++) {
                    int fn = fnh * 2 + f2;
                    mma4(hc[fm][fn], Ah[fm], Bh + 2 * f2);
                    mma4(hc[fm][fn], Ah[fm], Bl + 2 * f2);
                    mma4(hc[fm][fn], Al[fm], Bh + 2 * f2);
                }
            ldm_x4(Bh, bb + 30720 + bo);
            ldm_x4(Bl, bb + 35840 + bo);
            #pragma unroll
            for (int fm = 0; fm < 2; fm++)
                #pragma unroll
                for (int f2 = 0; f2 < 2; f2++) {
                    int fn = fnh * 2 + f2;
                    mma4(gc[fm][fn], Ah[fm], Bh + 2 * f2);
                    mma4(gc[fm][fn], Ah[fm], Bl + 2 * f2);
                    mma4(gc[fm][fn], Al[fm], Bh + 2 * f2);
                }
        }
    };

    for (int s = 0; s < 32; s++) {
        const uint32_t bb = sb + (uint32_t)(s & 1) * G1_STG;
        char* bp = sm + ((s + 1) & 1) * G1_STG;
        const bool more = (s + 1 < 32);
        const int k0 = (s + 1) * 32;

        mma_blk(bb, 0);
        if (more) {
            // LDG immediately consumed by STS (2 float4 live at a time): no
            // long-lived staging registers, no spills. The ~250cy L2 latency
            // stalls only this warp; 15 other warps keep the tensor pipe fed.
            #pragma unroll
            for (int i = 0; i < 4; i += 2) {
                float4 v0 = *reinterpret_cast<const float4*>(asrc[i] + k0);
                float4 v1 = *reinterpret_cast<const float4*>(asrc[i + 1] + k0);
                store_hl(bp + aoffH[i], bp + aoffH[i] + 10240, v0);
                store_hl(bp + aoffH[i + 1], bp + aoffH[i + 1] + 10240, v1);
            }
        }
        mma_blk(bb, 32);
        if (more) {
            #pragma unroll
            for (int i = 0; i < 4; i += 2) {
                float4 v0 = *reinterpret_cast<const float4*>(bsrc[i] + k0);
                float4 v1 = *reinterpret_cast<const float4*>(bsrc[i + 1] + k0);
                store_hl(bp + boffH[i], bp + boffH[i] + 5120, v0);
                store_hl(bp + boffH[i + 1], bp + boffH[i + 1] + 5120, v1);
            }
            __syncthreads();
        }
    }

    // epilogue: act = pw * g * silu(h)
    const int g = lane >> 2, tq = lane & 3;
    #pragma unroll
    for (int fm = 0; fm < 2; fm++) {
        #pragma unroll
        for (int fn = 0; fn < 4; fn++) {
            int rl = wm * 32 + fm * 16 + g;
            int c  = f0 + wn * 32 + fn * 8 + 2 * tq;
            float pw0 = spw[rl], pw1 = spw[rl + 8];
            float h0 = hc[fm][fn][0], h1 = hc[fm][fn][1];
            float h2 = hc[fm][fn][2], h3 = hc[fm][fn][3];
            float2 v0, v1;
            v0.x = pw0 * gc[fm][fn][0] * (h0 / (1.f + expf(-h0)));
            v0.y = pw0 * gc[fm][fn][1] * (h1 / (1.f + expf(-h1)));
            v1.x = pw1 * gc[fm][fn][2] * (h2 / (1.f + expf(-h2)));
            v1.y = pw1 * gc[fm][fn][3] * (h3 / (1.f + expf(-h3)));
            *reinterpret_cast<float2*>(g_act + ((size_t)(e * T + m0 + rl)) * FDIM + c) = v0;
            *reinterpret_cast<float2*>(g_act + ((size_t)(e * T + m0 + rl + 8)) * FDIM + c) = v1;
        }
    }
}

// ---------------- gemm2: 128x128 tile, 8 warps (2x4), warp tile 64x32 ----
__global__ void __launch_bounds__(256, 2) gemm2_mma(const float* __restrict__ w2,
                                                    float* __restrict__ out) {
    extern __shared__ char sm[];
    const int e = blockIdx.z;
    const int Ne = g_cnt[e];
    const int m0 = blockIdx.x * 128;
    if (m0 >= Ne) return;
    const int n0 = blockIdx.y * 128;
    const int tid = threadIdx.x;
    const int lane = tid & 31, wid = tid >> 5;
    const int wm = wid & 1, wn = wid >> 1;   // 2 x 4 warp grid

    const uint32_t sb = smem_u32(sm);
    int* stok = reinterpret_cast<int*>(sm + 2 * G2_STG);
    if (tid < 128) {
        int m = m0 + tid; int tk = 0;
        if (m < Ne) tk = g_ptok[e * T + m];
        stok[tid] = tk;
    }
    __syncthreads();

    // producer: A 4 f4/thread, B 4 f4/thread per stage (128 rows each)
    const float* asrc[4]; int aoffH[4];
    const float* bsrc[4]; int boffH[4];
    #pragma unroll
    for (int i = 0; i < 4; i++) {
        int idx = tid + i * 256;
        int r = idx >> 3, c4 = (idx & 7) << 2;
        asrc[i]  = g_act + ((size_t)(e * T + m0 + r)) * FDIM + c4;
        aoffH[i] = r * RS + c4 * 2;
        bsrc[i]  = w2 + ((size_t)e * HDIM + n0 + r) * FDIM + c4;
        boffH[i] = 20480 + r * RS + c4 * 2;
    }

    #pragma unroll
    for (int i = 0; i < 4; i++)
        store_hl(sm + aoffH[i], sm + aoffH[i] + 10240, *reinterpret_cast<const float4*>(asrc[i]));
    #pragma unroll
    for (int i = 0; i < 4; i++)
        store_hl(sm + boffH[i], sm + boffH[i] + 10240, *reinterpret_cast<const float4*>(bsrc[i]));
    __syncthreads();

    const int lrow = lane & 15;
    const int lhik = ((lane >> 4) & 1) * 16;
    const int bn = (lane & 7) + ((lane >> 4) & 1) * 8;
    const int bhk = ((lane >> 3) & 1) * 16;

    float acc[4][4][4] = {{{0.f}}};

    auto mma_blk = [&](uint32_t bb, uint32_t koff) {
        uint32_t Bh[2][4], Bl[2][4];
        #pragma unroll
        for (int f2 = 0; f2 < 2; f2++) {
            uint32_t bo = (uint32_t)((wn * 32 + f2 * 16 + bn) * RS) + koff + bhk;
            ldm_x4(Bh[f2], bb + 20480 + bo);
            ldm_x4(Bl[f2], bb + 30720 + bo);
        }
        #pragma unroll
        for (int fm = 0; fm < 4; fm++) {
            uint32_t Ah[4], Al[4];
            uint32_t o = (uint32_t)((wm * 64 + fm * 16 + lrow) * RS) + koff + lhik;
            ldm_x4(Ah, bb + o);
            ldm_x4(Al, bb + 10240 + o);
            #pragma unroll
            for (int f2 = 0; f2 < 2; f2++)
                #pragma unroll
                for (int j = 0; j < 2; j++) {
                    int fn = f2 * 2 + j;
                    mma4(acc[fm][fn], Ah, Bh[f2] + 2 * j);
                    mma4(acc[fm][fn], Ah, Bl[f2] + 2 * j);
                    mma4(acc[fm][fn], Al, Bh[f2] + 2 * j);
                }
        }
    };

    const int NST = FDIM / 32;  // 112
    for (int s = 0; s < NST; s++) {
        const uint32_t bb = sb + (uint32_t)(s & 1) * G2_STG;
        char* bp = sm + ((s + 1) & 1) * G2_STG;
        const bool more = (s + 1 < NST);
        const int k0 = (s + 1) * 32;

        mma_blk(bb, 0);
        if (more) {
            #pragma unroll
            for (int i = 0; i < 4; i += 2) {
                float4 v0 = *reinterpret_cast<const float4*>(asrc[i] + k0);
                float4 v1 = *reinterpret_cast<const float4*>(asrc[i + 1] + k0);
                store_hl(bp + aoffH[i], bp + aoffH[i] + 10240, v0);
                store_hl(bp + aoffH[i + 1], bp + aoffH[i + 1] + 10240, v1);
            }
        }
        mma_blk(bb, 32);
        if (more) {
            #pragma unroll
            for (int i = 0; i < 4; i += 2) {
                float4 v0 = *reinterpret_cast<const float4*>(bsrc[i] + k0);
                float4 v1 = *reinterpret_cast<const float4*>(bsrc[i + 1] + k0);
                store_hl(bp + boffH[i], bp + boffH[i] + 10240, v0);
                store_hl(bp + boffH[i + 1], bp + boffH[i + 1] + 10240, v1);
            }
            __syncthreads();
        }
    }

    // epilogue: scatter-add
    const int g = lane >> 2, tq = lane & 3;
    #pragma unroll
    for (int fm = 0; fm < 4; fm++) {
        #pragma unroll
        for (int fn = 0; fn < 4; fn++) {
            int rl = wm * 64 + fm * 16 + g;
            int c  = n0 + wn * 32 + fn * 8 + 2 * tq;
            if (m0 + rl < Ne) {
                float* o = out + (size_t)stok[rl] * HDIM + c;
                atomicAdd(o + 0, acc[fm][fn][0]);
                atomicAdd(o + 1, acc[fm][fn][1]);
            }
            if (m0 + rl + 8 < Ne) {
                float* o = out + (size_t)stok[rl + 8] * HDIM + c;
                atomicAdd(o + 0, acc[fm][fn][2]);
                atomicAdd(o + 1, acc[fm][fn][3]);
            }
        }
    }
}

// ---------------- launch ---------------------------------------------------
extern "C" void kernel_launch(void* const* d_in, const int* in_sizes, int n_in,
                              void* d_out, int out_size) {
    const float* x    = (const float*)d_in[0];
    const float* attn = (const float*)d_in[1];
    const float* gw   = (const float*)d_in[2];
    const float* w1   = (const float*)d_in[3];
    const float* w2   = (const float*)d_in[4];
    const float* w3   = (const float*)d_in[5];

    float* out = (float*)d_out;
    float* logits = (out_size >= (int)(T * HDIM + T * NEXP)) ? out + (size_t)T * HDIM
                                                             : nullptr;

    cudaFuncSetAttribute(gemm1_mma, cudaFuncAttributeMaxDynamicSharedMemorySize, G1_SMEM);
    cudaFuncSetAttribute(gemm2_mma, cudaFuncAttributeMaxDynamicSharedMemorySize, G2_SMEM);

    cudaMemsetAsync(d_out, 0, (size_t)T * HDIM * sizeof(float));
    router_kernel<<<T, 256>>>(x, gw, logits);
    attn_kernel<<<SEQ, 256>>>(attn);
    route_finalize_kernel<<<1, 1024>>>();
    gemm1_mma<<<dim3(16, FDIM / 64, NEXP), 256, G1_SMEM>>>(x, w1, w3);
    gemm2_mma<<<dim3(16, HDIM / 128, NEXP), 256, G2_SMEM>>>(w2, out);
}

// round 6
// speedup vs baseline: 3.8338x; 1.5945x over previous
#include <cuda_runtime.h>
#include <cuda_fp16.h>
#include <math.h>
#include <stdint.h>

#define T    2048
#define HDIM 1024
#define FDIM 3584
#define NEXP 8
#define NH   16
#define SEQ  2048
#define NSEL 204   // int(0.1 * 2048)

// ---------------- device scratch (no allocations allowed) ----------------
__device__ float g_scores[T];
__device__ float g_l1[T];
__device__ int   g_sel[T * 2];
__device__ float g_rw[T * 2];
__device__ int   g_top1prune[T];
__device__ int   g_low[T];
__device__ int   g_high[T];
__device__ int   g_cnt[NEXP];
__device__ int   g_ptok[NEXP * T];
__device__ float g_pw[NEXP * T];
__device__ float g_act[(size_t)NEXP * T * FDIM];  // fp32 activations

// ============================ helpers =====================================
__device__ __forceinline__ uint32_t smem_u32(const void* p) {
    uint32_t a;
    asm("{ .reg .u64 t; cvta.to.shared.u64 t, %1; cvt.u32.u64 %0, t; }" : "=r"(a) : "l"(p));
    return a;
}

__device__ __forceinline__ void ldm_x4(uint32_t r[4], uint32_t addr) {
    asm volatile("ldmatrix.sync.aligned.m8n8.x4.shared.b16 {%0,%1,%2,%3}, [%4];"
                 : "=r"(r[0]), "=r"(r[1]), "=r"(r[2]), "=r"(r[3]) : "r"(addr));
}

__device__ __forceinline__ void mma4(float d[4], const uint32_t a[4], const uint32_t b[2]) {
    asm volatile("mma.sync.aligned.m16n8k16.row.col.f32.f16.f16.f32 "
                 "{%0,%1,%2,%3}, {%4,%5,%6,%7}, {%8,%9}, {%0,%1,%2,%3};"
                 : "+f"(d[0]), "+f"(d[1]), "+f"(d[2]), "+f"(d[3])
                 : "r"(a[0]), "r"(a[1]), "r"(a[2]), "r"(a[3]), "r"(b[0]), "r"(b[1]));
}

// convert float4 -> 4 fp16, store 8B
__device__ __forceinline__ void store_h(char* p, float4 v) {
    uint2 u;
    u.x = (uint32_t)__half_as_ushort(__float2half(v.x))
        | ((uint32_t)__half_as_ushort(__float2half(v.y)) << 16);
    u.y = (uint32_t)__half_as_ushort(__float2half(v.z))
        | ((uint32_t)__half_as_ushort(__float2half(v.w)) << 16);
    *reinterpret_cast<uint2*>(p) = u;
}

// row stride: 64 fp16 (128B) + 16B pad = 144B, conflict-free for ldmatrix
#define RS2 144

// gemm1 per-stage (K=64): A 128x144 @0, B1 64x144 @18432, B3 64x144 @27648
#define G1_STG   36864
#define G1_SMEM  (2 * G1_STG + 1024)
// gemm2 per-stage (K=64): A 128x144 @0, B 128x144 @18432
#define G2_STG   36864
#define G2_SMEM  (2 * G2_STG + 512)

// ---------------- kernel 1: router ---------------------------------------
__global__ void router_kernel(const float* __restrict__ x,
                              const float* __restrict__ gw,
                              float* logits_out) {
    int t = blockIdx.x;
    int lane = threadIdx.x & 31;
    int w = threadIdx.x >> 5;
    __shared__ float s_logit[NEXP];
    __shared__ float s_l1;

    const float* xr = x + (size_t)t * HDIM;
    const float* ge = gw + (size_t)w * HDIM;
    float acc = 0.f, l1 = 0.f;
    for (int i = lane; i < HDIM; i += 32) {
        float xv = xr[i];
        acc += xv * ge[i];
        l1 += fabsf(xv);
    }
    #pragma unroll
    for (int o = 16; o; o >>= 1) {
        acc += __shfl_xor_sync(0xffffffffu, acc, o);
        l1  += __shfl_xor_sync(0xffffffffu, l1, o);
    }
    if (lane == 0) {
        s_logit[w] = acc;
        if (w == 0) s_l1 = l1;
    }
    __syncthreads();
    if (threadIdx.x == 0) {
        float p[NEXP];
        float mx = s_logit[0];
        for (int e = 1; e < NEXP; e++) if (s_logit[e] > mx) mx = s_logit[e];
        float sum = 0.f;
        for (int e = 0; e < NEXP; e++) { p[e] = expf(s_logit[e] - mx); sum += p[e]; }
        float inv = 1.f / sum;
        for (int e = 0; e < NEXP; e++) p[e] *= inv;
        int i0 = 0;
        for (int e = 1; e < NEXP; e++) if (p[e] > p[i0]) i0 = e;
        int i1 = (i0 == 0) ? 1 : 0;
        for (int e = 0; e < NEXP; e++) if (e != i0 && p[e] > p[i1]) i1 = e;
        g_sel[2 * t] = i0;  g_sel[2 * t + 1] = i1;
        g_rw[2 * t] = p[i0]; g_rw[2 * t + 1] = p[i1];
        g_top1prune[t] = (p[i1] < 0.5f * p[i0]) ? 1 : 0;
        g_l1[t] = s_l1;
        if (logits_out) {
            for (int e = 0; e < NEXP; e++) logits_out[(size_t)t * NEXP + e] = s_logit[e];
        }
    }
}

// ---------------- kernel 2: attention-score reduction --------------------
__global__ void attn_kernel(const float* __restrict__ attn) {
    int i = blockIdx.x;
    float s = 0.f;
    for (int h = 0; h < NH; h++) {
        const float4* row = reinterpret_cast<const float4*>(attn + ((size_t)h * SEQ + i) * SEQ);
        for (int j = threadIdx.x; j < SEQ / 4; j += 256) {
            float4 v = row[j];
            s += v.x + v.y + v.z + v.w;
        }
    }
    __shared__ float red[256];
    red[threadIdx.x] = s;
    __syncthreads();
    for (int st = 128; st > 0; st >>= 1) {
        if (threadIdx.x < st) red[threadIdx.x] += red[threadIdx.x + st];
        __syncthreads();
    }
    if (threadIdx.x == 0)
        g_scores[i] = red[0] / (16.f * (float)(SEQ - i)) * g_l1[i];
}

// ---------------- kernel 3: single bitonic sort + routing finalize -------
__global__ void route_finalize_kernel() {
    __shared__ float sval[T];
    __shared__ int   sidx[T];
    int tid = threadIdx.x;  // 1024 threads

    for (int t = tid; t < T; t += 1024) {
        g_low[t] = 0; g_high[t] = 0;
        sval[t] = g_scores[t]; sidx[t] = t;
    }
    if (tid < NEXP) g_cnt[tid] = 0;
    __syncthreads();

    for (int k = 2; k <= T; k <<= 1) {
        for (int j = k >> 1; j > 0; j >>= 1) {
            #pragma unroll
            for (int s = 0; s < 2; s++) {
                int i = tid + s * 1024;
                int ixj = i ^ j;
                if (ixj > i) {
                    float va = sval[i], vb = sval[ixj];
                    int ia = sidx[i], ib = sidx[ixj];
                    bool aBeforeB = (va < vb) || (va == vb && ia < ib);
                    bool up = ((i & k) == 0);
                    bool doswap = up ? !aBeforeB : aBeforeB;
                    if (doswap) {
                        sval[i] = vb; sval[ixj] = va;
                        sidx[i] = ib; sidx[ixj] = ia;
                    }
                }
            }
            __syncthreads();
        }
    }
    for (int r = tid; r < NSEL; r += 1024) {
        g_low[sidx[r]] = 1;
        g_high[sidx[T - 1 - r]] = 1;
    }
    __syncthreads();

    for (int t = tid; t < T; t += 1024) {
        float r0 = g_rw[2 * t], r1 = g_rw[2 * t + 1];
        float n0 = 1.f;
        float n1 = g_top1prune[t] ? 0.f : 1.f;
        if (g_low[t])  { n0 = 0.f; n1 = 0.f; }
        if (g_high[t]) { n0 = 1.f; n1 = 1.f; }
        r0 *= n0; r1 *= n1;
        float d = r0 + r1;
        if (d > 0.f) { r0 /= d; r1 /= d; }
        if (r0 > 0.f) {
            int e = g_sel[2 * t];
            int p = atomicAdd(&g_cnt[e], 1);
            g_ptok[e * T + p] = t;  g_pw[e * T + p] = r0;
        }
        if (r1 > 0.f) {
            int e = g_sel[2 * t + 1];
            int p = atomicAdd(&g_cnt[e], 1);
            g_ptok[e * T + p] = t;  g_pw[e * T + p] = r1;
        }
    }
}

// ---------------- gemm1: fp16 1-pass, 128x64 tile, warps 4x2 -------------
__global__ void __launch_bounds__(256, 2) gemm1_mma(const float* __restrict__ x,
                                                    const float* __restrict__ w1,
                                                    const float* __restrict__ w3) {
    extern __shared__ char sm[];
    const int e = blockIdx.z;
    const int Ne = g_cnt[e];
    const int m0 = blockIdx.x * 128;
    if (m0 >= Ne) return;
    const int f0 = blockIdx.y * 64;
    const int tid = threadIdx.x;
    const int lane = tid & 31, wid = tid >> 5;
    const int wm = wid & 3, wn = wid >> 2;   // 4m x 2n warp grid

    const uint32_t sb = smem_u32(sm);
    int*   stok = reinterpret_cast<int*>(sm + 2 * G1_STG);
    float* spw  = reinterpret_cast<float*>(sm + 2 * G1_STG + 512);
    if (tid < 128) {
        int m = m0 + tid; int tk = 0; float pw = 0.f;
        if (m < Ne) { tk = g_ptok[e * T + m]; pw = g_pw[e * T + m]; }
        stok[tid] = tk; spw[tid] = pw;
    }
    __syncthreads();

    // producer mapping: per stage (K=64) A 8 float4/thread, B 8 float4/thread
    int abase[8], aoff[8];
    int bbase[8], boff[8];
    const float* wsel[8];
    #pragma unroll
    for (int i = 0; i < 8; i++) {
        int idx = tid + i * 256;               // [0, 2048)
        int ar = idx >> 4, ac4 = (idx & 15) << 2;
        abase[i] = stok[ar] * HDIM + ac4;
        aoff[i]  = ar * RS2 + ac4 * 2;
        int bm = idx >> 10, br = (idx >> 4) & 63, bc4 = (idx & 15) << 2;
        wsel[i]  = bm ? w3 : w1;
        bbase[i] = (e * FDIM + f0 + br) * HDIM + bc4;
        boff[i]  = 18432 + bm * 9216 + br * RS2 + bc4 * 2;
    }

    // prologue: fill stage 0
    #pragma unroll
    for (int i = 0; i < 8; i++)
        store_h(sm + aoff[i], *reinterpret_cast<const float4*>(x + abase[i]));
    #pragma unroll
    for (int i = 0; i < 8; i++)
        store_h(sm + boff[i], *reinterpret_cast<const float4*>(wsel[i] + bbase[i]));
    __syncthreads();

    const int lrow = lane & 15;
    const int lhik = ((lane >> 4) & 1) * 16;
    const int bn = (lane & 7) + ((lane >> 4) & 1) * 8;
    const int bhk = ((lane >> 3) & 1) * 16;

    float hc[2][4][4] = {{{0.f}}}, gc[2][4][4] = {{{0.f}}};

    auto mma_blk = [&](uint32_t bb, int kk) {
        const uint32_t koff = (uint32_t)kk * 32;
        uint32_t Ah[2][4];
        #pragma unroll
        for (int fm = 0; fm < 2; fm++)
            ldm_x4(Ah[fm], bb + (uint32_t)((wm * 32 + fm * 16 + lrow) * RS2) + koff + lhik);
        #pragma unroll
        for (int fnh = 0; fnh < 2; fnh++) {
            uint32_t bo = (uint32_t)((wn * 32 + fnh * 16 + bn) * RS2) + koff + bhk;
            uint32_t B1[4], B3[4];
            ldm_x4(B1, bb + 18432 + bo);
            ldm_x4(B3, bb + 27648 + bo);
            #pragma unroll
            for (int fm = 0; fm < 2; fm++)
                #pragma unroll
                for (int f2 = 0; f2 < 2; f2++) {
                    int fn = fnh * 2 + f2;
                    mma4(hc[fm][fn], Ah[fm], B1 + 2 * f2);
                    mma4(gc[fm][fn], Ah[fm], B3 + 2 * f2);
                }
        }
    };

    for (int s = 0; s < 16; s++) {
        const uint32_t bb = sb + (uint32_t)(s & 1) * G1_STG;
        char* bp = sm + ((s + 1) & 1) * G1_STG;
        const bool more = (s + 1 < 16);
        const int k0 = (s + 1) * 64;

        mma_blk(bb, 0);
        if (more) {
            #pragma unroll
            for (int i = 0; i < 4; i++)
                store_h(bp + aoff[i], *reinterpret_cast<const float4*>(x + abase[i] + k0));
        }
        mma_blk(bb, 1);
        if (more) {
            #pragma unroll
            for (int i = 4; i < 8; i++)
                store_h(bp + aoff[i], *reinterpret_cast<const float4*>(x + abase[i] + k0));
        }
        mma_blk(bb, 2);
        if (more) {
            #pragma unroll
            for (int i = 0; i < 4; i++)
                store_h(bp + boff[i], *reinterpret_cast<const float4*>(wsel[i] + bbase[i] + k0));
        }
        mma_blk(bb, 3);
        if (more) {
            #pragma unroll
            for (int i = 4; i < 8; i++)
                store_h(bp + boff[i], *reinterpret_cast<const float4*>(wsel[i] + bbase[i] + k0));
            __syncthreads();
        }
    }

    // epilogue: act = pw * g * silu(h)
    const int g = lane >> 2, tq = lane & 3;
    #pragma unroll
    for (int fm = 0; fm < 2; fm++) {
        #pragma unroll
        for (int fn = 0; fn < 4; fn++) {
            int rl = wm * 32 + fm * 16 + g;
            int c  = f0 + wn * 32 + fn * 8 + 2 * tq;
            float pw0 = spw[rl], pw1 = spw[rl + 8];
            float h0 = hc[fm][fn][0], h1 = hc[fm][fn][1];
            float h2 = hc[fm][fn][2], h3 = hc[fm][fn][3];
            float2 v0, v1;
            v0.x = pw0 * gc[fm][fn][0] * (h0 / (1.f + expf(-h0)));
            v0.y = pw0 * gc[fm][fn][1] * (h1 / (1.f + expf(-h1)));
            v1.x = pw1 * gc[fm][fn][2] * (h2 / (1.f + expf(-h2)));
            v1.y = pw1 * gc[fm][fn][3] * (h3 / (1.f + expf(-h3)));
            *reinterpret_cast<float2*>(g_act + ((size_t)(e * T + m0 + rl)) * FDIM + c) = v0;
            *reinterpret_cast<float2*>(g_act + ((size_t)(e * T + m0 + rl + 8)) * FDIM + c) = v1;
        }
    }
}

// ---------------- gemm2: fp16 1-pass, 128x128 tile, warps 2x4 ------------
__global__ void __launch_bounds__(256, 2) gemm2_mma(const float* __restrict__ w2,
                                                    float* __restrict__ out) {
    extern __shared__ char sm[];
    const int e = blockIdx.z;
    const int Ne = g_cnt[e];
    const int m0 = blockIdx.x * 128;
    if (m0 >= Ne) return;
    const int n0 = blockIdx.y * 128;
    const int tid = threadIdx.x;
    const int lane = tid & 31, wid = tid >> 5;
    const int wm = wid & 1, wn = wid >> 1;   // 2m x 4n warp grid

    const uint32_t sb = smem_u32(sm);
    int* stok = reinterpret_cast<int*>(sm + 2 * G2_STG);
    if (tid < 128) {
        int m = m0 + tid; int tk = 0;
        if (m < Ne) tk = g_ptok[e * T + m];
        stok[tid] = tk;
    }
    __syncthreads();

    int abase[8], aoff[8];
    int bbase[8], boff[8];
    #pragma unroll
    for (int i = 0; i < 8; i++) {
        int idx = tid + i * 256;
        int r = idx >> 4, c4 = (idx & 15) << 2;
        abase[i] = (e * T + m0 + r) * FDIM + c4;
        aoff[i]  = r * RS2 + c4 * 2;
        bbase[i] = (e * HDIM + n0 + r) * FDIM + c4;
        boff[i]  = 18432 + r * RS2 + c4 * 2;
    }

    #pragma unroll
    for (int i = 0; i < 8; i++)
        store_h(sm + aoff[i], *reinterpret_cast<const float4*>(g_act + abase[i]));
    #pragma unroll
    for (int i = 0; i < 8; i++)
        store_h(sm + boff[i], *reinterpret_cast<const float4*>(w2 + bbase[i]));
    __syncthreads();

    const int lrow = lane & 15;
    const int lhik = ((lane >> 4) & 1) * 16;
    const int bn = (lane & 7) + ((lane >> 4) & 1) * 8;
    const int bhk = ((lane >> 3) & 1) * 16;

    float acc[4][4][4] = {{{0.f}}};

    auto mma_blk = [&](uint32_t bb, int kk) {
        const uint32_t koff = (uint32_t)kk * 32;
        uint32_t Bf[2][4];
        #pragma unroll
        for (int f2 = 0; f2 < 2; f2++)
            ldm_x4(Bf[f2], bb + 18432 + (uint32_t)((wn * 32 + f2 * 16 + bn) * RS2) + koff + bhk);
        #pragma unroll
        for (int fm = 0; fm < 4; fm++) {
            uint32_t Af[4];
            ldm_x4(Af, bb + (uint32_t)((wm * 64 + fm * 16 + lrow) * RS2) + koff + lhik);
            #pragma unroll
            for (int f2 = 0; f2 < 2; f2++)
                #pragma unroll
                for (int j = 0; j < 2; j++)
                    mma4(acc[fm][f2 * 2 + j], Af, Bf[f2] + 2 * j);
        }
    };

    const int NST = FDIM / 64;  // 56
    for (int s = 0; s < NST; s++) {
        const uint32_t bb = sb + (uint32_t)(s & 1) * G2_STG;
        char* bp = sm + ((s + 1) & 1) * G2_STG;
        const bool more = (s + 1 < NST);
        const int k0 = (s + 1) * 64;

        mma_blk(bb, 0);
        if (more) {
            #pragma unroll
            for (int i = 0; i < 4; i++)
                store_h(bp + aoff[i], *reinterpret_cast<const float4*>(g_act + abase[i] + k0));
        }
        mma_blk(bb, 1);
        if (more) {
            #pragma unroll
            for (int i = 4; i < 8; i++)
                store_h(bp + aoff[i], *reinterpret_cast<const float4*>(g_act + abase[i] + k0));
        }
        mma_blk(bb, 2);
        if (more) {
            #pragma unroll
            for (int i = 0; i < 4; i++)
                store_h(bp + boff[i], *reinterpret_cast<const float4*>(w2 + bbase[i] + k0));
        }
        mma_blk(bb, 3);
        if (more) {
            #pragma unroll
            for (int i = 4; i < 8; i++)
                store_h(bp + boff[i], *reinterpret_cast<const float4*>(w2 + bbase[i] + k0));
            __syncthreads();
        }
    }

    // epilogue: scatter-add
    const int g = lane >> 2, tq = lane & 3;
    #pragma unroll
    for (int fm = 0; fm < 4; fm++) {
        #pragma unroll
        for (int fn = 0; fn < 4; fn++) {
            int rl = wm * 64 + fm * 16 + g;
            int c  = n0 + wn * 32 + fn * 8 + 2 * tq;
            if (m0 + rl < Ne) {
                float* o = out + (size_t)stok[rl] * HDIM + c;
                atomicAdd(o + 0, acc[fm][fn][0]);
                atomicAdd(o + 1, acc[fm][fn][1]);
            }
            if (m0 + rl + 8 < Ne) {
                float* o = out + (size_t)stok[rl + 8] * HDIM + c;
                atomicAdd(o + 0, acc[fm][fn][2]);
                atomicAdd(o + 1, acc[fm][fn][3]);
            }
        }
    }
}

// ---------------- launch ---------------------------------------------------
extern "C" void kernel_launch(void* const* d_in, const int* in_sizes, int n_in,
                              void* d_out, int out_size) {
    const float* x    = (const float*)d_in[0];
    const float* attn = (const float*)d_in[1];
    const float* gw   = (const float*)d_in[2];
    const float* w1   = (const float*)d_in[3];
    const float* w2   = (const float*)d_in[4];
    const float* w3   = (const float*)d_in[5];

    float* out = (float*)d_out;
    float* logits = (out_size >= (int)(T * HDIM + T * NEXP)) ? out + (size_t)T * HDIM
                                                             : nullptr;

    cudaFuncSetAttribute(gemm1_mma, cudaFuncAttributeMaxDynamicSharedMemorySize, G1_SMEM);
    cudaFuncSetAttribute(gemm2_mma, cudaFuncAttributeMaxDynamicSharedMemorySize, G2_SMEM);

    cudaMemsetAsync(d_out, 0, (size_t)T * HDIM * sizeof(float));
    router_kernel<<<T, 256>>>(x, gw, logits);
    attn_kernel<<<SEQ, 256>>>(attn);
    route_finalize_kernel<<<1, 1024>>>();
    gemm1_mma<<<dim3(16, FDIM / 64, NEXP), 256, G1_SMEM>>>(x, w1, w3);
    gemm2_mma<<<dim3(16, HDIM / 128, NEXP), 256, G2_SMEM>>>(w2, out);
}

// round 7
// speedup vs baseline: 4.9242x; 1.2844x over previous
#include <cuda_runtime.h>
#include <cuda_fp16.h>
#include <math.h>
#include <stdint.h>

#define T    2048
#define HDIM 1024
#define FDIM 3584
#define NEXP 8
#define NH   16
#define SEQ  2048
#define NSEL 204   // int(0.1 * 2048)

#define NWELEM (NEXP * FDIM * HDIM)   // 29360128 per weight tensor

// ---------------- device scratch (no allocations allowed) ----------------
__device__ float g_scores[T];
__device__ float g_l1[T];
__device__ int   g_sel[T * 2];
__device__ float g_rw[T * 2];
__device__ int   g_top1prune[T];
__device__ int   g_low[T];
__device__ int   g_high[T];
__device__ int   g_cnt[NEXP];
__device__ int   g_ptok[NEXP * T];
__device__ float g_pw[NEXP * T];
__device__ __half g_xh[T * HDIM];
__device__ __half g_w1h[NWELEM];
__device__ __half g_w3h[NWELEM];
__device__ __half g_w2h[NWELEM];
__device__ __half g_acth[(size_t)NEXP * T * FDIM];  // fp16 activations

// ============================ helpers =====================================
__device__ __forceinline__ uint32_t smem_u32(const void* p) {
    uint32_t a;
    asm("{ .reg .u64 t; cvta.to.shared.u64 t, %1; cvt.u32.u64 %0, t; }" : "=r"(a) : "l"(p));
    return a;
}
__device__ __forceinline__ void ldm_x4(uint32_t r[4], uint32_t addr) {
    asm volatile("ldmatrix.sync.aligned.m8n8.x4.shared.b16 {%0,%1,%2,%3}, [%4];"
                 : "=r"(r[0]), "=r"(r[1]), "=r"(r[2]), "=r"(r[3]) : "r"(addr));
}
__device__ __forceinline__ void mma4(float d[4], const uint32_t a[4], const uint32_t b[2]) {
    asm volatile("mma.sync.aligned.m16n8k16.row.col.f32.f16.f16.f32 "
                 "{%0,%1,%2,%3}, {%4,%5,%6,%7}, {%8,%9}, {%0,%1,%2,%3};"
                 : "+f"(d[0]), "+f"(d[1]), "+f"(d[2]), "+f"(d[3])
                 : "r"(a[0]), "r"(a[1]), "r"(a[2]), "r"(a[3]), "r"(b[0]), "r"(b[1]));
}
__device__ __forceinline__ void cpa16(uint32_t s, const void* g) {
    asm volatile("cp.async.ca.shared.global [%0], [%1], 16;" :: "r"(s), "l"(g) : "memory");
}
#define CP_COMMIT() asm volatile("cp.async.commit_group;" ::: "memory")
#define CP_WAIT0()  asm volatile("cp.async.wait_group 0;" ::: "memory")

__device__ __forceinline__ uint32_t pkh(float a, float b) {
    return (uint32_t)__half_as_ushort(__float2half(a))
         | ((uint32_t)__half_as_ushort(__float2half(b)) << 16);
}

// row stride: 64 fp16 (128B) + 16B pad = 144B (conflict-free ldmatrix)
#define RS2 144
// gemm1 per-stage: A 128x144 @0, B1 64x144 @18432, B3 64x144 @27648
#define G1_STG   36864
#define G1_SMEM  (2 * G1_STG + 1024)
// gemm2 per-stage: A 128x144 @0, B 128x144 @18432
#define G2_STG   36864
#define G2_SMEM  (2 * G2_STG + 512)

// ---------------- convert: fp32 -> fp16 (vectorized) ----------------------
__global__ void cvt_kernel(const float4* __restrict__ src, uint2* __restrict__ dst, int n4) {
    int i = blockIdx.x * blockDim.x + threadIdx.x;
    if (i < n4) {
        float4 v = src[i];
        uint2 u;
        u.x = pkh(v.x, v.y);
        u.y = pkh(v.z, v.w);
        dst[i] = u;
    }
}

// ---------------- kernel 1: router ---------------------------------------
__global__ void router_kernel(const float* __restrict__ x,
                              const float* __restrict__ gw,
                              float* logits_out) {
    int t = blockIdx.x;
    int lane = threadIdx.x & 31;
    int w = threadIdx.x >> 5;
    __shared__ float s_logit[NEXP];
    __shared__ float s_l1;

    const float* xr = x + (size_t)t * HDIM;
    const float* ge = gw + (size_t)w * HDIM;
    float acc = 0.f, l1 = 0.f;
    for (int i = lane; i < HDIM; i += 32) {
        float xv = xr[i];
        acc += xv * ge[i];
        l1 += fabsf(xv);
    }
    #pragma unroll
    for (int o = 16; o; o >>= 1) {
        acc += __shfl_xor_sync(0xffffffffu, acc, o);
        l1  += __shfl_xor_sync(0xffffffffu, l1, o);
    }
    if (lane == 0) {
        s_logit[w] = acc;
        if (w == 0) s_l1 = l1;
    }
    __syncthreads();
    if (threadIdx.x == 0) {
        float p[NEXP];
        float mx = s_logit[0];
        for (int e = 1; e < NEXP; e++) if (s_logit[e] > mx) mx = s_logit[e];
        float sum = 0.f;
        for (int e = 0; e < NEXP; e++) { p[e] = expf(s_logit[e] - mx); sum += p[e]; }
        float inv = 1.f / sum;
        for (int e = 0; e < NEXP; e++) p[e] *= inv;
        int i0 = 0;
        for (int e = 1; e < NEXP; e++) if (p[e] > p[i0]) i0 = e;
        int i1 = (i0 == 0) ? 1 : 0;
        for (int e = 0; e < NEXP; e++) if (e != i0 && p[e] > p[i1]) i1 = e;
        g_sel[2 * t] = i0;  g_sel[2 * t + 1] = i1;
        g_rw[2 * t] = p[i0]; g_rw[2 * t + 1] = p[i1];
        g_top1prune[t] = (p[i1] < 0.5f * p[i0]) ? 1 : 0;
        g_l1[t] = s_l1;
        if (logits_out) {
            for (int e = 0; e < NEXP; e++) logits_out[(size_t)t * NEXP + e] = s_logit[e];
        }
    }
}

// ---------------- kernel 2: attention-score reduction --------------------
__global__ void attn_kernel(const float* __restrict__ attn) {
    int i = blockIdx.x;
    float s = 0.f;
    for (int h = 0; h < NH; h++) {
        const float4* row = reinterpret_cast<const float4*>(attn + ((size_t)h * SEQ + i) * SEQ);
        for (int j = threadIdx.x; j < SEQ / 4; j += 256) {
            float4 v = row[j];
            s += v.x + v.y + v.z + v.w;
        }
    }
    __shared__ float red[256];
    red[threadIdx.x] = s;
    __syncthreads();
    for (int st = 128; st > 0; st >>= 1) {
        if (threadIdx.x < st) red[threadIdx.x] += red[threadIdx.x + st];
        __syncthreads();
    }
    if (threadIdx.x == 0)
        g_scores[i] = red[0] / (16.f * (float)(SEQ - i)) * g_l1[i];
}

// ---------------- kernel 3: single bitonic sort + routing finalize -------
__global__ void route_finalize_kernel() {
    __shared__ float sval[T];
    __shared__ int   sidx[T];
    int tid = threadIdx.x;  // 1024 threads

    for (int t = tid; t < T; t += 1024) {
        g_low[t] = 0; g_high[t] = 0;
        sval[t] = g_scores[t]; sidx[t] = t;
    }
    if (tid < NEXP) g_cnt[tid] = 0;
    __syncthreads();

    for (int k = 2; k <= T; k <<= 1) {
        for (int j = k >> 1; j > 0; j >>= 1) {
            #pragma unroll
            for (int s = 0; s < 2; s++) {
                int i = tid + s * 1024;
                int ixj = i ^ j;
                if (ixj > i) {
                    float va = sval[i], vb = sval[ixj];
                    int ia = sidx[i], ib = sidx[ixj];
                    bool aBeforeB = (va < vb) || (va == vb && ia < ib);
                    bool up = ((i & k) == 0);
                    bool doswap = up ? !aBeforeB : aBeforeB;
                    if (doswap) {
                        sval[i] = vb; sval[ixj] = va;
                        sidx[i] = ib; sidx[ixj] = ia;
                    }
                }
            }
            __syncthreads();
        }
    }
    for (int r = tid; r < NSEL; r += 1024) {
        g_low[sidx[r]] = 1;
        g_high[sidx[T - 1 - r]] = 1;
    }
    __syncthreads();

    for (int t = tid; t < T; t += 1024) {
        float r0 = g_rw[2 * t], r1 = g_rw[2 * t + 1];
        float n0 = 1.f;
        float n1 = g_top1prune[t] ? 0.f : 1.f;
        if (g_low[t])  { n0 = 0.f; n1 = 0.f; }
        if (g_high[t]) { n0 = 1.f; n1 = 1.f; }
        r0 *= n0; r1 *= n1;
        float d = r0 + r1;
        if (d > 0.f) { r0 /= d; r1 /= d; }
        if (r0 > 0.f) {
            int e = g_sel[2 * t];
            int p = atomicAdd(&g_cnt[e], 1);
            g_ptok[e * T + p] = t;  g_pw[e * T + p] = r0;
        }
        if (r1 > 0.f) {
            int e = g_sel[2 * t + 1];
            int p = atomicAdd(&g_cnt[e], 1);
            g_ptok[e * T + p] = t;  g_pw[e * T + p] = r1;
        }
    }
}

// ---------------- gemm1: fp16 cp.async, 128x64 tile, warps 4x2 -----------
__global__ void __launch_bounds__(256, 2) gemm1_mma() {
    extern __shared__ char sm[];
    const int e = blockIdx.z;
    const int Ne = g_cnt[e];
    const int m0 = blockIdx.x * 128;
    if (m0 >= Ne) return;
    const int f0 = blockIdx.y * 64;
    const int tid = threadIdx.x;
    const int lane = tid & 31, wid = tid >> 5;
    const int wm = wid & 3, wn = wid >> 2;   // 4m x 2n warp grid

    const uint32_t sb = smem_u32(sm);
    int*   stok = reinterpret_cast<int*>(sm + 2 * G1_STG);
    float* spw  = reinterpret_cast<float*>(sm + 2 * G1_STG + 512);
    if (tid < 128) {
        int m = m0 + tid; int tk = 0; float pw = 0.f;
        if (m < Ne) { tk = g_ptok[e * T + m]; pw = g_pw[e * T + m]; }
        stok[tid] = tk; spw[tid] = pw;
    }
    __syncthreads();

    // producer mapping: per stage A 4 chunks/thread, B 4 chunks/thread (16B)
    int abase[4]; uint32_t aoff[4];
    int bbase[4]; uint32_t boff[4];
    const __half* wsrc[4];
    #pragma unroll
    for (int i = 0; i < 4; i++) {
        int idx = tid + i * 256;               // [0,1024): A chunks
        int ar = idx >> 3, c8 = (idx & 7) << 3;
        abase[i] = stok[ar] * HDIM + c8;
        aoff[i]  = (uint32_t)(ar * RS2 + c8 * 2);
        int bm = idx >> 9, br = (idx >> 3) & 63;  // B chunks
        wsrc[i]  = bm ? g_w3h : g_w1h;
        bbase[i] = (e * FDIM + f0 + br) * HDIM + c8;
        boff[i]  = (uint32_t)(18432 + bm * 9216 + br * RS2 + c8 * 2);
    }

    auto issue_stage = [&](int s) {
        uint32_t bp = sb + (uint32_t)(s & 1) * G1_STG;
        int k0 = s * 64;
        #pragma unroll
        for (int i = 0; i < 4; i++) cpa16(bp + aoff[i], g_xh + abase[i] + k0);
        #pragma unroll
        for (int i = 0; i < 4; i++) cpa16(bp + boff[i], wsrc[i] + bbase[i] + k0);
        CP_COMMIT();
    };

    issue_stage(0);
    CP_WAIT0();
    __syncthreads();

    const int lrow = lane & 15;
    const int lhik = ((lane >> 4) & 1) * 16;
    const int bn = (lane & 7) + ((lane >> 4) & 1) * 8;
    const int bhk = ((lane >> 3) & 1) * 16;

    float hc[2][4][4] = {{{0.f}}}, gc[2][4][4] = {{{0.f}}};

    auto mma_blk = [&](uint32_t bb, int kk) {
        const uint32_t koff = (uint32_t)kk * 32;
        uint32_t Ah[2][4];
        #pragma unroll
        for (int fm = 0; fm < 2; fm++)
            ldm_x4(Ah[fm], bb + (uint32_t)((wm * 32 + fm * 16 + lrow) * RS2) + koff + lhik);
        #pragma unroll
        for (int fnh = 0; fnh < 2; fnh++) {
            uint32_t bo = (uint32_t)((wn * 32 + fnh * 16 + bn) * RS2) + koff + bhk;
            uint32_t B1[4], B3[4];
            ldm_x4(B1, bb + 18432 + bo);
            ldm_x4(B3, bb + 27648 + bo);
            #pragma unroll
            for (int fm = 0; fm < 2; fm++)
                #pragma unroll
                for (int f2 = 0; f2 < 2; f2++) {
                    int fn = fnh * 2 + f2;
                    mma4(hc[fm][fn], Ah[fm], B1 + 2 * f2);
                    mma4(gc[fm][fn], Ah[fm], B3 + 2 * f2);
                }
        }
    };

    for (int s = 0; s < 16; s++) {
        const uint32_t bb = sb + (uint32_t)(s & 1) * G1_STG;
        const bool more = (s + 1 < 16);
        if (more) issue_stage(s + 1);
        mma_blk(bb, 0);
        mma_blk(bb, 1);
        mma_blk(bb, 2);
        mma_blk(bb, 3);
        if (more) { CP_WAIT0(); __syncthreads(); }
    }

    // epilogue: act = pw * g * silu(h), write fp16
    const int g = lane >> 2, tq = lane & 3;
    #pragma unroll
    for (int fm = 0; fm < 2; fm++) {
        #pragma unroll
        for (int fn = 0; fn < 4; fn++) {
            int rl = wm * 32 + fm * 16 + g;
            int c  = f0 + wn * 32 + fn * 8 + 2 * tq;
            float pw0 = spw[rl], pw1 = spw[rl + 8];
            float h0 = hc[fm][fn][0], h1 = hc[fm][fn][1];
            float h2 = hc[fm][fn][2], h3 = hc[fm][fn][3];
            float a0 = pw0 * gc[fm][fn][0] * (h0 / (1.f + expf(-h0)));
            float a1 = pw0 * gc[fm][fn][1] * (h1 / (1.f + expf(-h1)));
            float a2 = pw1 * gc[fm][fn][2] * (h2 / (1.f + expf(-h2)));
            float a3 = pw1 * gc[fm][fn][3] * (h3 / (1.f + expf(-h3)));
            *reinterpret_cast<uint32_t*>(g_acth + ((size_t)(e * T + m0 + rl)) * FDIM + c) = pkh(a0, a1);
            *reinterpret_cast<uint32_t*>(g_acth + ((size_t)(e * T + m0 + rl + 8)) * FDIM + c) = pkh(a2, a3);
        }
    }
}

// ---------------- gemm2: fp16 cp.async, 128x128 tile, warps 2x4 ----------
__global__ void __launch_bounds__(256, 2) gemm2_mma(float* __restrict__ out) {
    extern __shared__ char sm[];
    const int e = blockIdx.z;
    const int Ne = g_cnt[e];
    const int m0 = blockIdx.x * 128;
    if (m0 >= Ne) return;
    const int n0 = blockIdx.y * 128;
    const int tid = threadIdx.x;
    const int lane = tid & 31, wid = tid >> 5;
    const int wm = wid & 1, wn = wid >> 1;   // 2m x 4n warp grid

    const uint32_t sb = smem_u32(sm);
    int* stok = reinterpret_cast<int*>(sm + 2 * G2_STG);
    if (tid < 128) {
        int m = m0 + tid; int tk = 0;
        if (m < Ne) tk = g_ptok[e * T + m];
        stok[tid] = tk;
    }
    __syncthreads();

    int abase[4]; uint32_t aoff[4];
    int bbase[4]; uint32_t boff[4];
    #pragma unroll
    for (int i = 0; i < 4; i++) {
        int idx = tid + i * 256;
        int r = idx >> 3, c8 = (idx & 7) << 3;
        abase[i] = (e * T + m0 + r) * FDIM + c8;
        aoff[i]  = (uint32_t)(r * RS2 + c8 * 2);
        bbase[i] = (e * HDIM + n0 + r) * FDIM + c8;
        boff[i]  = (uint32_t)(18432 + r * RS2 + c8 * 2);
    }

    auto issue_stage = [&](int s) {
        uint32_t bp = sb + (uint32_t)(s & 1) * G2_STG;
        int k0 = s * 64;
        #pragma unroll
        for (int i = 0; i < 4; i++) cpa16(bp + aoff[i], g_acth + abase[i] + k0);
        #pragma unroll
        for (int i = 0; i < 4; i++) cpa16(bp + boff[i], g_w2h + bbase[i] + k0);
        CP_COMMIT();
    };

    issue_stage(0);
    CP_WAIT0();
    __syncthreads();

    const int lrow = lane & 15;
    const int lhik = ((lane >> 4) & 1) * 16;
    const int bn = (lane & 7) + ((lane >> 4) & 1) * 8;
    const int bhk = ((lane >> 3) & 1) * 16;

    float acc[4][4][4] = {{{0.f}}};

    auto mma_blk = [&](uint32_t bb, int kk) {
        const uint32_t koff = (uint32_t)kk * 32;
        uint32_t Bf[2][4];
        #pragma unroll
        for (int f2 = 0; f2 < 2; f2++)
            ldm_x4(Bf[f2], bb + 18432 + (uint32_t)((wn * 32 + f2 * 16 + bn) * RS2) + koff + bhk);
        #pragma unroll
        for (int fm = 0; fm < 4; fm++) {
            uint32_t Af[4];
            ldm_x4(Af, bb + (uint32_t)((wm * 64 + fm * 16 + lrow) * RS2) + koff + lhik);
            #pragma unroll
            for (int f2 = 0; f2 < 2; f2++)
                #pragma unroll
                for (int j = 0; j < 2; j++)
                    mma4(acc[fm][f2 * 2 + j], Af, Bf[f2] + 2 * j);
        }
    };

    const int NST = FDIM / 64;  // 56
    for (int s = 0; s < NST; s++) {
        const uint32_t bb = sb + (uint32_t)(s & 1) * G2_STG;
        const bool more = (s + 1 < NST);
        if (more) issue_stage(s + 1);
        mma_blk(bb, 0);
        mma_blk(bb, 1);
        mma_blk(bb, 2);
        mma_blk(bb, 3);
        if (more) { CP_WAIT0(); __syncthreads(); }
    }

    // epilogue: scatter-add fp32
    const int g = lane >> 2, tq = lane & 3;
    #pragma unroll
    for (int fm = 0; fm < 4; fm++) {
        #pragma unroll
        for (int fn = 0; fn < 4; fn++) {
            int rl = wm * 64 + fm * 16 + g;
            int c  = n0 + wn * 32 + fn * 8 + 2 * tq;
            if (m0 + rl < Ne) {
                float* o = out + (size_t)stok[rl] * HDIM + c;
                atomicAdd(o + 0, acc[fm][fn][0]);
                atomicAdd(o + 1, acc[fm][fn][1]);
            }
            if (m0 + rl + 8 < Ne) {
                float* o = out + (size_t)stok[rl + 8] * HDIM + c;
                atomicAdd(o + 0, acc[fm][fn][2]);
                atomicAdd(o + 1, acc[fm][fn][3]);
            }
        }
    }
}

// ---------------- launch ---------------------------------------------------
extern "C" void kernel_launch(void* const* d_in, const int* in_sizes, int n_in,
                              void* d_out, int out_size) {
    const float* x    = (const float*)d_in[0];
    const float* attn = (const float*)d_in[1];
    const float* gw   = (const float*)d_in[2];
    const float* w1   = (const float*)d_in[3];
    const float* w2   = (const float*)d_in[4];
    const float* w3   = (const float*)d_in[5];

    float* out = (float*)d_out;
    float* logits = (out_size >= (int)(T * HDIM + T * NEXP)) ? out + (size_t)T * HDIM
                                                             : nullptr;

    cudaFuncSetAttribute(gemm1_mma, cudaFuncAttributeMaxDynamicSharedMemorySize, G1_SMEM);
    cudaFuncSetAttribute(gemm2_mma, cudaFuncAttributeMaxDynamicSharedMemorySize, G2_SMEM);

    __half* d_xh;  cudaGetSymbolAddress((void**)&d_xh,  g_xh);
    __half* d_w1h; cudaGetSymbolAddress((void**)&d_w1h, g_w1h);
    __half* d_w3h; cudaGetSymbolAddress((void**)&d_w3h, g_w3h);
    __half* d_w2h; cudaGetSymbolAddress((void**)&d_w2h, g_w2h);

    const int NW4 = NWELEM / 4;        // 7340032
    const int NX4 = T * HDIM / 4;      // 524288

    cudaMemsetAsync(d_out, 0, (size_t)T * HDIM * sizeof(float));
    cvt_kernel<<<(NX4 + 255) / 256, 256>>>((const float4*)x,  (uint2*)d_xh,  NX4);
    cvt_kernel<<<(NW4 + 255) / 256, 256>>>((const float4*)w1, (uint2*)d_w1h, NW4);
    cvt_kernel<<<(NW4 + 255) / 256, 256>>>((const float4*)w3, (uint2*)d_w3h, NW4);
    cvt_kernel<<<(NW4 + 255) / 256, 256>>>((const float4*)w2, (uint2*)d_w2h, NW4);
    router_kernel<<<T, 256>>>(x, gw, logits);
    attn_kernel<<<SEQ, 256>>>(attn);
    route_finalize_kernel<<<1, 1024>>>();
    gemm1_mma<<<dim3(16, FDIM / 64, NEXP), 256, G1_SMEM>>>();
    gemm2_mma<<<dim3(16, HDIM / 128, NEXP), 256, G2_SMEM>>>(out);
}

// round 8
// speedup vs baseline: 4.9358x; 1.0023x over previous
#include <cuda_runtime.h>
#include <cuda_fp16.h>
#include <math.h>
#include <stdint.h>

#define T    2048
#define HDIM 1024
#define FDIM 3584
#define NEXP 8
#define NH   16
#define SEQ  2048
#define NSEL 204   // int(0.1 * 2048)

#define NWELEM (NEXP * FDIM * HDIM)   // 29360128 per weight tensor

// ---------------- device scratch (no allocations allowed) ----------------
__device__ float g_scores[T];
__device__ float g_l1[T];
__device__ int   g_sel[T * 2];
__device__ float g_rw[T * 2];
__device__ int   g_top1prune[T];
__device__ int   g_low[T];
__device__ int   g_high[T];
__device__ int   g_cnt[NEXP];
__device__ int   g_ptok[NEXP * T];
__device__ float g_pw[NEXP * T];
__device__ __half g_xh[T * HDIM];
__device__ __half g_w1h[NWELEM];
__device__ __half g_w3h[NWELEM];
__device__ __half g_w2h[NWELEM];
__device__ __half g_acth[(size_t)NEXP * T * FDIM];  // fp16 activations

// ============================ helpers =====================================
__device__ __forceinline__ uint32_t smem_u32(const void* p) {
    uint32_t a;
    asm("{ .reg .u64 t; cvta.to.shared.u64 t, %1; cvt.u32.u64 %0, t; }" : "=r"(a) : "l"(p));
    return a;
}
__device__ __forceinline__ void ldm_x4(uint32_t r[4], uint32_t addr) {
    asm volatile("ldmatrix.sync.aligned.m8n8.x4.shared.b16 {%0,%1,%2,%3}, [%4];"
                 : "=r"(r[0]), "=r"(r[1]), "=r"(r[2]), "=r"(r[3]) : "r"(addr));
}
__device__ __forceinline__ void mma4(float d[4], const uint32_t a[4], const uint32_t b[2]) {
    asm volatile("mma.sync.aligned.m16n8k16.row.col.f32.f16.f16.f32 "
                 "{%0,%1,%2,%3}, {%4,%5,%6,%7}, {%8,%9}, {%0,%1,%2,%3};"
                 : "+f"(d[0]), "+f"(d[1]), "+f"(d[2]), "+f"(d[3])
                 : "r"(a[0]), "r"(a[1]), "r"(a[2]), "r"(a[3]), "r"(b[0]), "r"(b[1]));
}
__device__ __forceinline__ void cpa16(uint32_t s, const void* g) {
    asm volatile("cp.async.ca.shared.global [%0], [%1], 16;" :: "r"(s), "l"(g) : "memory");
}
#define CP_COMMIT() asm volatile("cp.async.commit_group;" ::: "memory")
#define CP_WAIT0()  asm volatile("cp.async.wait_group 0;" ::: "memory")

__device__ __forceinline__ uint32_t pkh(float a, float b) {
    return (uint32_t)__half_as_ushort(__float2half(a))
         | ((uint32_t)__half_as_ushort(__float2half(b)) << 16);
}

// row stride: 64 fp16 (128B) + 16B pad = 144B (conflict-free ldmatrix)
#define RS2 144
// gemm1 per-stage: A 128x144 @0, B1 64x144 @18432, B3 64x144 @27648
#define G1_STG   36864
#define G1_SMEM  (2 * G1_STG + 1024)
// gemm2 per-stage: A 128x144 @0, B 128x144 @18432
#define G2_STG   36864
#define G2_SMEM  (2 * G2_STG + 512)

// ---------------- convert: fp32 -> fp16 (vectorized) ----------------------
__global__ void cvt_kernel(const float4* __restrict__ src, uint2* __restrict__ dst, int n4) {
    int i = blockIdx.x * blockDim.x + threadIdx.x;
    if (i < n4) {
        float4 v = src[i];
        uint2 u;
        u.x = pkh(v.x, v.y);
        u.y = pkh(v.z, v.w);
        dst[i] = u;
    }
}

// ---------------- kernel 1: router ---------------------------------------
__global__ void router_kernel(const float* __restrict__ x,
                              const float* __restrict__ gw,
                              float* logits_out) {
    int t = blockIdx.x;
    int lane = threadIdx.x & 31;
    int w = threadIdx.x >> 5;
    __shared__ float s_logit[NEXP];
    __shared__ float s_l1;

    const float* xr = x + (size_t)t * HDIM;
    const float* ge = gw + (size_t)w * HDIM;
    float acc = 0.f, l1 = 0.f;
    for (int i = lane; i < HDIM; i += 32) {
        float xv = xr[i];
        acc += xv * ge[i];
        l1 += fabsf(xv);
    }
    #pragma unroll
    for (int o = 16; o; o >>= 1) {
        acc += __shfl_xor_sync(0xffffffffu, acc, o);
        l1  += __shfl_xor_sync(0xffffffffu, l1, o);
    }
    if (lane == 0) {
        s_logit[w] = acc;
        if (w == 0) s_l1 = l1;
    }
    __syncthreads();
    if (threadIdx.x == 0) {
        float p[NEXP];
        float mx = s_logit[0];
        for (int e = 1; e < NEXP; e++) if (s_logit[e] > mx) mx = s_logit[e];
        float sum = 0.f;
        for (int e = 0; e < NEXP; e++) { p[e] = expf(s_logit[e] - mx); sum += p[e]; }
        float inv = 1.f / sum;
        for (int e = 0; e < NEXP; e++) p[e] *= inv;
        int i0 = 0;
        for (int e = 1; e < NEXP; e++) if (p[e] > p[i0]) i0 = e;
        int i1 = (i0 == 0) ? 1 : 0;
        for (int e = 0; e < NEXP; e++) if (e != i0 && p[e] > p[i1]) i1 = e;
        g_sel[2 * t] = i0;  g_sel[2 * t + 1] = i1;
        g_rw[2 * t] = p[i0]; g_rw[2 * t + 1] = p[i1];
        g_top1prune[t] = (p[i1] < 0.5f * p[i0]) ? 1 : 0;
        g_l1[t] = s_l1;
        if (logits_out) {
            for (int e = 0; e < NEXP; e++) logits_out[(size_t)t * NEXP + e] = s_logit[e];
        }
    }
}

// ---------------- kernel 2: attention-score reduction --------------------
__global__ void attn_kernel(const float* __restrict__ attn) {
    int i = blockIdx.x;
    float s = 0.f;
    for (int h = 0; h < NH; h++) {
        const float4* row = reinterpret_cast<const float4*>(attn + ((size_t)h * SEQ + i) * SEQ);
        for (int j = threadIdx.x; j < SEQ / 4; j += 256) {
            float4 v = row[j];
            s += v.x + v.y + v.z + v.w;
        }
    }
    __shared__ float red[256];
    red[threadIdx.x] = s;
    __syncthreads();
    for (int st = 128; st > 0; st >>= 1) {
        if (threadIdx.x < st) red[threadIdx.x] += red[threadIdx.x + st];
        __syncthreads();
    }
    if (threadIdx.x == 0)
        g_scores[i] = red[0] / (16.f * (float)(SEQ - i)) * g_l1[i];
}

// ---------------- kernel 3: single bitonic sort + routing finalize -------
__global__ void route_finalize_kernel() {
    __shared__ float sval[T];
    __shared__ int   sidx[T];
    int tid = threadIdx.x;  // 1024 threads

    for (int t = tid; t < T; t += 1024) {
        g_low[t] = 0; g_high[t] = 0;
        sval[t] = g_scores[t]; sidx[t] = t;
    }
    if (tid < NEXP) g_cnt[tid] = 0;
    __syncthreads();

    for (int k = 2; k <= T; k <<= 1) {
        for (int j = k >> 1; j > 0; j >>= 1) {
            #pragma unroll
            for (int s = 0; s < 2; s++) {
                int i = tid + s * 1024;
                int ixj = i ^ j;
                if (ixj > i) {
                    float va = sval[i], vb = sval[ixj];
                    int ia = sidx[i], ib = sidx[ixj];
                    bool aBeforeB = (va < vb) || (va == vb && ia < ib);
                    bool up = ((i & k) == 0);
                    bool doswap = up ? !aBeforeB : aBeforeB;
                    if (doswap) {
                        sval[i] = vb; sval[ixj] = va;
                        sidx[i] = ib; sidx[ixj] = ia;
                    }
                }
            }
            __syncthreads();
        }
    }
    for (int r = tid; r < NSEL; r += 1024) {
        g_low[sidx[r]] = 1;
        g_high[sidx[T - 1 - r]] = 1;
    }
    __syncthreads();

    for (int t = tid; t < T; t += 1024) {
        float r0 = g_rw[2 * t], r1 = g_rw[2 * t + 1];
        float n0 = 1.f;
        float n1 = g_top1prune[t] ? 0.f : 1.f;
        if (g_low[t])  { n0 = 0.f; n1 = 0.f; }
        if (g_high[t]) { n0 = 1.f; n1 = 1.f; }
        r0 *= n0; r1 *= n1;
        float d = r0 + r1;
        if (d > 0.f) { r0 /= d; r1 /= d; }
        if (r0 > 0.f) {
            int e = g_sel[2 * t];
            int p = atomicAdd(&g_cnt[e], 1);
            g_ptok[e * T + p] = t;  g_pw[e * T + p] = r0;
        }
        if (r1 > 0.f) {
            int e = g_sel[2 * t + 1];
            int p = atomicAdd(&g_cnt[e], 1);
            g_ptok[e * T + p] = t;  g_pw[e * T + p] = r1;
        }
    }
}

// ---------------- gemm1: fp16 cp.async, 128x64 tile, warps 4x2 -----------
__global__ void __launch_bounds__(256, 2) gemm1_mma() {
    extern __shared__ char sm[];
    const int e = blockIdx.z;
    const int Ne = g_cnt[e];
    const int m0 = blockIdx.x * 128;
    if (m0 >= Ne) return;
    const int f0 = blockIdx.y * 64;
    const int tid = threadIdx.x;
    const int lane = tid & 31, wid = tid >> 5;
    const int wm = wid & 3, wn = wid >> 2;   // 4m x 2n warp grid

    const uint32_t sb = smem_u32(sm);
    int*   stok = reinterpret_cast<int*>(sm + 2 * G1_STG);
    float* spw  = reinterpret_cast<float*>(sm + 2 * G1_STG + 512);
    if (tid < 128) {
        int m = m0 + tid; int tk = 0; float pw = 0.f;
        if (m < Ne) { tk = g_ptok[e * T + m]; pw = g_pw[e * T + m]; }
        stok[tid] = tk; spw[tid] = pw;
    }
    __syncthreads();

    // producer mapping: per stage A 4 chunks/thread, B 4 chunks/thread (16B)
    int abase[4]; uint32_t aoff[4];
    int bbase[4]; uint32_t boff[4];
    const __half* wsrc[4];
    #pragma unroll
    for (int i = 0; i < 4; i++) {
        int idx = tid + i * 256;               // [0,1024): A chunks
        int ar = idx >> 3, c8 = (idx & 7) << 3;
        abase[i] = stok[ar] * HDIM + c8;
        aoff[i]  = (uint32_t)(ar * RS2 + c8 * 2);
        int bm = idx >> 9, br = (idx >> 3) & 63;  // B chunks
        wsrc[i]  = bm ? g_w3h : g_w1h;
        bbase[i] = (e * FDIM + f0 + br) * HDIM + c8;
        boff[i]  = (uint32_t)(18432 + bm * 9216 + br * RS2 + c8 * 2);
    }

    auto issue_stage = [&](int s) {
        uint32_t bp = sb + (uint32_t)(s & 1) * G1_STG;
        int k0 = s * 64;
        #pragma unroll
        for (int i = 0; i < 4; i++) cpa16(bp + aoff[i], g_xh + abase[i] + k0);
        #pragma unroll
        for (int i = 0; i < 4; i++) cpa16(bp + boff[i], wsrc[i] + bbase[i] + k0);
        CP_COMMIT();
    };

    issue_stage(0);
    CP_WAIT0();
    __syncthreads();

    const int lrow = lane & 15;
    const int lhik = ((lane >> 4) & 1) * 16;
    const int bn = (lane & 7) + ((lane >> 4) & 1) * 8;
    const int bhk = ((lane >> 3) & 1) * 16;

    float hc[2][4][4] = {{{0.f}}}, gc[2][4][4] = {{{0.f}}};

    auto mma_blk = [&](uint32_t bb, int kk) {
        const uint32_t koff = (uint32_t)kk * 32;
        uint32_t Ah[2][4];
        #pragma unroll
        for (int fm = 0; fm < 2; fm++)
            ldm_x4(Ah[fm], bb + (uint32_t)((wm * 32 + fm * 16 + lrow) * RS2) + koff + lhik);
        #pragma unroll
        for (int fnh = 0; fnh < 2; fnh++) {
            uint32_t bo = (uint32_t)((wn * 32 + fnh * 16 + bn) * RS2) + koff + bhk;
            uint32_t B1[4], B3[4];
            ldm_x4(B1, bb + 18432 + bo);
            ldm_x4(B3, bb + 27648 + bo);
            #pragma unroll
            for (int fm = 0; fm < 2; fm++)
                #pragma unroll
                for (int f2 = 0; f2 < 2; f2++) {
                    int fn = fnh * 2 + f2;
                    mma4(hc[fm][fn], Ah[fm], B1 + 2 * f2);
                    mma4(gc[fm][fn], Ah[fm], B3 + 2 * f2);
                }
        }
    };

    for (int s = 0; s < 16; s++) {
        const uint32_t bb = sb + (uint32_t)(s & 1) * G1_STG;
        const bool more = (s + 1 < 16);
        if (more) issue_stage(s + 1);
        mma_blk(bb, 0);
        mma_blk(bb, 1);
        mma_blk(bb, 2);
        mma_blk(bb, 3);
        if (more) { CP_WAIT0(); __syncthreads(); }
    }

    // epilogue: act = pw * g * silu(h), write fp16
    const int g = lane >> 2, tq = lane & 3;
    #pragma unroll
    for (int fm = 0; fm < 2; fm++) {
        #pragma unroll
        for (int fn = 0; fn < 4; fn++) {
            int rl = wm * 32 + fm * 16 + g;
            int c  = f0 + wn * 32 + fn * 8 + 2 * tq;
            float pw0 = spw[rl], pw1 = spw[rl + 8];
            float h0 = hc[fm][fn][0], h1 = hc[fm][fn][1];
            float h2 = hc[fm][fn][2], h3 = hc[fm][fn][3];
            float a0 = pw0 * gc[fm][fn][0] * (h0 / (1.f + expf(-h0)));
            float a1 = pw0 * gc[fm][fn][1] * (h1 / (1.f + expf(-h1)));
            float a2 = pw1 * gc[fm][fn][2] * (h2 / (1.f + expf(-h2)));
            float a3 = pw1 * gc[fm][fn][3] * (h3 / (1.f + expf(-h3)));
            *reinterpret_cast<uint32_t*>(g_acth + ((size_t)(e * T + m0 + rl)) * FDIM + c) = pkh(a0, a1);
            *reinterpret_cast<uint32_t*>(g_acth + ((size_t)(e * T + m0 + rl + 8)) * FDIM + c) = pkh(a2, a3);
        }
    }
}

// ---------------- gemm2: fp16 cp.async, 128x128 tile, warps 2x4 ----------
__global__ void __launch_bounds__(256, 2) gemm2_mma(float* __restrict__ out) {
    extern __shared__ char sm[];
    const int e = blockIdx.z;
    const int Ne = g_cnt[e];
    const int m0 = blockIdx.x * 128;
    if (m0 >= Ne) return;
    const int n0 = blockIdx.y * 128;
    const int tid = threadIdx.x;
    const int lane = tid & 31, wid = tid >> 5;
    const int wm = wid & 1, wn = wid >> 1;   // 2m x 4n warp grid

    const uint32_t sb = smem_u32(sm);
    int* stok = reinterpret_cast<int*>(sm + 2 * G2_STG);
    if (tid < 128) {
        int m = m0 + tid; int tk = 0;
        if (m < Ne) tk = g_ptok[e * T + m];
        stok[tid] = tk;
    }
    __syncthreads();

    int abase[4]; uint32_t aoff[4];
    int bbase[4]; uint32_t boff[4];
    #pragma unroll
    for (int i = 0; i < 4; i++) {
        int idx = tid + i * 256;
        int r = idx >> 3, c8 = (idx & 7) << 3;
        abase[i] = (e * T + m0 + r) * FDIM + c8;
        aoff[i]  = (uint32_t)(r * RS2 + c8 * 2);
        bbase[i] = (e * HDIM + n0 + r) * FDIM + c8;
        boff[i]  = (uint32_t)(18432 + r * RS2 + c8 * 2);
    }

    auto issue_stage = [&](int s) {
        uint32_t bp = sb + (uint32_t)(s & 1) * G2_STG;
        int k0 = s * 64;
        #pragma unroll
        for (int i = 0; i < 4; i++) cpa16(bp + aoff[i], g_acth + abase[i] + k0);
        #pragma unroll
        for (int i = 0; i < 4; i++) cpa16(bp + boff[i], g_w2h + bbase[i] + k0);
        CP_COMMIT();
    };

    issue_stage(0);
    CP_WAIT0();
    __syncthreads();

    const int lrow = lane & 15;
    const int lhik = ((lane >> 4) & 1) * 16;
    const int bn = (lane & 7) + ((lane >> 4) & 1) * 8;
    const int bhk = ((lane >> 3) & 1) * 16;

    float acc[4][4][4] = {{{0.f}}};

    auto mma_blk = [&](uint32_t bb, int kk) {
        const uint32_t koff = (uint32_t)kk * 32;
        uint32_t Bf[2][4];
        #pragma unroll
        for (int f2 = 0; f2 < 2; f2++)
            ldm_x4(Bf[f2], bb + 18432 + (uint32_t)((wn * 32 + f2 * 16 + bn) * RS2) + koff + bhk);
        #pragma unroll
        for (int fm = 0; fm < 4; fm++) {
            uint32_t Af[4];
            ldm_x4(Af, bb + (uint32_t)((wm * 64 + fm * 16 + lrow) * RS2) + koff + lhik);
            #pragma unroll
            for (int f2 = 0; f2 < 2; f2++)
                #pragma unroll
                for (int j = 0; j < 2; j++)
                    mma4(acc[fm][f2 * 2 + j], Af, Bf[f2] + 2 * j);
        }
    };

    const int NST = FDIM / 64;  // 56
    for (int s = 0; s < NST; s++) {
        const uint32_t bb = sb + (uint32_t)(s & 1) * G2_STG;
        const bool more = (s + 1 < NST);
        if (more) issue_stage(s + 1);
        mma_blk(bb, 0);
        mma_blk(bb, 1);
        mma_blk(bb, 2);
        mma_blk(bb, 3);
        if (more) { CP_WAIT0(); __syncthreads(); }
    }

    // epilogue: scatter-add fp32
    const int g = lane >> 2, tq = lane & 3;
    #pragma unroll
    for (int fm = 0; fm < 4; fm++) {
        #pragma unroll
        for (int fn = 0; fn < 4; fn++) {
            int rl = wm * 64 + fm * 16 + g;
            int c  = n0 + wn * 32 + fn * 8 + 2 * tq;
            if (m0 + rl < Ne) {
                float* o = out + (size_t)stok[rl] * HDIM + c;
                atomicAdd(o + 0, acc[fm][fn][0]);
                atomicAdd(o + 1, acc[fm][fn][1]);
            }
            if (m0 + rl + 8 < Ne) {
                float* o = out + (size_t)stok[rl + 8] * HDIM + c;
                atomicAdd(o + 0, acc[fm][fn][2]);
                atomicAdd(o + 1, acc[fm][fn][3]);
            }
        }
    }
}

// ---------------- launch ---------------------------------------------------
extern "C" void kernel_launch(void* const* d_in, const int* in_sizes, int n_in,
                              void* d_out, int out_size) {
    const float* x    = (const float*)d_in[0];
    const float* attn = (const float*)d_in[1];
    const float* gw   = (const float*)d_in[2];
    const float* w1   = (const float*)d_in[3];
    const float* w2   = (const float*)d_in[4];
    const float* w3   = (const float*)d_in[5];

    float* out = (float*)d_out;
    float* logits = (out_size >= (int)(T * HDIM + T * NEXP)) ? out + (size_t)T * HDIM
                                                             : nullptr;

    cudaFuncSetAttribute(gemm1_mma, cudaFuncAttributeMaxDynamicSharedMemorySize, G1_SMEM);
    cudaFuncSetAttribute(gemm2_mma, cudaFuncAttributeMaxDynamicSharedMemorySize, G2_SMEM);

    __half* d_xh;  cudaGetSymbolAddress((void**)&d_xh,  g_xh);
    __half* d_w1h; cudaGetSymbolAddress((void**)&d_w1h, g_w1h);
    __half* d_w3h; cudaGetSymbolAddress((void**)&d_w3h, g_w3h);
    __half* d_w2h; cudaGetSymbolAddress((void**)&d_w2h, g_w2h);

    const int NW4 = NWELEM / 4;        // 7340032
    const int NX4 = T * HDIM / 4;      // 524288

    cudaMemsetAsync(d_out, 0, (size_t)T * HDIM * sizeof(float));
    cvt_kernel<<<(NX4 + 255) / 256, 256>>>((const float4*)x,  (uint2*)d_xh,  NX4);
    cvt_kernel<<<(NW4 + 255) / 256, 256>>>((const float4*)w1, (uint2*)d_w1h, NW4);
    cvt_kernel<<<(NW4 + 255) / 256, 256>>>((const float4*)w3, (uint2*)d_w3h, NW4);
    cvt_kernel<<<(NW4 + 255) / 256, 256>>>((const float4*)w2, (uint2*)d_w2h, NW4);
    router_kernel<<<T, 256>>>(x, gw, logits);
    attn_kernel<<<SEQ, 256>>>(attn);
    route_finalize_kernel<<<1, 1024>>>();
    gemm1_mma<<<dim3(16, FDIM / 64, NEXP), 256, G1_SMEM>>>();
    gemm2_mma<<<dim3(16, HDIM / 128, NEXP), 256, G2_SMEM>>>(out);
}

// round 9
// speedup vs baseline: 5.2920x; 1.0722x over previous
#include <cuda_runtime.h>
#include <cuda_fp16.h>
#include <math.h>
#include <stdint.h>

#define T    2048
#define HDIM 1024
#define FDIM 3584
#define NEXP 8
#define NH   16
#define SEQ  2048
#define NSEL 204   // int(0.1 * 2048)

#define NWELEM (NEXP * FDIM * HDIM)   // 29360128 per weight tensor

// ---------------- device scratch (no allocations allowed) ----------------
__device__ float g_scores[T];
__device__ float g_l1[T];
__device__ int   g_sel[T * 2];
__device__ float g_rw[T * 2];
__device__ int   g_top1prune[T];
__device__ int   g_low[T];
__device__ int   g_high[T];
__device__ int   g_cnt[NEXP];
__device__ int   g_ptok[NEXP * T];
__device__ float g_pw[NEXP * T];
__device__ __half g_xh[T * HDIM];
__device__ __half g_w1h[NWELEM];
__device__ __half g_w3h[NWELEM];
__device__ __half g_w2h[NWELEM];
__device__ __half g_acth[(size_t)NEXP * T * FDIM];  // fp16 activations

// ============================ helpers =====================================
__device__ __forceinline__ uint32_t smem_u32(const void* p) {
    uint32_t a;
    asm("{ .reg .u64 t; cvta.to.shared.u64 t, %1; cvt.u32.u64 %0, t; }" : "=r"(a) : "l"(p));
    return a;
}
__device__ __forceinline__ void ldm_x4(uint32_t r[4], uint32_t addr) {
    asm volatile("ldmatrix.sync.aligned.m8n8.x4.shared.b16 {%0,%1,%2,%3}, [%4];"
                 : "=r"(r[0]), "=r"(r[1]), "=r"(r[2]), "=r"(r[3]) : "r"(addr));
}
__device__ __forceinline__ void mma4(float d[4], const uint32_t a[4], const uint32_t b[2]) {
    asm volatile("mma.sync.aligned.m16n8k16.row.col.f32.f16.f16.f32 "
                 "{%0,%1,%2,%3}, {%4,%5,%6,%7}, {%8,%9}, {%0,%1,%2,%3};"
                 : "+f"(d[0]), "+f"(d[1]), "+f"(d[2]), "+f"(d[3])
                 : "r"(a[0]), "r"(a[1]), "r"(a[2]), "r"(a[3]), "r"(b[0]), "r"(b[1]));
}
__device__ __forceinline__ void cpa16(uint32_t s, const void* g) {
    asm volatile("cp.async.ca.shared.global [%0], [%1], 16;" :: "r"(s), "l"(g) : "memory");
}
#define CP_COMMIT() asm volatile("cp.async.commit_group;" ::: "memory")
#define CP_WAIT0()  asm volatile("cp.async.wait_group 0;" ::: "memory")

__device__ __forceinline__ uint32_t pkh(float a, float b) {
    return (uint32_t)__half_as_ushort(__float2half(a))
         | ((uint32_t)__half_as_ushort(__float2half(b)) << 16);
}

// row stride: 64 fp16 (128B) + 16B pad = 144B (conflict-free ldmatrix)
#define RS2 144
// gemm1 per-stage: A 128x144 @0, B1 64x144 @18432, B3 64x144 @27648
#define G1_STG   36864
#define G1_SMEM  (2 * G1_STG + 1024)
// gemm2 per-stage: A 128x144 @0, B 128x144 @18432
#define G2_STG   36864
#define G2_SMEM  (2 * G2_STG + 512)

// ---------------- convert: fp32 -> fp16, 4 float4/thread ------------------
__global__ void cvt_kernel(const float4* __restrict__ src, uint2* __restrict__ dst, int n4) {
    int base = (blockIdx.x * blockDim.x) * 4 + threadIdx.x;
    #pragma unroll
    for (int it = 0; it < 4; it++) {
        int i = base + it * 256;
        if (i < n4) {
            float4 v = src[i];
            uint2 u;
            u.x = pkh(v.x, v.y);
            u.y = pkh(v.z, v.w);
            dst[i] = u;
        }
    }
}

// ---------------- kernel 1: router ---------------------------------------
__global__ void router_kernel(const float* __restrict__ x,
                              const float* __restrict__ gw,
                              float* logits_out) {
    int t = blockIdx.x;
    int lane = threadIdx.x & 31;
    int w = threadIdx.x >> 5;
    __shared__ float s_logit[NEXP];
    __shared__ float s_l1;

    const float* xr = x + (size_t)t * HDIM;
    const float* ge = gw + (size_t)w * HDIM;
    float acc = 0.f, l1 = 0.f;
    for (int i = lane; i < HDIM; i += 32) {
        float xv = xr[i];
        acc += xv * ge[i];
        l1 += fabsf(xv);
    }
    #pragma unroll
    for (int o = 16; o; o >>= 1) {
        acc += __shfl_xor_sync(0xffffffffu, acc, o);
        l1  += __shfl_xor_sync(0xffffffffu, l1, o);
    }
    if (lane == 0) {
        s_logit[w] = acc;
        if (w == 0) s_l1 = l1;
    }
    __syncthreads();
    if (threadIdx.x == 0) {
        float p[NEXP];
        float mx = s_logit[0];
        for (int e = 1; e < NEXP; e++) if (s_logit[e] > mx) mx = s_logit[e];
        float sum = 0.f;
        for (int e = 0; e < NEXP; e++) { p[e] = expf(s_logit[e] - mx); sum += p[e]; }
        float inv = 1.f / sum;
        for (int e = 0; e < NEXP; e++) p[e] *= inv;
        int i0 = 0;
        for (int e = 1; e < NEXP; e++) if (p[e] > p[i0]) i0 = e;
        int i1 = (i0 == 0) ? 1 : 0;
        for (int e = 0; e < NEXP; e++) if (e != i0 && p[e] > p[i1]) i1 = e;
        g_sel[2 * t] = i0;  g_sel[2 * t + 1] = i1;
        g_rw[2 * t] = p[i0]; g_rw[2 * t + 1] = p[i1];
        g_top1prune[t] = (p[i1] < 0.5f * p[i0]) ? 1 : 0;
        g_l1[t] = s_l1;
        if (logits_out) {
            for (int e = 0; e < NEXP; e++) logits_out[(size_t)t * NEXP + e] = s_logit[e];
        }
    }
}

// ---------------- kernel 2: attention-score reduction --------------------
__global__ void attn_kernel(const float* __restrict__ attn) {
    int i = blockIdx.x;
    float s = 0.f;
    for (int h = 0; h < NH; h++) {
        const float4* row = reinterpret_cast<const float4*>(attn + ((size_t)h * SEQ + i) * SEQ);
        for (int j = threadIdx.x; j < SEQ / 4; j += 256) {
            float4 v = row[j];
            s += v.x + v.y + v.z + v.w;
        }
    }
    __shared__ float red[256];
    red[threadIdx.x] = s;
    __syncthreads();
    for (int st = 128; st > 0; st >>= 1) {
        if (threadIdx.x < st) red[threadIdx.x] += red[threadIdx.x + st];
        __syncthreads();
    }
    if (threadIdx.x == 0)
        g_scores[i] = red[0] / (16.f * (float)(SEQ - i)) * g_l1[i];
}

// ---------------- kernel 3: single bitonic sort + routing finalize -------
__global__ void route_finalize_kernel() {
    __shared__ float sval[T];
    __shared__ int   sidx[T];
    int tid = threadIdx.x;  // 1024 threads

    for (int t = tid; t < T; t += 1024) {
        g_low[t] = 0; g_high[t] = 0;
        sval[t] = g_scores[t]; sidx[t] = t;
    }
    if (tid < NEXP) g_cnt[tid] = 0;
    __syncthreads();

    for (int k = 2; k <= T; k <<= 1) {
        for (int j = k >> 1; j > 0; j >>= 1) {
            #pragma unroll
            for (int s = 0; s < 2; s++) {
                int i = tid + s * 1024;
                int ixj = i ^ j;
                if (ixj > i) {
                    float va = sval[i], vb = sval[ixj];
                    int ia = sidx[i], ib = sidx[ixj];
                    bool aBeforeB = (va < vb) || (va == vb && ia < ib);
                    bool up = ((i & k) == 0);
                    bool doswap = up ? !aBeforeB : aBeforeB;
                    if (doswap) {
                        sval[i] = vb; sval[ixj] = va;
                        sidx[i] = ib; sidx[ixj] = ia;
                    }
                }
            }
            __syncthreads();
        }
    }
    for (int r = tid; r < NSEL; r += 1024) {
        g_low[sidx[r]] = 1;
        g_high[sidx[T - 1 - r]] = 1;
    }
    __syncthreads();

    for (int t = tid; t < T; t += 1024) {
        float r0 = g_rw[2 * t], r1 = g_rw[2 * t + 1];
        float n0 = 1.f;
        float n1 = g_top1prune[t] ? 0.f : 1.f;
        if (g_low[t])  { n0 = 0.f; n1 = 0.f; }
        if (g_high[t]) { n0 = 1.f; n1 = 1.f; }
        r0 *= n0; r1 *= n1;
        float d = r0 + r1;
        if (d > 0.f) { r0 /= d; r1 /= d; }
        if (r0 > 0.f) {
            int e = g_sel[2 * t];
            int p = atomicAdd(&g_cnt[e], 1);
            g_ptok[e * T + p] = t;  g_pw[e * T + p] = r0;
        }
        if (r1 > 0.f) {
            int e = g_sel[2 * t + 1];
            int p = atomicAdd(&g_cnt[e], 1);
            g_ptok[e * T + p] = t;  g_pw[e * T + p] = r1;
        }
    }
}

// ---------------- gemm1: fp16 cp.async, 128x64 tile, warps 4x2 -----------
__global__ void __launch_bounds__(256, 2) gemm1_mma() {
    extern __shared__ char sm[];
    const int e = blockIdx.z;
    const int Ne = g_cnt[e];
    const int m0 = blockIdx.x * 128;
    if (m0 >= Ne) return;
    const int f0 = blockIdx.y * 64;
    const int tid = threadIdx.x;
    const int lane = tid & 31, wid = tid >> 5;
    const int wm = wid & 3, wn = wid >> 2;   // 4m x 2n warp grid

    const uint32_t sb = smem_u32(sm);
    int*   stok = reinterpret_cast<int*>(sm + 2 * G1_STG);
    float* spw  = reinterpret_cast<float*>(sm + 2 * G1_STG + 512);
    if (tid < 128) {
        int m = m0 + tid; int tk = 0; float pw = 0.f;
        if (m < Ne) { tk = g_ptok[e * T + m]; pw = g_pw[e * T + m]; }
        stok[tid] = tk; spw[tid] = pw;
    }
    __syncthreads();

    // producer mapping: per stage A 4 chunks/thread, B 4 chunks/thread (16B)
    int abase[4]; uint32_t aoff[4];
    int bbase[4]; uint32_t boff[4];
    const __half* wsrc[4];
    #pragma unroll
    for (int i = 0; i < 4; i++) {
        int idx = tid + i * 256;               // [0,1024): A chunks
        int ar = idx >> 3, c8 = (idx & 7) << 3;
        abase[i] = stok[ar] * HDIM + c8;
        aoff[i]  = (uint32_t)(ar * RS2 + c8 * 2);
        int bm = idx >> 9, br = (idx >> 3) & 63;  // B chunks
        wsrc[i]  = bm ? g_w3h : g_w1h;
        bbase[i] = (e * FDIM + f0 + br) * HDIM + c8;
        boff[i]  = (uint32_t)(18432 + bm * 9216 + br * RS2 + c8 * 2);
    }

    auto issue_stage = [&](int s) {
        uint32_t bp = sb + (uint32_t)(s & 1) * G1_STG;
        int k0 = s * 64;
        #pragma unroll
        for (int i = 0; i < 4; i++) cpa16(bp + aoff[i], g_xh + abase[i] + k0);
        #pragma unroll
        for (int i = 0; i < 4; i++) cpa16(bp + boff[i], wsrc[i] + bbase[i] + k0);
        CP_COMMIT();
    };

    issue_stage(0);
    CP_WAIT0();
    __syncthreads();

    const int lrow = lane & 15;
    const int lhik = ((lane >> 4) & 1) * 16;
    const int bn = (lane & 7) + ((lane >> 4) & 1) * 8;
    const int bhk = ((lane >> 3) & 1) * 16;

    float hc[2][4][4] = {{{0.f}}}, gc[2][4][4] = {{{0.f}}};

    auto mma_blk = [&](uint32_t bb, int kk) {
        const uint32_t koff = (uint32_t)kk * 32;
        uint32_t Ah[2][4];
        #pragma unroll
        for (int fm = 0; fm < 2; fm++)
            ldm_x4(Ah[fm], bb + (uint32_t)((wm * 32 + fm * 16 + lrow) * RS2) + koff + lhik);
        #pragma unroll
        for (int fnh = 0; fnh < 2; fnh++) {
            uint32_t bo = (uint32_t)((wn * 32 + fnh * 16 + bn) * RS2) + koff + bhk;
            uint32_t B1[4], B3[4];
            ldm_x4(B1, bb + 18432 + bo);
            ldm_x4(B3, bb + 27648 + bo);
            #pragma unroll
            for (int fm = 0; fm < 2; fm++)
                #pragma unroll
                for (int f2 = 0; f2 < 2; f2++) {
                    int fn = fnh * 2 + f2;
                    mma4(hc[fm][fn], Ah[fm], B1 + 2 * f2);
                    mma4(gc[fm][fn], Ah[fm], B3 + 2 * f2);
                }
        }
    };

    for (int s = 0; s < 16; s++) {
        const uint32_t bb = sb + (uint32_t)(s & 1) * G1_STG;
        const bool more = (s + 1 < 16);
        if (more) issue_stage(s + 1);
        mma_blk(bb, 0);
        mma_blk(bb, 1);
        mma_blk(bb, 2);
        mma_blk(bb, 3);
        if (more) { CP_WAIT0(); __syncthreads(); }
    }

    // epilogue: act = pw * g * silu(h), write fp16
    const int g = lane >> 2, tq = lane & 3;
    #pragma unroll
    for (int fm = 0; fm < 2; fm++) {
        #pragma unroll
        for (int fn = 0; fn < 4; fn++) {
            int rl = wm * 32 + fm * 16 + g;
            int c  = f0 + wn * 32 + fn * 8 + 2 * tq;
            float pw0 = spw[rl], pw1 = spw[rl + 8];
            float h0 = hc[fm][fn][0], h1 = hc[fm][fn][1];
            float h2 = hc[fm][fn][2], h3 = hc[fm][fn][3];
            float a0 = pw0 * gc[fm][fn][0] * (h0 / (1.f + expf(-h0)));
            float a1 = pw0 * gc[fm][fn][1] * (h1 / (1.f + expf(-h1)));
            float a2 = pw1 * gc[fm][fn][2] * (h2 / (1.f + expf(-h2)));
            float a3 = pw1 * gc[fm][fn][3] * (h3 / (1.f + expf(-h3)));
            *reinterpret_cast<uint32_t*>(g_acth + ((size_t)(e * T + m0 + rl)) * FDIM + c) = pkh(a0, a1);
            *reinterpret_cast<uint32_t*>(g_acth + ((size_t)(e * T + m0 + rl + 8)) * FDIM + c) = pkh(a2, a3);
        }
    }
}

// ---------------- gemm2: fp16 cp.async, 128x128 tile, warps 2x4 ----------
__global__ void __launch_bounds__(256, 2) gemm2_mma(float* __restrict__ out) {
    extern __shared__ char sm[];
    const int e = blockIdx.z;
    const int Ne = g_cnt[e];
    const int m0 = blockIdx.x * 128;
    if (m0 >= Ne) return;
    const int n0 = blockIdx.y * 128;
    const int tid = threadIdx.x;
    const int lane = tid & 31, wid = tid >> 5;
    const int wm = wid & 1, wn = wid >> 1;   // 2m x 4n warp grid

    const uint32_t sb = smem_u32(sm);
    int* stok = reinterpret_cast<int*>(sm + 2 * G2_STG);
    if (tid < 128) {
        int m = m0 + tid; int tk = 0;
        if (m < Ne) tk = g_ptok[e * T + m];
        stok[tid] = tk;
    }
    __syncthreads();

    int abase[4]; uint32_t aoff[4];
    int bbase[4]; uint32_t boff[4];
    #pragma unroll
    for (int i = 0; i < 4; i++) {
        int idx = tid + i * 256;
        int r = idx >> 3, c8 = (idx & 7) << 3;
        abase[i] = (e * T + m0 + r) * FDIM + c8;
        aoff[i]  = (uint32_t)(r * RS2 + c8 * 2);
        bbase[i] = (e * HDIM + n0 + r) * FDIM + c8;
        boff[i]  = (uint32_t)(18432 + r * RS2 + c8 * 2);
    }

    auto issue_stage = [&](int s) {
        uint32_t bp = sb + (uint32_t)(s & 1) * G2_STG;
        int k0 = s * 64;
        #pragma unroll
        for (int i = 0; i < 4; i++) cpa16(bp + aoff[i], g_acth + abase[i] + k0);
        #pragma unroll
        for (int i = 0; i < 4; i++) cpa16(bp + boff[i], g_w2h + bbase[i] + k0);
        CP_COMMIT();
    };

    issue_stage(0);
    CP_WAIT0();
    __syncthreads();

    const int lrow = lane & 15;
    const int lhik = ((lane >> 4) & 1) * 16;
    const int bn = (lane & 7) + ((lane >> 4) & 1) * 8;
    const int bhk = ((lane >> 3) & 1) * 16;

    float acc[4][4][4] = {{{0.f}}};

    auto mma_blk = [&](uint32_t bb, int kk) {
        const uint32_t koff = (uint32_t)kk * 32;
        uint32_t Bf[2][4];
        #pragma unroll
        for (int f2 = 0; f2 < 2; f2++)
            ldm_x4(Bf[f2], bb + 18432 + (uint32_t)((wn * 32 + f2 * 16 + bn) * RS2) + koff + bhk);
        #pragma unroll
        for (int fm = 0; fm < 4; fm++) {
            uint32_t Af[4];
            ldm_x4(Af, bb + (uint32_t)((wm * 64 + fm * 16 + lrow) * RS2) + koff + lhik);
            #pragma unroll
            for (int f2 = 0; f2 < 2; f2++)
                #pragma unroll
                for (int j = 0; j < 2; j++)
                    mma4(acc[fm][f2 * 2 + j], Af, Bf[f2] + 2 * j);
        }
    };

    const int NST = FDIM / 64;  // 56
    for (int s = 0; s < NST; s++) {
        const uint32_t bb = sb + (uint32_t)(s & 1) * G2_STG;
        const bool more = (s + 1 < NST);
        if (more) issue_stage(s + 1);
        mma_blk(bb, 0);
        mma_blk(bb, 1);
        mma_blk(bb, 2);
        mma_blk(bb, 3);
        if (more) { CP_WAIT0(); __syncthreads(); }
    }

    // epilogue: scatter-add fp32
    const int g = lane >> 2, tq = lane & 3;
    #pragma unroll
    for (int fm = 0; fm < 4; fm++) {
        #pragma unroll
        for (int fn = 0; fn < 4; fn++) {
            int rl = wm * 64 + fm * 16 + g;
            int c  = n0 + wn * 32 + fn * 8 + 2 * tq;
            if (m0 + rl < Ne) {
                float* o = out + (size_t)stok[rl] * HDIM + c;
                atomicAdd(o + 0, acc[fm][fn][0]);
                atomicAdd(o + 1, acc[fm][fn][1]);
            }
            if (m0 + rl + 8 < Ne) {
                float* o = out + (size_t)stok[rl + 8] * HDIM + c;
                atomicAdd(o + 0, acc[fm][fn][2]);
                atomicAdd(o + 1, acc[fm][fn][3]);
            }
        }
    }
}

// ---------------- launch ---------------------------------------------------
extern "C" void kernel_launch(void* const* d_in, const int* in_sizes, int n_in,
                              void* d_out, int out_size) {
    const float* x    = (const float*)d_in[0];
    const float* attn = (const float*)d_in[1];
    const float* gw   = (const float*)d_in[2];
    const float* w1   = (const float*)d_in[3];
    const float* w2   = (const float*)d_in[4];
    const float* w3   = (const float*)d_in[5];

    float* out = (float*)d_out;
    float* logits = (out_size >= (int)(T * HDIM + T * NEXP)) ? out + (size_t)T * HDIM
                                                             : nullptr;

    cudaFuncSetAttribute(gemm1_mma, cudaFuncAttributeMaxDynamicSharedMemorySize, G1_SMEM);
    cudaFuncSetAttribute(gemm2_mma, cudaFuncAttributeMaxDynamicSharedMemorySize, G2_SMEM);

    __half* d_xh;  cudaGetSymbolAddress((void**)&d_xh,  g_xh);
    __half* d_w1h; cudaGetSymbolAddress((void**)&d_w1h, g_w1h);
    __half* d_w3h; cudaGetSymbolAddress((void**)&d_w3h, g_w3h);
    __half* d_w2h; cudaGetSymbolAddress((void**)&d_w2h, g_w2h);

    const int NW4 = NWELEM / 4;        // 7340032
    const int NX4 = T * HDIM / 4;      // 524288
    const int CVB = 256 * 4;           // elements-of-float4 per block

    // fork a side stream (capture-safe event fork/join pattern)
    cudaStream_t s2;
    cudaStreamCreateWithFlags(&s2, cudaStreamNonBlocking);
    cudaEvent_t evFork, evRoute, evW2;
    cudaEventCreateWithFlags(&evFork,  cudaEventDisableTiming);
    cudaEventCreateWithFlags(&evRoute, cudaEventDisableTiming);
    cudaEventCreateWithFlags(&evW2,    cudaEventDisableTiming);

    cudaEventRecord(evFork, 0);
    cudaStreamWaitEvent(s2, evFork, 0);

    // stream 0: conversions needed by gemm1
    cudaMemsetAsync(d_out, 0, (size_t)T * HDIM * sizeof(float));
    cvt_kernel<<<(NX4 + CVB - 1) / CVB, 256>>>((const float4*)x,  (uint2*)d_xh,  NX4);
    cvt_kernel<<<(NW4 + CVB - 1) / CVB, 256>>>((const float4*)w1, (uint2*)d_w1h, NW4);
    cvt_kernel<<<(NW4 + CVB - 1) / CVB, 256>>>((const float4*)w3, (uint2*)d_w3h, NW4);

    // stream s2: routing pipeline, then w2 conversion (overlaps gemm1)
    router_kernel<<<T, 256, 0, s2>>>(x, gw, logits);
    attn_kernel<<<SEQ, 256, 0, s2>>>(attn);
    route_finalize_kernel<<<1, 1024, 0, s2>>>();
    cudaEventRecord(evRoute, s2);
    cvt_kernel<<<(NW4 + CVB - 1) / CVB, 256, 0, s2>>>((const float4*)w2, (uint2*)d_w2h, NW4);
    cudaEventRecord(evW2, s2);

    // join: gemm1 needs routing + x/w1/w3 fp16
    cudaStreamWaitEvent(0, evRoute, 0);
    gemm1_mma<<<dim3(16, FDIM / 64, NEXP), 256, G1_SMEM>>>();

    // join: gemm2 needs w2 fp16 + act
    cudaStreamWaitEvent(0, evW2, 0);
    gemm2_mma<<<dim3(16, HDIM / 128, NEXP), 256, G2_SMEM>>>(out);
}

// round 10
// speedup vs baseline: 5.2969x; 1.0009x over previous
#include <cuda_runtime.h>
#include <cuda_fp16.h>
#include <math.h>
#include <stdint.h>

#define T    2048
#define HDIM 1024
#define FDIM 3584
#define NEXP 8
#define NH   16
#define SEQ  2048
#define NSEL 204   // int(0.1 * 2048)

#define NWELEM (NEXP * FDIM * HDIM)   // 29360128 per weight tensor

// ---------------- device scratch (no allocations allowed) ----------------
__device__ float g_scores[T];
__device__ float g_l1[T];
__device__ int   g_sel[T * 2];
__device__ float g_rw[T * 2];
__device__ int   g_top1prune[T];
__device__ int   g_low[T];
__device__ int   g_high[T];
__device__ int   g_cnt[NEXP];
__device__ int   g_ptok[NEXP * T];
__device__ float g_pw[NEXP * T];
__device__ __half g_xh[T * HDIM];
__device__ __half g_w1h[NWELEM];
__device__ __half g_w3h[NWELEM];
__device__ __half g_w2h[NWELEM];
__device__ __half g_acth[(size_t)NEXP * T * FDIM];  // fp16 activations

// ============================ helpers =====================================
__device__ __forceinline__ uint32_t smem_u32(const void* p) {
    uint32_t a;
    asm("{ .reg .u64 t; cvta.to.shared.u64 t, %1; cvt.u32.u64 %0, t; }" : "=r"(a) : "l"(p));
    return a;
}
__device__ __forceinline__ void ldm_x4(uint32_t r[4], uint32_t addr) {
    asm volatile("ldmatrix.sync.aligned.m8n8.x4.shared.b16 {%0,%1,%2,%3}, [%4];"
                 : "=r"(r[0]), "=r"(r[1]), "=r"(r[2]), "=r"(r[3]) : "r"(addr));
}
__device__ __forceinline__ void mma4(float d[4], const uint32_t a[4], const uint32_t b[2]) {
    asm volatile("mma.sync.aligned.m16n8k16.row.col.f32.f16.f16.f32 "
                 "{%0,%1,%2,%3}, {%4,%5,%6,%7}, {%8,%9}, {%0,%1,%2,%3};"
                 : "+f"(d[0]), "+f"(d[1]), "+f"(d[2]), "+f"(d[3])
                 : "r"(a[0]), "r"(a[1]), "r"(a[2]), "r"(a[3]), "r"(b[0]), "r"(b[1]));
}
__device__ __forceinline__ void cpa16(uint32_t s, const void* g) {
    asm volatile("cp.async.ca.shared.global [%0], [%1], 16;" :: "r"(s), "l"(g) : "memory");
}
#define CP_COMMIT() asm volatile("cp.async.commit_group;" ::: "memory")
#define CP_WAIT0()  asm volatile("cp.async.wait_group 0;" ::: "memory")

__device__ __forceinline__ uint32_t pkh(float a, float b) {
    return (uint32_t)__half_as_ushort(__float2half(a))
         | ((uint32_t)__half_as_ushort(__float2half(b)) << 16);
}

// row stride: 64 fp16 (128B) + 16B pad = 144B (conflict-free ldmatrix)
#define RS2 144
// gemm1 per-stage: A 128x144 @0, B1 64x144 @18432, B3 64x144 @27648
#define G1_STG   36864
#define G1_SMEM  (2 * G1_STG + 1024)
// gemm2 per-stage: A 128x144 @0, B 128x144 @18432
#define G2_STG   36864
#define G2_SMEM  (2 * G2_STG + 512)

// ---------------- convert: fp32 -> fp16, 4 float4/thread ------------------
__global__ void cvt_kernel(const float4* __restrict__ src, uint2* __restrict__ dst, int n4) {
    int base = (blockIdx.x * blockDim.x) * 4 + threadIdx.x;
    #pragma unroll
    for (int it = 0; it < 4; it++) {
        int i = base + it * 256;
        if (i < n4) {
            float4 v = src[i];
            uint2 u;
            u.x = pkh(v.x, v.y);
            u.y = pkh(v.z, v.w);
            dst[i] = u;
        }
    }
}

// ---------------- kernel 1: router ---------------------------------------
__global__ void router_kernel(const float* __restrict__ x,
                              const float* __restrict__ gw,
                              float* logits_out) {
    int t = blockIdx.x;
    int lane = threadIdx.x & 31;
    int w = threadIdx.x >> 5;
    __shared__ float s_logit[NEXP];
    __shared__ float s_l1;

    const float* xr = x + (size_t)t * HDIM;
    const float* ge = gw + (size_t)w * HDIM;
    float acc = 0.f, l1 = 0.f;
    for (int i = lane; i < HDIM; i += 32) {
        float xv = xr[i];
        acc += xv * ge[i];
        l1 += fabsf(xv);
    }
    #pragma unroll
    for (int o = 16; o; o >>= 1) {
        acc += __shfl_xor_sync(0xffffffffu, acc, o);
        l1  += __shfl_xor_sync(0xffffffffu, l1, o);
    }
    if (lane == 0) {
        s_logit[w] = acc;
        if (w == 0) s_l1 = l1;
    }
    __syncthreads();
    if (threadIdx.x == 0) {
        float p[NEXP];
        float mx = s_logit[0];
        for (int e = 1; e < NEXP; e++) if (s_logit[e] > mx) mx = s_logit[e];
        float sum = 0.f;
        for (int e = 0; e < NEXP; e++) { p[e] = expf(s_logit[e] - mx); sum += p[e]; }
        float inv = 1.f / sum;
        for (int e = 0; e < NEXP; e++) p[e] *= inv;
        int i0 = 0;
        for (int e = 1; e < NEXP; e++) if (p[e] > p[i0]) i0 = e;
        int i1 = (i0 == 0) ? 1 : 0;
        for (int e = 0; e < NEXP; e++) if (e != i0 && p[e] > p[i1]) i1 = e;
        g_sel[2 * t] = i0;  g_sel[2 * t + 1] = i1;
        g_rw[2 * t] = p[i0]; g_rw[2 * t + 1] = p[i1];
        g_top1prune[t] = (p[i1] < 0.5f * p[i0]) ? 1 : 0;
        g_l1[t] = s_l1;
        if (logits_out) {
            for (int e = 0; e < NEXP; e++) logits_out[(size_t)t * NEXP + e] = s_logit[e];
        }
    }
}

// ---------------- kernel 2: attention-score reduction --------------------
__global__ void attn_kernel(const float* __restrict__ attn) {
    int i = blockIdx.x;
    float s = 0.f;
    for (int h = 0; h < NH; h++) {
        const float4* row = reinterpret_cast<const float4*>(attn + ((size_t)h * SEQ + i) * SEQ);
        for (int j = threadIdx.x; j < SEQ / 4; j += 256) {
            float4 v = row[j];
            s += v.x + v.y + v.z + v.w;
        }
    }
    __shared__ float red[256];
    red[threadIdx.x] = s;
    __syncthreads();
    for (int st = 128; st > 0; st >>= 1) {
        if (threadIdx.x < st) red[threadIdx.x] += red[threadIdx.x + st];
        __syncthreads();
    }
    if (threadIdx.x == 0)
        g_scores[i] = red[0] / (16.f * (float)(SEQ - i)) * g_l1[i];
}

// ---------------- kernel 3: single bitonic sort + routing finalize -------
__global__ void route_finalize_kernel() {
    __shared__ float sval[T];
    __shared__ int   sidx[T];
    int tid = threadIdx.x;  // 1024 threads

    for (int t = tid; t < T; t += 1024) {
        g_low[t] = 0; g_high[t] = 0;
        sval[t] = g_scores[t]; sidx[t] = t;
    }
    if (tid < NEXP) g_cnt[tid] = 0;
    __syncthreads();

    for (int k = 2; k <= T; k <<= 1) {
        for (int j = k >> 1; j > 0; j >>= 1) {
            #pragma unroll
            for (int s = 0; s < 2; s++) {
                int i = tid + s * 1024;
                int ixj = i ^ j;
                if (ixj > i) {
                    float va = sval[i], vb = sval[ixj];
                    int ia = sidx[i], ib = sidx[ixj];
                    bool aBeforeB = (va < vb) || (va == vb && ia < ib);
                    bool up = ((i & k) == 0);
                    bool doswap = up ? !aBeforeB : aBeforeB;
                    if (doswap) {
                        sval[i] = vb; sval[ixj] = va;
                        sidx[i] = ib; sidx[ixj] = ia;
                    }
                }
            }
            __syncthreads();
        }
    }
    for (int r = tid; r < NSEL; r += 1024) {
        g_low[sidx[r]] = 1;
        g_high[sidx[T - 1 - r]] = 1;
    }
    __syncthreads();

    for (int t = tid; t < T; t += 1024) {
        float r0 = g_rw[2 * t], r1 = g_rw[2 * t + 1];
        float n0 = 1.f;
        float n1 = g_top1prune[t] ? 0.f : 1.f;
        if (g_low[t])  { n0 = 0.f; n1 = 0.f; }
        if (g_high[t]) { n0 = 1.f; n1 = 1.f; }
        r0 *= n0; r1 *= n1;
        float d = r0 + r1;
        if (d > 0.f) { r0 /= d; r1 /= d; }
        if (r0 > 0.f) {
            int e = g_sel[2 * t];
            int p = atomicAdd(&g_cnt[e], 1);
            g_ptok[e * T + p] = t;  g_pw[e * T + p] = r0;
        }
        if (r1 > 0.f) {
            int e = g_sel[2 * t + 1];
            int p = atomicAdd(&g_cnt[e], 1);
            g_ptok[e * T + p] = t;  g_pw[e * T + p] = r1;
        }
    }
}

// ---------------- gemm1: fp16 cp.async, 128x64 tile, warps 4x2 -----------
__global__ void __launch_bounds__(256, 2) gemm1_mma() {
    extern __shared__ char sm[];
    const int e = blockIdx.z;
    const int Ne = g_cnt[e];
    const int m0 = blockIdx.x * 128;
    if (m0 >= Ne) return;
    const int f0 = blockIdx.y * 64;
    const int tid = threadIdx.x;
    const int lane = tid & 31, wid = tid >> 5;
    const int wm = wid & 3, wn = wid >> 2;   // 4m x 2n warp grid

    const uint32_t sb = smem_u32(sm);
    int*   stok = reinterpret_cast<int*>(sm + 2 * G1_STG);
    float* spw  = reinterpret_cast<float*>(sm + 2 * G1_STG + 512);
    if (tid < 128) {
        int m = m0 + tid; int tk = 0; float pw = 0.f;
        if (m < Ne) { tk = g_ptok[e * T + m]; pw = g_pw[e * T + m]; }
        stok[tid] = tk; spw[tid] = pw;
    }
    __syncthreads();

    // producer mapping: per stage A 4 chunks/thread, B 4 chunks/thread (16B)
    int abase[4]; uint32_t aoff[4];
    int bbase[4]; uint32_t boff[4];
    const __half* wsrc[4];
    #pragma unroll
    for (int i = 0; i < 4; i++) {
        int idx = tid + i * 256;               // [0,1024): A chunks
        int ar = idx >> 3, c8 = (idx & 7) << 3;
        abase[i] = stok[ar] * HDIM + c8;
        aoff[i]  = (uint32_t)(ar * RS2 + c8 * 2);
        int bm = idx >> 9, br = (idx >> 3) & 63;  // B chunks
        wsrc[i]  = bm ? g_w3h : g_w1h;
        bbase[i] = (e * FDIM + f0 + br) * HDIM + c8;
        boff[i]  = (uint32_t)(18432 + bm * 9216 + br * RS2 + c8 * 2);
    }

    auto issue_stage = [&](int s) {
        uint32_t bp = sb + (uint32_t)(s & 1) * G1_STG;
        int k0 = s * 64;
        #pragma unroll
        for (int i = 0; i < 4; i++) cpa16(bp + aoff[i], g_xh + abase[i] + k0);
        #pragma unroll
        for (int i = 0; i < 4; i++) cpa16(bp + boff[i], wsrc[i] + bbase[i] + k0);
        CP_COMMIT();
    };

    issue_stage(0);
    CP_WAIT0();
    __syncthreads();

    const int lrow = lane & 15;
    const int lhik = ((lane >> 4) & 1) * 16;
    const int bn = (lane & 7) + ((lane >> 4) & 1) * 8;
    const int bhk = ((lane >> 3) & 1) * 16;

    float hc[2][4][4] = {{{0.f}}}, gc[2][4][4] = {{{0.f}}};

    auto mma_blk = [&](uint32_t bb, int kk) {
        const uint32_t koff = (uint32_t)kk * 32;
        uint32_t Ah[2][4];
        #pragma unroll
        for (int fm = 0; fm < 2; fm++)
            ldm_x4(Ah[fm], bb + (uint32_t)((wm * 32 + fm * 16 + lrow) * RS2) + koff + lhik);
        #pragma unroll
        for (int fnh = 0; fnh < 2; fnh++) {
            uint32_t bo = (uint32_t)((wn * 32 + fnh * 16 + bn) * RS2) + koff + bhk;
            uint32_t B1[4], B3[4];
            ldm_x4(B1, bb + 18432 + bo);
            ldm_x4(B3, bb + 27648 + bo);
            #pragma unroll
            for (int fm = 0; fm < 2; fm++)
                #pragma unroll
                for (int f2 = 0; f2 < 2; f2++) {
                    int fn = fnh * 2 + f2;
                    mma4(hc[fm][fn], Ah[fm], B1 + 2 * f2);
                    mma4(gc[fm][fn], Ah[fm], B3 + 2 * f2);
                }
        }
    };

    for (int s = 0; s < 16; s++) {
        const uint32_t bb = sb + (uint32_t)(s & 1) * G1_STG;
        const bool more = (s + 1 < 16);
        if (more) issue_stage(s + 1);
        mma_blk(bb, 0);
        mma_blk(bb, 1);
        mma_blk(bb, 2);
        mma_blk(bb, 3);
        if (more) { CP_WAIT0(); __syncthreads(); }
    }

    // epilogue: act = pw * g * silu(h), write fp16
    const int g = lane >> 2, tq = lane & 3;
    #pragma unroll
    for (int fm = 0; fm < 2; fm++) {
        #pragma unroll
        for (int fn = 0; fn < 4; fn++) {
            int rl = wm * 32 + fm * 16 + g;
            int c  = f0 + wn * 32 + fn * 8 + 2 * tq;
            float pw0 = spw[rl], pw1 = spw[rl + 8];
            float h0 = hc[fm][fn][0], h1 = hc[fm][fn][1];
            float h2 = hc[fm][fn][2], h3 = hc[fm][fn][3];
            float a0 = pw0 * gc[fm][fn][0] * (h0 / (1.f + expf(-h0)));
            float a1 = pw0 * gc[fm][fn][1] * (h1 / (1.f + expf(-h1)));
            float a2 = pw1 * gc[fm][fn][2] * (h2 / (1.f + expf(-h2)));
            float a3 = pw1 * gc[fm][fn][3] * (h3 / (1.f + expf(-h3)));
            *reinterpret_cast<uint32_t*>(g_acth + ((size_t)(e * T + m0 + rl)) * FDIM + c) = pkh(a0, a1);
            *reinterpret_cast<uint32_t*>(g_acth + ((size_t)(e * T + m0 + rl + 8)) * FDIM + c) = pkh(a2, a3);
        }
    }
}

// ---------------- gemm2: fp16 cp.async, 128x128 tile, warps 2x4 ----------
__global__ void __launch_bounds__(256, 2) gemm2_mma(float* __restrict__ out) {
    extern __shared__ char sm[];
    const int e = blockIdx.z;
    const int Ne = g_cnt[e];
    const int m0 = blockIdx.x * 128;
    if (m0 >= Ne) return;
    const int n0 = blockIdx.y * 128;
    const int tid = threadIdx.x;
    const int lane = tid & 31, wid = tid >> 5;
    const int wm = wid & 1, wn = wid >> 1;   // 2m x 4n warp grid

    const uint32_t sb = smem_u32(sm);
    int* stok = reinterpret_cast<int*>(sm + 2 * G2_STG);
    if (tid < 128) {
        int m = m0 + tid; int tk = 0;
        if (m < Ne) tk = g_ptok[e * T + m];
        stok[tid] = tk;
    }
    __syncthreads();

    int abase[4]; uint32_t aoff[4];
    int bbase[4]; uint32_t boff[4];
    #pragma unroll
    for (int i = 0; i < 4; i++) {
        int idx = tid + i * 256;
        int r = idx >> 3, c8 = (idx & 7) << 3;
        abase[i] = (e * T + m0 + r) * FDIM + c8;
        aoff[i]  = (uint32_t)(r * RS2 + c8 * 2);
        bbase[i] = (e * HDIM + n0 + r) * FDIM + c8;
        boff[i]  = (uint32_t)(18432 + r * RS2 + c8 * 2);
    }

    auto issue_stage = [&](int s) {
        uint32_t bp = sb + (uint32_t)(s & 1) * G2_STG;
        int k0 = s * 64;
        #pragma unroll
        for (int i = 0; i < 4; i++) cpa16(bp + aoff[i], g_acth + abase[i] + k0);
        #pragma unroll
        for (int i = 0; i < 4; i++) cpa16(bp + boff[i], g_w2h + bbase[i] + k0);
        CP_COMMIT();
    };

    issue_stage(0);
    CP_WAIT0();
    __syncthreads();

    const int lrow = lane & 15;
    const int lhik = ((lane >> 4) & 1) * 16;
    const int bn = (lane & 7) + ((lane >> 4) & 1) * 8;
    const int bhk = ((lane >> 3) & 1) * 16;

    float acc[4][4][4] = {{{0.f}}};

    auto mma_blk = [&](uint32_t bb, int kk) {
        const uint32_t koff = (uint32_t)kk * 32;
        uint32_t Bf[2][4];
        #pragma unroll
        for (int f2 = 0; f2 < 2; f2++)
            ldm_x4(Bf[f2], bb + 18432 + (uint32_t)((wn * 32 + f2 * 16 + bn) * RS2) + koff + bhk);
        #pragma unroll
        for (int fm = 0; fm < 4; fm++) {
            uint32_t Af[4];
            ldm_x4(Af, bb + (uint32_t)((wm * 64 + fm * 16 + lrow) * RS2) + koff + lhik);
            #pragma unroll
            for (int f2 = 0; f2 < 2; f2++)
                #pragma unroll
                for (int j = 0; j < 2; j++)
                    mma4(acc[fm][f2 * 2 + j], Af, Bf[f2] + 2 * j);
        }
    };

    const int NST = FDIM / 64;  // 56
    for (int s = 0; s < NST; s++) {
        const uint32_t bb = sb + (uint32_t)(s & 1) * G2_STG;
        const bool more = (s + 1 < NST);
        if (more) issue_stage(s + 1);
        mma_blk(bb, 0);
        mma_blk(bb, 1);
        mma_blk(bb, 2);
        mma_blk(bb, 3);
        if (more) { CP_WAIT0(); __syncthreads(); }
    }

    // epilogue: scatter-add fp32
    const int g = lane >> 2, tq = lane & 3;
    #pragma unroll
    for (int fm = 0; fm < 4; fm++) {
        #pragma unroll
        for (int fn = 0; fn < 4; fn++) {
            int rl = wm * 64 + fm * 16 + g;
            int c  = n0 + wn * 32 + fn * 8 + 2 * tq;
            if (m0 + rl < Ne) {
                float* o = out + (size_t)stok[rl] * HDIM + c;
                atomicAdd(o + 0, acc[fm][fn][0]);
                atomicAdd(o + 1, acc[fm][fn][1]);
            }
            if (m0 + rl + 8 < Ne) {
                float* o = out + (size_t)stok[rl + 8] * HDIM + c;
                atomicAdd(o + 0, acc[fm][fn][2]);
                atomicAdd(o + 1, acc[fm][fn][3]);
            }
        }
    }
}

// ---------------- launch ---------------------------------------------------
extern "C" void kernel_launch(void* const* d_in, const int* in_sizes, int n_in,
                              void* d_out, int out_size) {
    const float* x    = (const float*)d_in[0];
    const float* attn = (const float*)d_in[1];
    const float* gw   = (const float*)d_in[2];
    const float* w1   = (const float*)d_in[3];
    const float* w2   = (const float*)d_in[4];
    const float* w3   = (const float*)d_in[5];

    float* out = (float*)d_out;
    float* logits = (out_size >= (int)(T * HDIM + T * NEXP)) ? out + (size_t)T * HDIM
                                                             : nullptr;

    cudaFuncSetAttribute(gemm1_mma, cudaFuncAttributeMaxDynamicSharedMemorySize, G1_SMEM);
    cudaFuncSetAttribute(gemm2_mma, cudaFuncAttributeMaxDynamicSharedMemorySize, G2_SMEM);

    __half* d_xh;  cudaGetSymbolAddress((void**)&d_xh,  g_xh);
    __half* d_w1h; cudaGetSymbolAddress((void**)&d_w1h, g_w1h);
    __half* d_w3h; cudaGetSymbolAddress((void**)&d_w3h, g_w3h);
    __half* d_w2h; cudaGetSymbolAddress((void**)&d_w2h, g_w2h);

    const int NW4 = NWELEM / 4;        // 7340032
    const int NX4 = T * HDIM / 4;      // 524288
    const int CVB = 256 * 4;           // elements-of-float4 per block

    // fork a side stream (capture-safe event fork/join pattern)
    cudaStream_t s2;
    cudaStreamCreateWithFlags(&s2, cudaStreamNonBlocking);
    cudaEvent_t evFork, evRoute, evW2;
    cudaEventCreateWithFlags(&evFork,  cudaEventDisableTiming);
    cudaEventCreateWithFlags(&evRoute, cudaEventDisableTiming);
    cudaEventCreateWithFlags(&evW2,    cudaEventDisableTiming);

    cudaEventRecord(evFork, 0);
    cudaStreamWaitEvent(s2, evFork, 0);

    // stream 0: conversions needed by gemm1
    cudaMemsetAsync(d_out, 0, (size_t)T * HDIM * sizeof(float));
    cvt_kernel<<<(NX4 + CVB - 1) / CVB, 256>>>((const float4*)x,  (uint2*)d_xh,  NX4);
    cvt_kernel<<<(NW4 + CVB - 1) / CVB, 256>>>((const float4*)w1, (uint2*)d_w1h, NW4);
    cvt_kernel<<<(NW4 + CVB - 1) / CVB, 256>>>((const float4*)w3, (uint2*)d_w3h, NW4);

    // stream s2: routing pipeline, then w2 conversion (overlaps gemm1)
    router_kernel<<<T, 256, 0, s2>>>(x, gw, logits);
    attn_kernel<<<SEQ, 256, 0, s2>>>(attn);
    route_finalize_kernel<<<1, 1024, 0, s2>>>();
    cudaEventRecord(evRoute, s2);
    cvt_kernel<<<(NW4 + CVB - 1) / CVB, 256, 0, s2>>>((const float4*)w2, (uint2*)d_w2h, NW4);
    cudaEventRecord(evW2, s2);

    // join: gemm1 needs routing + x/w1/w3 fp16
    cudaStreamWaitEvent(0, evRoute, 0);
    gemm1_mma<<<dim3(16, FDIM / 64, NEXP), 256, G1_SMEM>>>();

    // join: gemm2 needs w2 fp16 + act
    cudaStreamWaitEvent(0, evW2, 0);
    gemm2_mma<<<dim3(16, HDIM / 128, NEXP), 256, G2_SMEM>>>(out);
}

// round 11
// speedup vs baseline: 5.3015x; 1.0009x over previous
#include <cuda_runtime.h>
#include <cuda_fp16.h>
#include <math.h>
#include <stdint.h>

#define T    2048
#define HDIM 1024
#define FDIM 3584
#define NEXP 8
#define NH   16
#define SEQ  2048
#define NSEL 204   // int(0.1 * 2048)

#define NWELEM (NEXP * FDIM * HDIM)   // 29360128 per weight tensor

// ---------------- device scratch (no allocations allowed) ----------------
__device__ float g_scores[T];
__device__ float g_l1[T];
__device__ int   g_sel[T * 2];
__device__ float g_rw[T * 2];
__device__ int   g_top1prune[T];
__device__ int   g_low[T];
__device__ int   g_high[T];
__device__ int   g_cnt[NEXP];
__device__ int   g_ptok[NEXP * T];
__device__ float g_pw[NEXP * T];
__device__ __half g_xh[T * HDIM];
__device__ __half g_w1h[NWELEM];
__device__ __half g_w3h[NWELEM];
__device__ __half g_w2h[NWELEM];
__device__ __half g_acth[(size_t)NEXP * T * FDIM];  // fp16 activations

// ============================ helpers =====================================
__device__ __forceinline__ uint32_t smem_u32(const void* p) {
    uint32_t a;
    asm("{ .reg .u64 t; cvta.to.shared.u64 t, %1; cvt.u32.u64 %0, t; }" : "=r"(a) : "l"(p));
    return a;
}
__device__ __forceinline__ void ldm_x4(uint32_t r[4], uint32_t addr) {
    asm volatile("ldmatrix.sync.aligned.m8n8.x4.shared.b16 {%0,%1,%2,%3}, [%4];"
                 : "=r"(r[0]), "=r"(r[1]), "=r"(r[2]), "=r"(r[3]) : "r"(addr));
}
__device__ __forceinline__ void mma4(float d[4], const uint32_t a[4], const uint32_t b[2]) {
    asm volatile("mma.sync.aligned.m16n8k16.row.col.f32.f16.f16.f32 "
                 "{%0,%1,%2,%3}, {%4,%5,%6,%7}, {%8,%9}, {%0,%1,%2,%3};"
                 : "+f"(d[0]), "+f"(d[1]), "+f"(d[2]), "+f"(d[3])
                 : "r"(a[0]), "r"(a[1]), "r"(a[2]), "r"(a[3]), "r"(b[0]), "r"(b[1]));
}
__device__ __forceinline__ void cpa16(uint32_t s, const void* g) {
    asm volatile("cp.async.ca.shared.global [%0], [%1], 16;" :: "r"(s), "l"(g) : "memory");
}
#define CP_COMMIT() asm volatile("cp.async.commit_group;" ::: "memory")
#define CP_WAIT0()  asm volatile("cp.async.wait_group 0;" ::: "memory")

__device__ __forceinline__ uint32_t pkh(float a, float b) {
    return (uint32_t)__half_as_ushort(__float2half(a))
         | ((uint32_t)__half_as_ushort(__float2half(b)) << 16);
}

// row stride: 64 fp16 (128B) + 16B pad = 144B (conflict-free ldmatrix)
#define RS2 144
// gemm1 per-stage: A 128x144 @0, B1 64x144 @18432, B3 64x144 @27648
#define G1_STG   36864
#define G1_SMEM  (2 * G1_STG + 1024)
// gemm2 per-stage: A 128x144 @0, B 128x144 @18432
#define G2_STG   36864
#define G2_SMEM  (2 * G2_STG + 512)

// ---------------- convert: fp32 -> fp16, 4 float4/thread ------------------
__global__ void cvt_kernel(const float4* __restrict__ src, uint2* __restrict__ dst, int n4) {
    int base = (blockIdx.x * blockDim.x) * 4 + threadIdx.x;
    #pragma unroll
    for (int it = 0; it < 4; it++) {
        int i = base + it * 256;
        if (i < n4) {
            float4 v = src[i];
            uint2 u;
            u.x = pkh(v.x, v.y);
            u.y = pkh(v.z, v.w);
            dst[i] = u;
        }
    }
}

// ---------------- kernel 1: router ---------------------------------------
__global__ void router_kernel(const float* __restrict__ x,
                              const float* __restrict__ gw,
                              float* logits_out) {
    int t = blockIdx.x;
    int lane = threadIdx.x & 31;
    int w = threadIdx.x >> 5;
    __shared__ float s_logit[NEXP];
    __shared__ float s_l1;

    const float* xr = x + (size_t)t * HDIM;
    const float* ge = gw + (size_t)w * HDIM;
    float acc = 0.f, l1 = 0.f;
    for (int i = lane; i < HDIM; i += 32) {
        float xv = xr[i];
        acc += xv * ge[i];
        l1 += fabsf(xv);
    }
    #pragma unroll
    for (int o = 16; o; o >>= 1) {
        acc += __shfl_xor_sync(0xffffffffu, acc, o);
        l1  += __shfl_xor_sync(0xffffffffu, l1, o);
    }
    if (lane == 0) {
        s_logit[w] = acc;
        if (w == 0) s_l1 = l1;
    }
    __syncthreads();
    if (threadIdx.x == 0) {
        float p[NEXP];
        float mx = s_logit[0];
        for (int e = 1; e < NEXP; e++) if (s_logit[e] > mx) mx = s_logit[e];
        float sum = 0.f;
        for (int e = 0; e < NEXP; e++) { p[e] = expf(s_logit[e] - mx); sum += p[e]; }
        float inv = 1.f / sum;
        for (int e = 0; e < NEXP; e++) p[e] *= inv;
        int i0 = 0;
        for (int e = 1; e < NEXP; e++) if (p[e] > p[i0]) i0 = e;
        int i1 = (i0 == 0) ? 1 : 0;
        for (int e = 0; e < NEXP; e++) if (e != i0 && p[e] > p[i1]) i1 = e;
        g_sel[2 * t] = i0;  g_sel[2 * t + 1] = i1;
        g_rw[2 * t] = p[i0]; g_rw[2 * t + 1] = p[i1];
        g_top1prune[t] = (p[i1] < 0.5f * p[i0]) ? 1 : 0;
        g_l1[t] = s_l1;
        if (logits_out) {
            for (int e = 0; e < NEXP; e++) logits_out[(size_t)t * NEXP + e] = s_logit[e];
        }
    }
}

// ---------------- kernel 2: attention-score reduction --------------------
__global__ void attn_kernel(const float* __restrict__ attn) {
    int i = blockIdx.x;
    float s = 0.f;
    for (int h = 0; h < NH; h++) {
        const float4* row = reinterpret_cast<const float4*>(attn + ((size_t)h * SEQ + i) * SEQ);
        for (int j = threadIdx.x; j < SEQ / 4; j += 256) {
            float4 v = row[j];
            s += v.x + v.y + v.z + v.w;
        }
    }
    __shared__ float red[256];
    red[threadIdx.x] = s;
    __syncthreads();
    for (int st = 128; st > 0; st >>= 1) {
        if (threadIdx.x < st) red[threadIdx.x] += red[threadIdx.x + st];
        __syncthreads();
    }
    if (threadIdx.x == 0)
        g_scores[i] = red[0] / (16.f * (float)(SEQ - i)) * g_l1[i];
}

// ---------------- kernel 3: single bitonic sort + routing finalize -------
__global__ void route_finalize_kernel() {
    __shared__ float sval[T];
    __shared__ int   sidx[T];
    int tid = threadIdx.x;  // 1024 threads

    for (int t = tid; t < T; t += 1024) {
        g_low[t] = 0; g_high[t] = 0;
        sval[t] = g_scores[t]; sidx[t] = t;
    }
    if (tid < NEXP) g_cnt[tid] = 0;
    __syncthreads();

    for (int k = 2; k <= T; k <<= 1) {
        for (int j = k >> 1; j > 0; j >>= 1) {
            #pragma unroll
            for (int s = 0; s < 2; s++) {
                int i = tid + s * 1024;
                int ixj = i ^ j;
                if (ixj > i) {
                    float va = sval[i], vb = sval[ixj];
                    int ia = sidx[i], ib = sidx[ixj];
                    bool aBeforeB = (va < vb) || (va == vb && ia < ib);
                    bool up = ((i & k) == 0);
                    bool doswap = up ? !aBeforeB : aBeforeB;
                    if (doswap) {
                        sval[i] = vb; sval[ixj] = va;
                        sidx[i] = ib; sidx[ixj] = ia;
                    }
                }
            }
            __syncthreads();
        }
    }
    for (int r = tid; r < NSEL; r += 1024) {
        g_low[sidx[r]] = 1;
        g_high[sidx[T - 1 - r]] = 1;
    }
    __syncthreads();

    for (int t = tid; t < T; t += 1024) {
        float r0 = g_rw[2 * t], r1 = g_rw[2 * t + 1];
        float n0 = 1.f;
        float n1 = g_top1prune[t] ? 0.f : 1.f;
        if (g_low[t])  { n0 = 0.f; n1 = 0.f; }
        if (g_high[t]) { n0 = 1.f; n1 = 1.f; }
        r0 *= n0; r1 *= n1;
        float d = r0 + r1;
        if (d > 0.f) { r0 /= d; r1 /= d; }
        if (r0 > 0.f) {
            int e = g_sel[2 * t];
            int p = atomicAdd(&g_cnt[e], 1);
            g_ptok[e * T + p] = t;  g_pw[e * T + p] = r0;
        }
        if (r1 > 0.f) {
            int e = g_sel[2 * t + 1];
            int p = atomicAdd(&g_cnt[e], 1);
            g_ptok[e * T + p] = t;  g_pw[e * T + p] = r1;
        }
    }
}

// ---------------- gemm1: fp16 cp.async, 128x64 tile, warps 4x2 -----------
__global__ void __launch_bounds__(256, 2) gemm1_mma() {
    extern __shared__ char sm[];
    const int e = blockIdx.z;
    const int Ne = g_cnt[e];
    const int m0 = blockIdx.x * 128;
    if (m0 >= Ne) return;
    const int f0 = blockIdx.y * 64;
    const int tid = threadIdx.x;
    const int lane = tid & 31, wid = tid >> 5;
    const int wm = wid & 3, wn = wid >> 2;   // 4m x 2n warp grid

    const uint32_t sb = smem_u32(sm);
    int*   stok = reinterpret_cast<int*>(sm + 2 * G1_STG);
    float* spw  = reinterpret_cast<float*>(sm + 2 * G1_STG + 512);
    if (tid < 128) {
        int m = m0 + tid; int tk = 0; float pw = 0.f;
        if (m < Ne) { tk = g_ptok[e * T + m]; pw = g_pw[e * T + m]; }
        stok[tid] = tk; spw[tid] = pw;
    }
    __syncthreads();

    // producer mapping: per stage A 4 chunks/thread, B 4 chunks/thread (16B)
    int abase[4]; uint32_t aoff[4];
    int bbase[4]; uint32_t boff[4];
    const __half* wsrc[4];
    #pragma unroll
    for (int i = 0; i < 4; i++) {
        int idx = tid + i * 256;               // [0,1024): A chunks
        int ar = idx >> 3, c8 = (idx & 7) << 3;
        abase[i] = stok[ar] * HDIM + c8;
        aoff[i]  = (uint32_t)(ar * RS2 + c8 * 2);
        int bm = idx >> 9, br = (idx >> 3) & 63;  // B chunks
        wsrc[i]  = bm ? g_w3h : g_w1h;
        bbase[i] = (e * FDIM + f0 + br) * HDIM + c8;
        boff[i]  = (uint32_t)(18432 + bm * 9216 + br * RS2 + c8 * 2);
    }

    auto issue_stage = [&](int s) {
        uint32_t bp = sb + (uint32_t)(s & 1) * G1_STG;
        int k0 = s * 64;
        #pragma unroll
        for (int i = 0; i < 4; i++) cpa16(bp + aoff[i], g_xh + abase[i] + k0);
        #pragma unroll
        for (int i = 0; i < 4; i++) cpa16(bp + boff[i], wsrc[i] + bbase[i] + k0);
        CP_COMMIT();
    };

    issue_stage(0);
    CP_WAIT0();
    __syncthreads();

    const int lrow = lane & 15;
    const int lhik = ((lane >> 4) & 1) * 16;
    const int bn = (lane & 7) + ((lane >> 4) & 1) * 8;
    const int bhk = ((lane >> 3) & 1) * 16;

    float hc[2][4][4] = {{{0.f}}}, gc[2][4][4] = {{{0.f}}};

    auto mma_blk = [&](uint32_t bb, int kk) {
        const uint32_t koff = (uint32_t)kk * 32;
        uint32_t Ah[2][4];
        #pragma unroll
        for (int fm = 0; fm < 2; fm++)
            ldm_x4(Ah[fm], bb + (uint32_t)((wm * 32 + fm * 16 + lrow) * RS2) + koff + lhik);
        #pragma unroll
        for (int fnh = 0; fnh < 2; fnh++) {
            uint32_t bo = (uint32_t)((wn * 32 + fnh * 16 + bn) * RS2) + koff + bhk;
            uint32_t B1[4], B3[4];
            ldm_x4(B1, bb + 18432 + bo);
            ldm_x4(B3, bb + 27648 + bo);
            #pragma unroll
            for (int fm = 0; fm < 2; fm++)
                #pragma unroll
                for (int f2 = 0; f2 < 2; f2++) {
                    int fn = fnh * 2 + f2;
                    mma4(hc[fm][fn], Ah[fm], B1 + 2 * f2);
                    mma4(gc[fm][fn], Ah[fm], B3 + 2 * f2);
                }
        }
    };

    for (int s = 0; s < 16; s++) {
        const uint32_t bb = sb + (uint32_t)(s & 1) * G1_STG;
        const bool more = (s + 1 < 16);
        if (more) issue_stage(s + 1);
        mma_blk(bb, 0);
        mma_blk(bb, 1);
        mma_blk(bb, 2);
        mma_blk(bb, 3);
        if (more) { CP_WAIT0(); __syncthreads(); }
    }

    // epilogue: act = pw * g * silu(h), write fp16
    const int g = lane >> 2, tq = lane & 3;
    #pragma unroll
    for (int fm = 0; fm < 2; fm++) {
        #pragma unroll
        for (int fn = 0; fn < 4; fn++) {
            int rl = wm * 32 + fm * 16 + g;
            int c  = f0 + wn * 32 + fn * 8 + 2 * tq;
            float pw0 = spw[rl], pw1 = spw[rl + 8];
            float h0 = hc[fm][fn][0], h1 = hc[fm][fn][1];
            float h2 = hc[fm][fn][2], h3 = hc[fm][fn][3];
            float a0 = pw0 * gc[fm][fn][0] * (h0 / (1.f + expf(-h0)));
            float a1 = pw0 * gc[fm][fn][1] * (h1 / (1.f + expf(-h1)));
            float a2 = pw1 * gc[fm][fn][2] * (h2 / (1.f + expf(-h2)));
            float a3 = pw1 * gc[fm][fn][3] * (h3 / (1.f + expf(-h3)));
            *reinterpret_cast<uint32_t*>(g_acth + ((size_t)(e * T + m0 + rl)) * FDIM + c) = pkh(a0, a1);
            *reinterpret_cast<uint32_t*>(g_acth + ((size_t)(e * T + m0 + rl + 8)) * FDIM + c) = pkh(a2, a3);
        }
    }
}

// ---------------- gemm2: fp16 cp.async, 128x128 tile, warps 2x4 ----------
__global__ void __launch_bounds__(256, 2) gemm2_mma(float* __restrict__ out) {
    extern __shared__ char sm[];
    const int e = blockIdx.z;
    const int Ne = g_cnt[e];
    const int m0 = blockIdx.x * 128;
    if (m0 >= Ne) return;
    const int n0 = blockIdx.y * 128;
    const int tid = threadIdx.x;
    const int lane = tid & 31, wid = tid >> 5;
    const int wm = wid & 1, wn = wid >> 1;   // 2m x 4n warp grid

    const uint32_t sb = smem_u32(sm);
    int* stok = reinterpret_cast<int*>(sm + 2 * G2_STG);
    if (tid < 128) {
        int m = m0 + tid; int tk = 0;
        if (m < Ne) tk = g_ptok[e * T + m];
        stok[tid] = tk;
    }
    __syncthreads();

    int abase[4]; uint32_t aoff[4];
    int bbase[4]; uint32_t boff[4];
    #pragma unroll
    for (int i = 0; i < 4; i++) {
        int idx = tid + i * 256;
        int r = idx >> 3, c8 = (idx & 7) << 3;
        abase[i] = (e * T + m0 + r) * FDIM + c8;
        aoff[i]  = (uint32_t)(r * RS2 + c8 * 2);
        bbase[i] = (e * HDIM + n0 + r) * FDIM + c8;
        boff[i]  = (uint32_t)(18432 + r * RS2 + c8 * 2);
    }

    auto issue_stage = [&](int s) {
        uint32_t bp = sb + (uint32_t)(s & 1) * G2_STG;
        int k0 = s * 64;
        #pragma unroll
        for (int i = 0; i < 4; i++) cpa16(bp + aoff[i], g_acth + abase[i] + k0);
        #pragma unroll
        for (int i = 0; i < 4; i++) cpa16(bp + boff[i], g_w2h + bbase[i] + k0);
        CP_COMMIT();
    };

    issue_stage(0);
    CP_WAIT0();
    __syncthreads();

    const int lrow = lane & 15;
    const int lhik = ((lane >> 4) & 1) * 16;
    const int bn = (lane & 7) + ((lane >> 4) & 1) * 8;
    const int bhk = ((lane >> 3) & 1) * 16;

    float acc[4][4][4] = {{{0.f}}};

    auto mma_blk = [&](uint32_t bb, int kk) {
        const uint32_t koff = (uint32_t)kk * 32;
        uint32_t Bf[2][4];
        #pragma unroll
        for (int f2 = 0; f2 < 2; f2++)
            ldm_x4(Bf[f2], bb + 18432 + (uint32_t)((wn * 32 + f2 * 16 + bn) * RS2) + koff + bhk);
        #pragma unroll
        for (int fm = 0; fm < 4; fm++) {
            uint32_t Af[4];
            ldm_x4(Af, bb + (uint32_t)((wm * 64 + fm * 16 + lrow) * RS2) + koff + lhik);
            #pragma unroll
            for (int f2 = 0; f2 < 2; f2++)
                #pragma unroll
                for (int j = 0; j < 2; j++)
                    mma4(acc[fm][f2 * 2 + j], Af, Bf[f2] + 2 * j);
        }
    };

    const int NST = FDIM / 64;  // 56
    for (int s = 0; s < NST; s++) {
        const uint32_t bb = sb + (uint32_t)(s & 1) * G2_STG;
        const bool more = (s + 1 < NST);
        if (more) issue_stage(s + 1);
        mma_blk(bb, 0);
        mma_blk(bb, 1);
        mma_blk(bb, 2);
        mma_blk(bb, 3);
        if (more) { CP_WAIT0(); __syncthreads(); }
    }

    // epilogue: scatter-add fp32
    const int g = lane >> 2, tq = lane & 3;
    #pragma unroll
    for (int fm = 0; fm < 4; fm++) {
        #pragma unroll
        for (int fn = 0; fn < 4; fn++) {
            int rl = wm * 64 + fm * 16 + g;
            int c  = n0 + wn * 32 + fn * 8 + 2 * tq;
            if (m0 + rl < Ne) {
                float* o = out + (size_t)stok[rl] * HDIM + c;
                atomicAdd(o + 0, acc[fm][fn][0]);
                atomicAdd(o + 1, acc[fm][fn][1]);
            }
            if (m0 + rl + 8 < Ne) {
                float* o = out + (size_t)stok[rl + 8] * HDIM + c;
                atomicAdd(o + 0, acc[fm][fn][2]);
                atomicAdd(o + 1, acc[fm][fn][3]);
            }
        }
    }
}

// ---------------- launch ---------------------------------------------------
extern "C" void kernel_launch(void* const* d_in, const int* in_sizes, int n_in,
                              void* d_out, int out_size) {
    const float* x    = (const float*)d_in[0];
    const float* attn = (const float*)d_in[1];
    const float* gw   = (const float*)d_in[2];
    const float* w1   = (const float*)d_in[3];
    const float* w2   = (const float*)d_in[4];
    const float* w3   = (const float*)d_in[5];

    float* out = (float*)d_out;
    float* logits = (out_size >= (int)(T * HDIM + T * NEXP)) ? out + (size_t)T * HDIM
                                                             : nullptr;

    cudaFuncSetAttribute(gemm1_mma, cudaFuncAttributeMaxDynamicSharedMemorySize, G1_SMEM);
    cudaFuncSetAttribute(gemm2_mma, cudaFuncAttributeMaxDynamicSharedMemorySize, G2_SMEM);

    __half* d_xh;  cudaGetSymbolAddress((void**)&d_xh,  g_xh);
    __half* d_w1h; cudaGetSymbolAddress((void**)&d_w1h, g_w1h);
    __half* d_w3h; cudaGetSymbolAddress((void**)&d_w3h, g_w3h);
    __half* d_w2h; cudaGetSymbolAddress((void**)&d_w2h, g_w2h);

    const int NW4 = NWELEM / 4;        // 7340032
    const int NX4 = T * HDIM / 4;      // 524288
    const int CVB = 256 * 4;           // elements-of-float4 per block

    // fork a side stream (capture-safe event fork/join pattern)
    cudaStream_t s2;
    cudaStreamCreateWithFlags(&s2, cudaStreamNonBlocking);
    cudaEvent_t evFork, evRoute, evW2;
    cudaEventCreateWithFlags(&evFork,  cudaEventDisableTiming);
    cudaEventCreateWithFlags(&evRoute, cudaEventDisableTiming);
    cudaEventCreateWithFlags(&evW2,    cudaEventDisableTiming);

    cudaEventRecord(evFork, 0);
    cudaStreamWaitEvent(s2, evFork, 0);

    // stream 0: conversions needed by gemm1
    cudaMemsetAsync(d_out, 0, (size_t)T * HDIM * sizeof(float));
    cvt_kernel<<<(NX4 + CVB - 1) / CVB, 256>>>((const float4*)x,  (uint2*)d_xh,  NX4);
    cvt_kernel<<<(NW4 + CVB - 1) / CVB, 256>>>((const float4*)w1, (uint2*)d_w1h, NW4);
    cvt_kernel<<<(NW4 + CVB - 1) / CVB, 256>>>((const float4*)w3, (uint2*)d_w3h, NW4);

    // stream s2: routing pipeline, then w2 conversion (overlaps gemm1)
    router_kernel<<<T, 256, 0, s2>>>(x, gw, logits);
    attn_kernel<<<SEQ, 256, 0, s2>>>(attn);
    route_finalize_kernel<<<1, 1024, 0, s2>>>();
    cudaEventRecord(evRoute, s2);
    cvt_kernel<<<(NW4 + CVB - 1) / CVB, 256, 0, s2>>>((const float4*)w2, (uint2*)d_w2h, NW4);
    cudaEventRecord(evW2, s2);

    // join: gemm1 needs routing + x/w1/w3 fp16
    cudaStreamWaitEvent(0, evRoute, 0);
    gemm1_mma<<<dim3(16, FDIM / 64, NEXP), 256, G1_SMEM>>>();

    // join: gemm2 needs w2 fp16 + act
    cudaStreamWaitEvent(0, evW2, 0);
    gemm2_mma<<<dim3(16, HDIM / 128, NEXP), 256, G2_SMEM>>>(out);
}